// round 11
// baseline (speedup 1.0000x reference)
#include <cuda_runtime.h>
#include <cuda_fp16.h>
#include <math.h>
#include <stdint.h>

#define S 1024
#define D 1024
#define H 16
#define HD 64
#define NL 6
#define DFF 4096
#define EPS 1.1920929e-07f

// ---------------- scratch (device globals; no allocation) ----------------
__device__ float  g_x [S * D];
__device__ float  g_x0[S * D];
__device__ float  g_xl[S * D];
__device__ __half g_xn[S * D];
__device__ __half g_q [S * D];
__device__ __half g_k [S * D];
__device__ __half g_v [S * D];
__device__ __half g_v1[S * D];
__device__ __half g_vt[S * D];
__device__ __half g_y [S * D];
__device__ __half g_h [S * DFF];
__device__ __half g_p [(size_t)H * S * S];
__device__ float  g_rs[(size_t)H * S];
__device__ float  g_fc2[4 * S * D];
__device__ int    g_cpad[S + 1];
__device__ unsigned char g_mask[(size_t)S * S];
// fp16 weight copies (converted once per replay, overlapped on stream 2)
__device__ __half g_wq[NL * D * D];
__device__ __half g_wk[NL * D * D];
__device__ __half g_wv[NL * D * D];
__device__ __half g_wo[NL * D * D];
__device__ __half g_wfc[(size_t)NL * DFF * D];
__device__ __half g_wp [(size_t)NL * DFF * D];

// ---------------- small kernels ----------------

// wide conversion: 32B read / 16B write per thread
__global__ void tohalf2_k(const float4* __restrict__ in, uint4* __restrict__ out, int n8) {
    int i = blockIdx.x * blockDim.x + threadIdx.x;
    if (i < n8) {
        float4 a = in[2 * i];
        float4 b = in[2 * i + 1];
        __half2 h0 = __floats2half2_rn(a.x, a.y);
        __half2 h1 = __floats2half2_rn(a.z, a.w);
        __half2 h2 = __floats2half2_rn(b.x, b.y);
        __half2 h3 = __floats2half2_rn(b.z, b.w);
        uint4 r;
        r.x = *(uint32_t*)&h0;
        r.y = *(uint32_t*)&h1;
        r.z = *(uint32_t*)&h2;
        r.w = *(uint32_t*)&h3;
        out[i] = r;
    }
}

__global__ void fc2_reduce_k(const float4* __restrict__ part, float4* __restrict__ x) {
    int i = blockIdx.x * blockDim.x + threadIdx.x;
    const int N4 = S * D / 4;
    float4 s = x[i];
    #pragma unroll
    for (int j = 0; j < 4; j++) {
        float4 t = part[(size_t)j * N4 + i];
        s.x += t.x; s.y += t.y; s.z += t.z; s.w += t.w;
    }
    x[i] = s;
}

__global__ void build_prefix_k(const int* __restrict__ levels, int* __restrict__ cpad) {
    if (threadIdx.x == 0) {
        cpad[0] = 0;
        for (int i = 0; i < S; i++) cpad[i + 1] = cpad[i] + (levels[i] == 0 ? 1 : 0);
    }
}

__global__ void build_mask_k(const int* __restrict__ levels, const int* __restrict__ sample,
                             const int* __restrict__ cpad, unsigned char* __restrict__ mask) {
    int idx = blockIdx.x * blockDim.x + threadIdx.x;
    int q = idx >> 10;
    int k = idx & 1023;
    bool causal = q >= k;
    bool same = sample[q] == sample[k];
    int cnt = cpad[q] - cpad[k + 1];
    bool markov = (levels[k] == 0) && (cnt > 0);
    mask[idx] = (causal && same && !markov) ? 1 : 0;
}

// RMS over fp32 rows of length D -> fp32 out — one row per block
__global__ void rms_rows_f_k(const float* __restrict__ in, float* __restrict__ out) {
    int row = blockIdx.x;
    const float4* p = (const float4*)(in + (size_t)row * D);
    float4* o = (float4*)(out + (size_t)row * D);
    int tid = threadIdx.x;
    float4 t = p[tid];
    float ss = t.x * t.x + t.y * t.y + t.z * t.z + t.w * t.w;
    __shared__ float red[256];
    red[tid] = ss;
    __syncthreads();
    for (int s = 128; s > 0; s >>= 1) {
        if (tid < s) red[tid] += red[tid + s];
        __syncthreads();
    }
    float sc = rsqrtf(red[0] / (float)D + EPS);
    o[tid] = make_float4(t.x * sc, t.y * sc, t.z * sc, t.w * sc);
}

// RMS over fp32 rows of length D -> fp16 out
__global__ void rms_rows_h_k(const float* __restrict__ in, __half* __restrict__ out) {
    int row = blockIdx.x;
    const float4* p = (const float4*)(in + (size_t)row * D);
    uint2* o = (uint2*)(out + (size_t)row * D);
    int tid = threadIdx.x;
    float4 t = p[tid];
    float ss = t.x * t.x + t.y * t.y + t.z * t.z + t.w * t.w;
    __shared__ float red[256];
    red[tid] = ss;
    __syncthreads();
    for (int s = 128; s > 0; s >>= 1) {
        if (tid < s) red[tid] += red[tid + s];
        __syncthreads();
    }
    float sc = rsqrtf(red[0] / (float)D + EPS);
    __half2 a = __floats2half2_rn(t.x * sc, t.y * sc);
    __half2 b = __floats2half2_rn(t.z * sc, t.w * sc);
    uint2 r;
    r.x = *(uint32_t*)&a;
    r.y = *(uint32_t*)&b;
    o[tid] = r;
}

// fused: xl = l0*x + l1*x0 (fp32 store); xn = fp16(rms(xl)). One row per block.
__global__ void xlrms_k(const float4* __restrict__ x, const float4* __restrict__ x0,
                        const float* __restrict__ lambdas, int layer,
                        float4* __restrict__ xl, __half* __restrict__ xn) {
    int row = blockIdx.x;
    int tid = threadIdx.x;
    int i = row * 256 + tid;
    float l0 = lambdas[layer * 2 + 0];
    float l1 = lambdas[layer * 2 + 1];
    float4 a = x[i], b = x0[i];
    float4 t = make_float4(l0 * a.x + l1 * b.x, l0 * a.y + l1 * b.y,
                           l0 * a.z + l1 * b.z, l0 * a.w + l1 * b.w);
    xl[i] = t;
    float ss = t.x * t.x + t.y * t.y + t.z * t.z + t.w * t.w;
    __shared__ float red[256];
    red[tid] = ss;
    __syncthreads();
    for (int s = 128; s > 0; s >>= 1) {
        if (tid < s) red[tid] += red[tid + s];
        __syncthreads();
    }
    float sc = rsqrtf(red[0] / (float)D + EPS);
    __half2 h0 = __floats2half2_rn(t.x * sc, t.y * sc);
    __half2 h1 = __floats2half2_rn(t.z * sc, t.w * sc);
    uint2 r;
    r.x = *(uint32_t*)&h0;
    r.y = *(uint32_t*)&h1;
    ((uint2*)xn)[i] = r;
}

__global__ void copyu2_k(const uint2* __restrict__ in, uint2* __restrict__ out) {
    int i = blockIdx.x * blockDim.x + threadIdx.x;
    out[i] = in[i];
}

// fused v-mix + transpose: vt[c][r] = (1-la)*v[r][c] + la*v1[r][c]
__global__ void transmix_k(const __half* __restrict__ v, const __half* __restrict__ v1,
                           const float* __restrict__ lamb, int layer,
                           __half* __restrict__ vt) {
    __shared__ __half tile[32][34];
    float la = lamb[layer];
    float om = 1.f - la;
    int x = blockIdx.x * 32 + threadIdx.x;
    int y0 = blockIdx.y * 32 + threadIdx.y;
    #pragma unroll
    for (int j = 0; j < 32; j += 8) {
        size_t idx = (size_t)(y0 + j) * D + x;
        float mv = om * __half2float(v[idx]) + la * __half2float(v1[idx]);
        tile[threadIdx.y + j][threadIdx.x] = __float2half_rn(mv);
    }
    __syncthreads();
    int x2 = blockIdx.y * 32 + threadIdx.x;
    int y2 = blockIdx.x * 32 + threadIdx.y;
    #pragma unroll
    for (int j = 0; j < 32; j += 8)
        vt[(size_t)(y2 + j) * D + x2] = tile[threadIdx.x][threadIdx.y + j];
}

// rs[h*S+q] = 1 / sum_k p[h][q][k]  (p fp16; valid region k < ((q>>7)+1)*128)
__global__ void rowsum_k(const __half* __restrict__ p, float* __restrict__ rs) {
    int row = blockIdx.x * 8 + (threadIdx.x >> 5);   // h*S + q
    int lane = threadIdx.x & 31;
    int q = row & (S - 1);
    const __half2* pr = (const __half2*)(p + (size_t)row * S);
    int n2 = (((q >> 7) + 1) << 7) >> 1;
    float s = 0.f;
    for (int i = lane; i < n2; i += 32) {
        float2 f = __half22float2(pr[i]);
        s += f.x + f.y;
    }
    #pragma unroll
    for (int o = 16; o; o >>= 1) s += __shfl_xor_sync(0xFFFFFFFFu, s, o);
    if (lane == 0) rs[row] = 1.f / s;
}

// ---------------- pipelined fp16 mma.sync GEMM (m16n8k16, ldmatrix), 4 warps ----------------
// C[M,N] = A[M,K] * B[N,K]^T  (NT; fp16 row-major, K contiguous)
// modes: 0 fp32 raw | 1 fp32 acc+R | 2 fp16 relu(acc)^2 | 3 fp16 mask?exp(acc*scale):0
//        4 fp16 acc*R[row] | 5 fp16 raw | 6 fp16, per-head RMS+RoPE for z<2 (QKV fusion)
// flags: 1 = triangular launch (z=h*36+t); 2 = K limited to row0+128; 4 = split-K over z

struct GArgs {
    const __half* A; int lda; long long sA;
    const __half* B; int ldb; long long sB;
    void* C; int ldc; long long sC;
    const float* R; long long sR;
    int K; int mode; int flags; float scale;
    const unsigned char* mask;
    const __half* Bm[3]; void* Cm[3]; int nMulti;
};

#define LDMX4(r0, r1, r2, r3, addr) \
    asm volatile("ldmatrix.sync.aligned.m8n8.x4.shared.b16 {%0,%1,%2,%3}, [%4];" \
                 : "=r"(r0), "=r"(r1), "=r"(r2), "=r"(r3) : "r"(addr))

template<int BN>
__global__ __launch_bounds__(128, 2) void gemm4(GArgs a) {
    constexpr int BM = 128, BK = 64;          // halves per K-tile (128 bytes/row)
    constexpr int SROW = 72;                  // padded row in halves (144B)
    constexpr int SSZ = (BM + BN) * SROW;     // halves per stage
    constexpr int WN = BN / 2;
    constexpr int FM = 4, FN = WN / 8;        // 64 x {64|32} per warp
    constexpr int CA = 8, CB = BN / 16;       // cp.async 16B chunks per thread
    extern __shared__ __half sh[];

    int tid = threadIdx.x, lane = tid & 31, warp = tid >> 5;
    int row0, col0, koff = 0;
    const __half *A, *B;
    char* C;
    const float* R = nullptr;
    int z = blockIdx.z;

    if (a.flags & 1) {
        int t = z % 36, h = z / 36;
        int by = 0;
        while ((by + 1) * (by + 2) / 2 <= t) by++;
        int bx = t - by * (by + 1) / 2;
        row0 = by * BM; col0 = bx * BN;
        A = a.A + (size_t)h * a.sA;
        B = a.B + (size_t)h * a.sB;
        C = (char*)a.C + (size_t)h * a.sC * 2;      // fp16 C
    } else {
        row0 = blockIdx.y * BM; col0 = blockIdx.x * BN;
        if (a.flags & 4) {
            A = a.A; B = a.B;
            C = (char*)a.C + (size_t)z * a.sC * 4;  // fp32 partials
            koff = z * a.K;
        } else if (a.nMulti) {
            A = a.A; B = a.Bm[z]; C = (char*)a.Cm[z];
        } else {
            A = a.A + (size_t)z * a.sA;
            B = a.B + (size_t)z * a.sB;
            int esz = (a.mode == 0 || a.mode == 1) ? 4 : 2;
            C = (char*)a.C + (size_t)z * a.sC * esz;
            if (a.R) R = a.R + (size_t)z * a.sR;
        }
    }

    int K = a.K;
    if (a.flags & 2) { int kl = row0 + BM; if (kl < K) K = kl; }
    int KT = K / BK;

    auto issue = [&](int kt, int st) {
        __half* dstA = sh + st * SSZ;
        #pragma unroll
        for (int i = 0; i < CA; i++) {
            int id = tid + 128 * i;
            int r = id >> 3, c = id & 7;
            unsigned u = (unsigned)__cvta_generic_to_shared(dstA + r * SROW + c * 8);
            const __half* gp = A + (size_t)(row0 + r) * a.lda + koff + kt * BK + c * 8;
            asm volatile("cp.async.cg.shared.global [%0], [%1], 16;\n" :: "r"(u), "l"(gp));
        }
        __half* dstB = sh + st * SSZ + BM * SROW;
        #pragma unroll
        for (int i = 0; i < CB; i++) {
            int id = tid + 128 * i;
            int r = id >> 3, c = id & 7;
            unsigned u = (unsigned)__cvta_generic_to_shared(dstB + r * SROW + c * 8);
            const __half* gp = B + (size_t)(col0 + r) * a.ldb + koff + kt * BK + c * 8;
            asm volatile("cp.async.cg.shared.global [%0], [%1], 16;\n" :: "r"(u), "l"(gp));
        }
        asm volatile("cp.async.commit_group;\n");
    };

    float acc[FM][FN][4] = {};

    issue(0, 0);
    if (KT > 1) issue(1, 1);

    int wm0 = (warp & 1) * 64, wn0 = (warp >> 1) * WN;
    int g = lane >> 2, tig = lane & 3;

    uint32_t shb = (uint32_t)__cvta_generic_to_shared(sh);
    int laneq = lane & 7, lane8 = (lane >> 3) & 1, lane16 = lane >> 4;
    uint32_t aoff = (uint32_t)((wm0 + laneq + 8 * lane8) * SROW + 8 * lane16);
    uint32_t boff = (uint32_t)((wn0 + laneq + 8 * lane16) * SROW + 8 * lane8);

    for (int kt = 0; kt < KT; kt++) {
        if (kt + 2 <= KT) asm volatile("cp.async.wait_group 1;\n");
        else              asm volatile("cp.async.wait_group 0;\n");
        __syncthreads();

        uint32_t sAb = shb + (uint32_t)((kt & 1) * SSZ) * 2;
        uint32_t sBb = sAb + BM * SROW * 2;

        #pragma unroll
        for (int s16 = 0; s16 < BK; s16 += 16) {
            uint32_t af[FM][4], bf[FN][2];
            #pragma unroll
            for (int fm = 0; fm < FM; fm++) {
                LDMX4(af[fm][0], af[fm][1], af[fm][2], af[fm][3],
                      sAb + (aoff + fm * 16 * SROW + s16) * 2);
            }
            #pragma unroll
            for (int fp = 0; fp < FN / 2; fp++) {
                LDMX4(bf[2 * fp][0], bf[2 * fp][1], bf[2 * fp + 1][0], bf[2 * fp + 1][1],
                      sBb + (boff + fp * 16 * SROW + s16) * 2);
            }
            #pragma unroll
            for (int fm = 0; fm < FM; fm++)
                #pragma unroll
                for (int fn = 0; fn < FN; fn++) {
                    asm volatile(
                        "mma.sync.aligned.m16n8k16.row.col.f32.f16.f16.f32 "
                        "{%0,%1,%2,%3}, {%4,%5,%6,%7}, {%8,%9}, {%0,%1,%2,%3};\n"
                        : "+f"(acc[fm][fn][0]), "+f"(acc[fm][fn][1]),
                          "+f"(acc[fm][fn][2]), "+f"(acc[fm][fn][3])
                        : "r"(af[fm][0]), "r"(af[fm][1]), "r"(af[fm][2]), "r"(af[fm][3]),
                          "r"(bf[fn][0]), "r"(bf[fn][1]));
                }
        }
        __syncthreads();
        if (kt + 2 < KT) issue(kt + 2, kt & 1);
    }

    // ---- mode 6 epilogue: per-head RMS + RoPE (z<2), raw fp16 for z==2 ----
    if (a.mode == 6) {
        // BN=128 only: warp spans exactly one 64-col head (wn0 in {0,64}, col0 % 128 == 0)
        bool dorope = (z < 2);
        float invj[FN];  // j = 8*fn + 2*tig + t ; x1 cols are fn 0..FN/2-1
        #pragma unroll
        for (int fn = 0; fn < FN / 2; fn++) {
            #pragma unroll
            for (int t = 0; t < 2; t++) {
                int j = 8 * fn + 2 * tig + t;
                invj[fn * 2 + t] = powf(10000.f, -(float)j / 32.f);
            }
        }
        #pragma unroll
        for (int fm = 0; fm < FM; fm++) {
            #pragma unroll
            for (int half = 0; half < 2; half++) {
                int r = row0 + wm0 + fm * 16 + g + 8 * half;
                float vb[FN][2];
                #pragma unroll
                for (int fn = 0; fn < FN; fn++) {
                    vb[fn][0] = acc[fm][fn][2 * half + 0];
                    vb[fn][1] = acc[fm][fn][2 * half + 1];
                }
                if (dorope) {
                    float ss = 0.f;
                    #pragma unroll
                    for (int fn = 0; fn < FN; fn++)
                        ss += vb[fn][0] * vb[fn][0] + vb[fn][1] * vb[fn][1];
                    ss += __shfl_xor_sync(0xFFFFFFFFu, ss, 1);
                    ss += __shfl_xor_sync(0xFFFFFFFFu, ss, 2);
                    float sc = rsqrtf(ss / 64.f + EPS);
                    #pragma unroll
                    for (int fn = 0; fn < FN / 2; fn++) {
                        #pragma unroll
                        for (int t = 0; t < 2; t++) {
                            float x1 = vb[fn][t] * sc;
                            float x2 = vb[fn + FN / 2][t] * sc;
                            float fr = (float)r * invj[fn * 2 + t];
                            float cs, sn;
                            sincosf(fr, &sn, &cs);
                            vb[fn][t] = x1 * cs + x2 * sn;
                            vb[fn + FN / 2][t] = -x1 * sn + x2 * cs;
                        }
                    }
                }
                #pragma unroll
                for (int fn = 0; fn < FN; fn++) {
                    size_t off = (size_t)r * a.ldc + col0 + wn0 + fn * 8 + 2 * tig;
                    __half2 hv = __floats2half2_rn(vb[fn][0], vb[fn][1]);
                    *(__half2*)((__half*)C + off) = hv;
                }
            }
        }
        return;
    }

    // ---- generic epilogue ----
    #pragma unroll
    for (int fm = 0; fm < FM; fm++) {
        #pragma unroll
        for (int fn = 0; fn < FN; fn++) {
            int r0 = row0 + wm0 + fm * 16 + g;
            int c  = col0 + wn0 + fn * 8 + 2 * tig;
            #pragma unroll
            for (int half = 0; half < 2; half++) {
                int r = r0 + 8 * half;
                float v0 = acc[fm][fn][2 * half + 0];
                float v1 = acc[fm][fn][2 * half + 1];
                size_t off = (size_t)r * a.ldc + c;
                if (a.mode == 0) {
                    ((float*)C)[off] = v0;
                    ((float*)C)[off + 1] = v1;
                } else if (a.mode == 1) {
                    ((float*)C)[off] = v0 + R[off];
                    ((float*)C)[off + 1] = v1 + R[off + 1];
                } else {
                    if (a.mode == 2) {
                        v0 = fmaxf(v0, 0.f); v0 *= v0;
                        v1 = fmaxf(v1, 0.f); v1 *= v1;
                    } else if (a.mode == 3) {
                        const unsigned char* m = a.mask + (size_t)r * S + c;
                        v0 = m[0] ? __expf(v0 * a.scale) : 0.f;
                        v1 = m[1] ? __expf(v1 * a.scale) : 0.f;
                    } else if (a.mode == 4) {
                        float rsv = R[r];
                        v0 *= rsv;
                        v1 *= rsv;
                    }
                    __half2 hv = __floats2half2_rn(v0, v1);
                    *(__half2*)((__half*)C + off) = hv;
                }
            }
        }
    }
}

// ---------------- host orchestration ----------------

static inline GArgs mkargs(const __half* A, int lda, long long sA,
                           const __half* B, int ldb, long long sB,
                           void* C, int ldc, long long sC,
                           const float* R, long long sR, int K, int mode) {
    GArgs a;
    a.A = A; a.lda = lda; a.sA = sA;
    a.B = B; a.ldb = ldb; a.sB = sB;
    a.C = C; a.ldc = ldc; a.sC = sC;
    a.R = R; a.sR = sR; a.K = K; a.mode = mode;
    a.flags = 0; a.scale = 0.f; a.mask = nullptr;
    a.Bm[0] = a.Bm[1] = a.Bm[2] = nullptr;
    a.Cm[0] = a.Cm[1] = a.Cm[2] = nullptr;
    a.nMulti = 0;
    return a;
}

extern "C" void kernel_launch(void* const* d_in, const int* in_sizes, int n_in,
                              void* d_out, int out_size) {
    const float* x_in    = (const float*)d_in[0];
    const float* Wq      = (const float*)d_in[1];
    const float* Wk      = (const float*)d_in[2];
    const float* Wv      = (const float*)d_in[3];
    const float* Wo      = (const float*)d_in[4];
    const float* lamb    = (const float*)d_in[5];
    const float* lambdas = (const float*)d_in[6];
    const float* Wfc     = (const float*)d_in[7];
    const float* Wp      = (const float*)d_in[8];
    const int*   levels  = (const int*)d_in[9];
    const int*   sample  = (const int*)d_in[10];

    float *x, *x0, *xl, *rs, *fc2;
    __half *xn, *q, *k, *v, *v1, *vt, *y, *h, *p;
    __half *wq, *wk, *wv, *wo, *wfc, *wp;
    int* cpad;
    unsigned char* mask;
    cudaGetSymbolAddress((void**)&x,  g_x);
    cudaGetSymbolAddress((void**)&x0, g_x0);
    cudaGetSymbolAddress((void**)&xl, g_xl);
    cudaGetSymbolAddress((void**)&xn, g_xn);
    cudaGetSymbolAddress((void**)&q,  g_q);
    cudaGetSymbolAddress((void**)&k,  g_k);
    cudaGetSymbolAddress((void**)&v,  g_v);
    cudaGetSymbolAddress((void**)&v1, g_v1);
    cudaGetSymbolAddress((void**)&vt, g_vt);
    cudaGetSymbolAddress((void**)&y,  g_y);
    cudaGetSymbolAddress((void**)&h,  g_h);
    cudaGetSymbolAddress((void**)&p,  g_p);
    cudaGetSymbolAddress((void**)&rs, g_rs);
    cudaGetSymbolAddress((void**)&fc2, g_fc2);
    cudaGetSymbolAddress((void**)&cpad, g_cpad);
    cudaGetSymbolAddress((void**)&mask, g_mask);
    cudaGetSymbolAddress((void**)&wq, g_wq);
    cudaGetSymbolAddress((void**)&wk, g_wk);
    cudaGetSymbolAddress((void**)&wv, g_wv);
    cudaGetSymbolAddress((void**)&wo, g_wo);
    cudaGetSymbolAddress((void**)&wfc, g_wfc);
    cudaGetSymbolAddress((void**)&wp, g_wp);

    const int SM128 = (128 + 128) * 72 * 2 * 2;  // 73728 bytes
    const int SM64  = (128 + 64) * 72 * 2 * 2;   // 55296 bytes
    cudaFuncSetAttribute(gemm4<128>, cudaFuncAttributeMaxDynamicSharedMemorySize, SM128);
    cudaFuncSetAttribute(gemm4<64>,  cudaFuncAttributeMaxDynamicSharedMemorySize, SM64);

    const int EW4 = (S * D / 4) / 256;
    const float scale = 1.0f / 8.0f;             // HD^-0.5

    // ---- stream-2 weight conversion, overlapped (measured -16us in R8) ----
    cudaStream_t s2;
    cudaStreamCreateWithFlags(&s2, cudaStreamNonBlocking);
    cudaEvent_t evRoot, evQKV, evWo, evWfc, evWp;
    cudaEventCreateWithFlags(&evRoot, cudaEventDisableTiming);
    cudaEventCreateWithFlags(&evQKV,  cudaEventDisableTiming);
    cudaEventCreateWithFlags(&evWo,   cudaEventDisableTiming);
    cudaEventCreateWithFlags(&evWfc,  cudaEventDisableTiming);
    cudaEventCreateWithFlags(&evWp,   cudaEventDisableTiming);

    cudaEventRecord(evRoot, 0);
    cudaStreamWaitEvent(s2, evRoot, 0);
    {
        int n8a = NL * D * D / 8;
        int n8b = NL * DFF * D / 8;
        tohalf2_k<<<(n8a + 255) / 256, 256, 0, s2>>>((const float4*)Wq, (uint4*)wq, n8a);
        tohalf2_k<<<(n8a + 255) / 256, 256, 0, s2>>>((const float4*)Wk, (uint4*)wk, n8a);
        tohalf2_k<<<(n8a + 255) / 256, 256, 0, s2>>>((const float4*)Wv, (uint4*)wv, n8a);
        cudaEventRecord(evQKV, s2);
        tohalf2_k<<<(n8a + 255) / 256, 256, 0, s2>>>((const float4*)Wo, (uint4*)wo, n8a);
        cudaEventRecord(evWo, s2);
        tohalf2_k<<<(n8b + 255) / 256, 256, 0, s2>>>((const float4*)Wfc, (uint4*)wfc, n8b);
        cudaEventRecord(evWfc, s2);
        tohalf2_k<<<(n8b + 255) / 256, 256, 0, s2>>>((const float4*)Wp, (uint4*)wp, n8b);
        cudaEventRecord(evWp, s2);
    }

    build_prefix_k<<<1, 32>>>(levels, cpad);
    build_mask_k<<<(S * S) / 256, 256>>>(levels, sample, cpad, mask);

    rms_rows_f_k<<<S, 256>>>(x_in, x);
    {
        int n4 = S * D / 4;
        copyu2_k<<<n4 / 256, 256>>>((const uint2*)x, (uint2*)(x0));
        copyu2_k<<<n4 / 256, 256>>>((const uint2*)(x + S * D / 2), (uint2*)(x0 + S * D / 2));
    }

    for (int i = 0; i < NL; i++) {
        const __half* Wqi = wq + (size_t)i * D * D;
        const __half* Wki = wk + (size_t)i * D * D;
        const __half* Wvi = wv + (size_t)i * D * D;
        const __half* Woi = wo + (size_t)i * D * D;
        const __half* Wfi = wfc + (size_t)i * DFF * D;
        const __half* Wpi = wp + (size_t)i * D * DFF;

        // xl = l0*x + l1*x0 ; xn = fp16(rms(xl))  (fused)
        xlrms_k<<<S, 256>>>((const float4*)x, (const float4*)x0, lambdas, i,
                            (float4*)xl, xn);

        // fused QKV (fp16 out; per-head RMS+RoPE fused for q,k via mode 6)
        if (i == 0) cudaStreamWaitEvent(0, evQKV, 0);
        {
            GArgs a = mkargs(xn, D, 0, nullptr, D, 0, nullptr, D, 0, nullptr, 0, D, 6);
            a.Bm[0] = Wqi; a.Bm[1] = Wki; a.Bm[2] = Wvi;
            a.Cm[0] = q;   a.Cm[1] = k;   a.Cm[2] = v;
            a.nMulti = 3;
            gemm4<128><<<dim3(D / 128, S / 128, 3), 128, SM128>>>(a);
        }

        if (i == 0) copyu2_k<<<EW4, 256>>>((const uint2*)v, (uint2*)v1);

        // vt = transpose((1-la)*v + la*v1)
        transmix_k<<<dim3(32, 32), dim3(32, 8)>>>(v, v1, lamb, i, vt);

        // p[h] = mask .* exp(scale * q_h k_h^T), lower-triangular blocks (fp16)
        {
            GArgs a = mkargs(q, D, HD, k, D, HD, p, S, (long long)S * S, nullptr, 0, HD, 3);
            a.flags = 1; a.scale = scale; a.mask = mask;
            gemm4<128><<<dim3(1, 1, H * 36), 128, SM128>>>(a);
        }

        rowsum_k<<<(H * S) / 8, 256>>>(p, rs);

        // y[:,h] = fp16((p_h @ V_h) * rs), K limited to row0+128
        {
            GArgs a = mkargs(p, S, (long long)S * S, vt, S, (long long)HD * S,
                             y, D, HD, rs, S, S, 4);
            a.flags = 2;
            gemm4<64><<<dim3(1, S / 128, H), 128, SM64>>>(a);
        }

        // x = xl + y @ Wo^T  (fp32 out)
        if (i == 0) cudaStreamWaitEvent(0, evWo, 0);
        {
            GArgs a = mkargs(y, D, 0, Woi, D, 0, x, D, 0, xl, 0, D, 1);
            gemm4<64><<<dim3(D / 64, S / 128, 1), 128, SM64>>>(a);
        }

        // h = fp16(relu(rms(x) @ Wfc^T)^2)
        rms_rows_h_k<<<S, 256>>>(x, xn);
        if (i == 0) cudaStreamWaitEvent(0, evWfc, 0);
        {
            GArgs a = mkargs(xn, D, 0, Wfi, D, 0, h, DFF, 0, nullptr, 0, D, 2);
            gemm4<128><<<dim3(DFF / 128, S / 128, 1), 128, SM128>>>(a);
        }

        // x += h @ Wp^T  via split-K x4 (fp32 partials) + reduce
        if (i == 0) cudaStreamWaitEvent(0, evWp, 0);
        {
            GArgs a = mkargs(h, DFF, 0, Wpi, DFF, 0, fc2, D, (long long)S * D,
                             nullptr, 0, DFF / 4, 0);
            a.flags = 4;
            gemm4<128><<<dim3(D / 128, S / 128, 4), 128, SM128>>>(a);
        }
        fc2_reduce_k<<<EW4, 256>>>((const float4*)fc2, (float4*)x);
    }

    rms_rows_f_k<<<S, 256>>>(x, (float*)d_out);
}

// round 12
// speedup vs baseline: 1.0922x; 1.0922x over previous
#include <cuda_runtime.h>
#include <cuda_fp16.h>
#include <math.h>
#include <stdint.h>

#define S 1024
#define D 1024
#define H 16
#define HD 64
#define NL 6
#define DFF 4096
#define EPS 1.1920929e-07f

// ---------------- scratch (device globals; no allocation) ----------------
__device__ float  g_x [S * D];
__device__ float  g_x0[S * D];
__device__ float  g_xl[S * D];
__device__ __half g_xn[S * D];
__device__ __half g_q [S * D];
__device__ __half g_k [S * D];
__device__ __half g_v [S * D];
__device__ __half g_v1[S * D];
__device__ __half g_vt[S * D];
__device__ __half g_y [S * D];
__device__ __half g_h [S * DFF];
__device__ __half g_p [(size_t)H * S * S];
__device__ float  g_fc2[4 * S * D];
__device__ int    g_cpad[S + 1];
__device__ unsigned char g_mask[(size_t)S * S];
// fp16 weight copies (converted once per replay)
__device__ __half g_wq[NL * D * D];
__device__ __half g_wk[NL * D * D];
__device__ __half g_wv[NL * D * D];
__device__ __half g_wo[NL * D * D];
__device__ __half g_wfc[(size_t)NL * DFF * D];
__device__ __half g_wp [(size_t)NL * DFF * D];

// ---------------- small kernels ----------------

// wide conversion: 32B read / 16B write per thread
__global__ void tohalf2_k(const float4* __restrict__ in, uint4* __restrict__ out, int n8) {
    int i = blockIdx.x * blockDim.x + threadIdx.x;
    if (i < n8) {
        float4 a = in[2 * i];
        float4 b = in[2 * i + 1];
        __half2 h0 = __floats2half2_rn(a.x, a.y);
        __half2 h1 = __floats2half2_rn(a.z, a.w);
        __half2 h2 = __floats2half2_rn(b.x, b.y);
        __half2 h3 = __floats2half2_rn(b.z, b.w);
        uint4 r;
        r.x = *(uint32_t*)&h0;
        r.y = *(uint32_t*)&h1;
        r.z = *(uint32_t*)&h2;
        r.w = *(uint32_t*)&h3;
        out[i] = r;
    }
}

__global__ void build_prefix_k(const int* __restrict__ levels, int* __restrict__ cpad) {
    if (threadIdx.x == 0) {
        cpad[0] = 0;
        for (int i = 0; i < S; i++) cpad[i + 1] = cpad[i] + (levels[i] == 0 ? 1 : 0);
    }
}

__global__ void build_mask_k(const int* __restrict__ levels, const int* __restrict__ sample,
                             const int* __restrict__ cpad, unsigned char* __restrict__ mask) {
    int idx = blockIdx.x * blockDim.x + threadIdx.x;
    int q = idx >> 10;
    int k = idx & 1023;
    bool causal = q >= k;
    bool same = sample[q] == sample[k];
    int cnt = cpad[q] - cpad[k + 1];
    bool markov = (levels[k] == 0) && (cnt > 0);
    mask[idx] = (causal && same && !markov) ? 1 : 0;
}

// RMS over fp32 rows of length D -> fp32 out — one row per block
__global__ void rms_rows_f_k(const float* __restrict__ in, float* __restrict__ out) {
    int row = blockIdx.x;
    const float4* p = (const float4*)(in + (size_t)row * D);
    float4* o = (float4*)(out + (size_t)row * D);
    int tid = threadIdx.x;
    float4 t = p[tid];
    float ss = t.x * t.x + t.y * t.y + t.z * t.z + t.w * t.w;
    __shared__ float red[256];
    red[tid] = ss;
    __syncthreads();
    for (int s = 128; s > 0; s >>= 1) {
        if (tid < s) red[tid] += red[tid + s];
        __syncthreads();
    }
    float sc = rsqrtf(red[0] / (float)D + EPS);
    o[tid] = make_float4(t.x * sc, t.y * sc, t.z * sc, t.w * sc);
}

// RMS over fp32 rows of length D -> fp16 out
__global__ void rms_rows_h_k(const float* __restrict__ in, __half* __restrict__ out) {
    int row = blockIdx.x;
    const float4* p = (const float4*)(in + (size_t)row * D);
    uint2* o = (uint2*)(out + (size_t)row * D);
    int tid = threadIdx.x;
    float4 t = p[tid];
    float ss = t.x * t.x + t.y * t.y + t.z * t.z + t.w * t.w;
    __shared__ float red[256];
    red[tid] = ss;
    __syncthreads();
    for (int s = 128; s > 0; s >>= 1) {
        if (tid < s) red[tid] += red[tid + s];
        __syncthreads();
    }
    float sc = rsqrtf(red[0] / (float)D + EPS);
    __half2 a = __floats2half2_rn(t.x * sc, t.y * sc);
    __half2 b = __floats2half2_rn(t.z * sc, t.w * sc);
    uint2 r;
    r.x = *(uint32_t*)&a;
    r.y = *(uint32_t*)&b;
    o[tid] = r;
}

// fused: xl = l0*x + l1*x0 ; xn = fp16(rms(xl)). One row per block. (layer 0)
__global__ void xlrms_k(const float4* __restrict__ x, const float4* __restrict__ x0,
                        const float* __restrict__ lambdas, int layer,
                        float4* __restrict__ xl, __half* __restrict__ xn) {
    int row = blockIdx.x;
    int tid = threadIdx.x;
    int i = row * 256 + tid;
    float l0 = lambdas[layer * 2 + 0];
    float l1 = lambdas[layer * 2 + 1];
    float4 a = x[i], b = x0[i];
    float4 t = make_float4(l0 * a.x + l1 * b.x, l0 * a.y + l1 * b.y,
                           l0 * a.z + l1 * b.z, l0 * a.w + l1 * b.w);
    xl[i] = t;
    float ss = t.x * t.x + t.y * t.y + t.z * t.z + t.w * t.w;
    __shared__ float red[256];
    red[tid] = ss;
    __syncthreads();
    for (int s = 128; s > 0; s >>= 1) {
        if (tid < s) red[tid] += red[tid + s];
        __syncthreads();
    }
    float sc = rsqrtf(red[0] / (float)D + EPS);
    __half2 h0 = __floats2half2_rn(t.x * sc, t.y * sc);
    __half2 h1 = __floats2half2_rn(t.z * sc, t.w * sc);
    uint2 r;
    r.x = *(uint32_t*)&h0;
    r.y = *(uint32_t*)&h1;
    ((uint2*)xn)[i] = r;
}

// fused: x += 4 FC2 partials (store); xl = l0*x + l1*x0; xn = fp16(rms(xl)). (layers 1..5)
__global__ void xlrms_red_k(float4* __restrict__ x, const float4* __restrict__ part,
                            const float4* __restrict__ x0,
                            const float* __restrict__ lambdas, int layer,
                            float4* __restrict__ xl, __half* __restrict__ xn) {
    int row = blockIdx.x;
    int tid = threadIdx.x;
    int i = row * 256 + tid;
    const int N4 = S * D / 4;
    float4 xv = x[i];
    #pragma unroll
    for (int j = 0; j < 4; j++) {
        float4 t = part[(size_t)j * N4 + i];
        xv.x += t.x; xv.y += t.y; xv.z += t.z; xv.w += t.w;
    }
    x[i] = xv;
    float l0 = lambdas[layer * 2 + 0];
    float l1 = lambdas[layer * 2 + 1];
    float4 b = x0[i];
    float4 t = make_float4(l0 * xv.x + l1 * b.x, l0 * xv.y + l1 * b.y,
                           l0 * xv.z + l1 * b.z, l0 * xv.w + l1 * b.w);
    xl[i] = t;
    float ss = t.x * t.x + t.y * t.y + t.z * t.z + t.w * t.w;
    __shared__ float red[256];
    red[tid] = ss;
    __syncthreads();
    for (int s = 128; s > 0; s >>= 1) {
        if (tid < s) red[tid] += red[tid + s];
        __syncthreads();
    }
    float sc = rsqrtf(red[0] / (float)D + EPS);
    __half2 h0 = __floats2half2_rn(t.x * sc, t.y * sc);
    __half2 h1 = __floats2half2_rn(t.z * sc, t.w * sc);
    uint2 r;
    r.x = *(uint32_t*)&h0;
    r.y = *(uint32_t*)&h1;
    ((uint2*)xn)[i] = r;
}

// final: out = rms(x + 4 FC2 partials)
__global__ void final_red_rms_k(const float4* __restrict__ x, const float4* __restrict__ part,
                                float4* __restrict__ out) {
    int row = blockIdx.x;
    int tid = threadIdx.x;
    int i = row * 256 + tid;
    const int N4 = S * D / 4;
    float4 xv = x[i];
    #pragma unroll
    for (int j = 0; j < 4; j++) {
        float4 t = part[(size_t)j * N4 + i];
        xv.x += t.x; xv.y += t.y; xv.z += t.z; xv.w += t.w;
    }
    float ss = xv.x * xv.x + xv.y * xv.y + xv.z * xv.z + xv.w * xv.w;
    __shared__ float red[256];
    red[tid] = ss;
    __syncthreads();
    for (int s = 128; s > 0; s >>= 1) {
        if (tid < s) red[tid] += red[tid + s];
        __syncthreads();
    }
    float sc = rsqrtf(red[0] / (float)D + EPS);
    out[i] = make_float4(xv.x * sc, xv.y * sc, xv.z * sc, xv.w * sc);
}

// fused per-(s,h) RMS + RoPE on fp16 q and k (blockIdx.y selects tensor)
__global__ void rmsrope2_k(__half* __restrict__ q, __half* __restrict__ k) {
    __half* t = blockIdx.y ? k : q;
    int warp = (blockIdx.x * blockDim.x + threadIdx.x) >> 5;
    int lane = threadIdx.x & 31;
    int s = warp >> 4;
    __half* p = t + (size_t)warp * 64;
    float a = __half2float(p[lane]);
    float b = __half2float(p[lane + 32]);
    float ss = a * a + b * b;
    #pragma unroll
    for (int o = 16; o; o >>= 1) ss += __shfl_xor_sync(0xFFFFFFFFu, ss, o);
    float sc = rsqrtf(ss / 64.f + EPS);
    a *= sc; b *= sc;
    float inv = powf(10000.f, -((float)(2 * lane)) / 64.f);
    float fr = (float)s * inv;
    float cs, sn;
    sincosf(fr, &sn, &cs);
    p[lane]      = __float2half_rn(a * cs + b * sn);
    p[lane + 32] = __float2half_rn(-a * sn + b * cs);
}

__global__ void copyu2_k(const uint2* __restrict__ in, uint2* __restrict__ out) {
    int i = blockIdx.x * blockDim.x + threadIdx.x;
    out[i] = in[i];
}

// fused v-mix + transpose: vt[c][r] = (1-la)*v[r][c] + la*v1[r][c]
__global__ void transmix_k(const __half* __restrict__ v, const __half* __restrict__ v1,
                           const float* __restrict__ lamb, int layer,
                           __half* __restrict__ vt) {
    __shared__ __half tile[32][34];
    float la = lamb[layer];
    float om = 1.f - la;
    int x = blockIdx.x * 32 + threadIdx.x;
    int y0 = blockIdx.y * 32 + threadIdx.y;
    #pragma unroll
    for (int j = 0; j < 32; j += 8) {
        size_t idx = (size_t)(y0 + j) * D + x;
        float mv = om * __half2float(v[idx]) + la * __half2float(v1[idx]);
        tile[threadIdx.y + j][threadIdx.x] = __float2half_rn(mv);
    }
    __syncthreads();
    int x2 = blockIdx.y * 32 + threadIdx.x;
    int y2 = blockIdx.x * 32 + threadIdx.y;
    #pragma unroll
    for (int j = 0; j < 32; j += 8)
        vt[(size_t)(y2 + j) * D + x2] = tile[threadIdx.x][threadIdx.y + j];
}

// ---------------- pipelined fp16 mma.sync GEMM (m16n8k16, ldmatrix), 4 warps ----------------
// C[M,N] = A[M,K] * B[N,K]^T  (NT; fp16 row-major, K contiguous)
// modes: 0 fp32 raw | 1 fp32 acc+R | 2 fp16 relu(acc)^2 | 3 fp16 mask?exp(acc*scale):0
//        5 fp16 raw | 7 fp16 acc/rowsum(A)  (rowsum computed in-kernel from staged A tiles)
// flags: 1 = triangular launch (z=h*36+t); 2 = K limited to row0+128; 4 = split-K over z

struct GArgs {
    const __half* A; int lda; long long sA;
    const __half* B; int ldb; long long sB;
    void* C; int ldc; long long sC;
    const float* R; long long sR;
    int K; int mode; int flags; float scale;
    const unsigned char* mask;
    const __half* Bm[3]; void* Cm[3]; int nMulti;
};

#define LDMX4(r0, r1, r2, r3, addr) \
    asm volatile("ldmatrix.sync.aligned.m8n8.x4.shared.b16 {%0,%1,%2,%3}, [%4];" \
                 : "=r"(r0), "=r"(r1), "=r"(r2), "=r"(r3) : "r"(addr))

template<int BN>
__global__ __launch_bounds__(128, 2) void gemm4(GArgs a) {
    constexpr int BM = 128, BK = 64;          // halves per K-tile (128 bytes/row)
    constexpr int SROW = 72;                  // padded row in halves (144B)
    constexpr int SSZ = (BM + BN) * SROW;     // halves per stage
    constexpr int WN = BN / 2;
    constexpr int FM = 4, FN = WN / 8;        // 64 x {64|32} per warp
    constexpr int CA = 8, CB = BN / 16;       // cp.async 16B chunks per thread
    extern __shared__ __half sh[];
    __shared__ float rowsumsh[BM];

    int tid = threadIdx.x, lane = tid & 31, warp = tid >> 5;
    int row0, col0, koff = 0;
    const __half *A, *B;
    char* C;
    const float* R = nullptr;
    int z = blockIdx.z;

    if (a.flags & 1) {
        int t = z % 36, h = z / 36;
        int by = 0;
        while ((by + 1) * (by + 2) / 2 <= t) by++;
        int bx = t - by * (by + 1) / 2;
        row0 = by * BM; col0 = bx * BN;
        A = a.A + (size_t)h * a.sA;
        B = a.B + (size_t)h * a.sB;
        C = (char*)a.C + (size_t)h * a.sC * 2;      // fp16 C
    } else {
        row0 = blockIdx.y * BM; col0 = blockIdx.x * BN;
        if (a.flags & 4) {
            A = a.A; B = a.B;
            C = (char*)a.C + (size_t)z * a.sC * 4;  // fp32 partials
            koff = z * a.K;
        } else if (a.nMulti) {
            A = a.A; B = a.Bm[z]; C = (char*)a.Cm[z];
        } else {
            A = a.A + (size_t)z * a.sA;
            B = a.B + (size_t)z * a.sB;
            int esz = (a.mode == 0 || a.mode == 1) ? 4 : 2;
            C = (char*)a.C + (size_t)z * a.sC * esz;
            if (a.R) R = a.R + (size_t)z * a.sR;
        }
    }

    int K = a.K;
    if (a.flags & 2) { int kl = row0 + BM; if (kl < K) K = kl; }
    int KT = K / BK;

    auto issue = [&](int kt, int st) {
        __half* dstA = sh + st * SSZ;
        #pragma unroll
        for (int i = 0; i < CA; i++) {
            int id = tid + 128 * i;
            int r = id >> 3, c = id & 7;
            unsigned u = (unsigned)__cvta_generic_to_shared(dstA + r * SROW + c * 8);
            const __half* gp = A + (size_t)(row0 + r) * a.lda + koff + kt * BK + c * 8;
            asm volatile("cp.async.cg.shared.global [%0], [%1], 16;\n" :: "r"(u), "l"(gp));
        }
        __half* dstB = sh + st * SSZ + BM * SROW;
        #pragma unroll
        for (int i = 0; i < CB; i++) {
            int id = tid + 128 * i;
            int r = id >> 3, c = id & 7;
            unsigned u = (unsigned)__cvta_generic_to_shared(dstB + r * SROW + c * 8);
            const __half* gp = B + (size_t)(col0 + r) * a.ldb + koff + kt * BK + c * 8;
            asm volatile("cp.async.cg.shared.global [%0], [%1], 16;\n" :: "r"(u), "l"(gp));
        }
        asm volatile("cp.async.commit_group;\n");
    };

    float acc[FM][FN][4] = {};
    float rsum_acc = 0.f;

    issue(0, 0);
    if (KT > 1) issue(1, 1);

    int wm0 = (warp & 1) * 64, wn0 = (warp >> 1) * WN;
    int g = lane >> 2, tig = lane & 3;

    uint32_t shb = (uint32_t)__cvta_generic_to_shared(sh);
    int laneq = lane & 7, lane8 = (lane >> 3) & 1, lane16 = lane >> 4;
    uint32_t aoff = (uint32_t)((wm0 + laneq + 8 * lane8) * SROW + 8 * lane16);
    uint32_t boff = (uint32_t)((wn0 + laneq + 8 * lane16) * SROW + 8 * lane8);

    for (int kt = 0; kt < KT; kt++) {
        if (kt + 2 <= KT) asm volatile("cp.async.wait_group 1;\n");
        else              asm volatile("cp.async.wait_group 0;\n");
        __syncthreads();

        uint32_t sAb = shb + (uint32_t)((kt & 1) * SSZ) * 2;
        uint32_t sBb = sAb + BM * SROW * 2;

        // in-kernel A row sums for PV normalization (reads staged tile before overwrite)
        if (a.mode == 7) {
            const __half2* rowp = (const __half2*)(sh + (kt & 1) * SSZ + tid * SROW);
            float s = 0.f;
            #pragma unroll
            for (int j = 0; j < 32; j++) {
                float2 f = __half22float2(rowp[j]);
                s += f.x + f.y;
            }
            rsum_acc += s;
        }

        #pragma unroll
        for (int s16 = 0; s16 < BK; s16 += 16) {
            uint32_t af[FM][4], bf[FN][2];
            #pragma unroll
            for (int fm = 0; fm < FM; fm++) {
                LDMX4(af[fm][0], af[fm][1], af[fm][2], af[fm][3],
                      sAb + (aoff + fm * 16 * SROW + s16) * 2);
            }
            #pragma unroll
            for (int fp = 0; fp < FN / 2; fp++) {
                LDMX4(bf[2 * fp][0], bf[2 * fp][1], bf[2 * fp + 1][0], bf[2 * fp + 1][1],
                      sBb + (boff + fp * 16 * SROW + s16) * 2);
            }
            #pragma unroll
            for (int fm = 0; fm < FM; fm++)
                #pragma unroll
                for (int fn = 0; fn < FN; fn++) {
                    asm volatile(
                        "mma.sync.aligned.m16n8k16.row.col.f32.f16.f16.f32 "
                        "{%0,%1,%2,%3}, {%4,%5,%6,%7}, {%8,%9}, {%0,%1,%2,%3};\n"
                        : "+f"(acc[fm][fn][0]), "+f"(acc[fm][fn][1]),
                          "+f"(acc[fm][fn][2]), "+f"(acc[fm][fn][3])
                        : "r"(af[fm][0]), "r"(af[fm][1]), "r"(af[fm][2]), "r"(af[fm][3]),
                          "r"(bf[fn][0]), "r"(bf[fn][1]));
                }
        }
        __syncthreads();
        if (kt + 2 < KT) issue(kt + 2, kt & 1);
    }

    if (a.mode == 7) {
        rowsumsh[tid] = rsum_acc;
        __syncthreads();
    }

    // epilogue
    #pragma unroll
    for (int fm = 0; fm < FM; fm++) {
        #pragma unroll
        for (int fn = 0; fn < FN; fn++) {
            int r0 = row0 + wm0 + fm * 16 + g;
            int c  = col0 + wn0 + fn * 8 + 2 * tig;
            #pragma unroll
            for (int half = 0; half < 2; half++) {
                int r = r0 + 8 * half;
                float v0 = acc[fm][fn][2 * half + 0];
                float v1 = acc[fm][fn][2 * half + 1];
                size_t off = (size_t)r * a.ldc + c;
                if (a.mode == 0) {
                    ((float*)C)[off] = v0;
                    ((float*)C)[off + 1] = v1;
                } else if (a.mode == 1) {
                    ((float*)C)[off] = v0 + R[off];
                    ((float*)C)[off + 1] = v1 + R[off + 1];
                } else {
                    if (a.mode == 2) {
                        v0 = fmaxf(v0, 0.f); v0 *= v0;
                        v1 = fmaxf(v1, 0.f); v1 *= v1;
                    } else if (a.mode == 3) {
                        const unsigned char* m = a.mask + (size_t)r * S + c;
                        v0 = m[0] ? __expf(v0 * a.scale) : 0.f;
                        v1 = m[1] ? __expf(v1 * a.scale) : 0.f;
                    } else if (a.mode == 7) {
                        float rsv = 1.0f / rowsumsh[r - row0];
                        v0 *= rsv;
                        v1 *= rsv;
                    }
                    __half2 hv = __floats2half2_rn(v0, v1);
                    *(__half2*)((__half*)C + off) = hv;
                }
            }
        }
    }
}

// ---------------- host orchestration ----------------

static inline GArgs mkargs(const __half* A, int lda, long long sA,
                           const __half* B, int ldb, long long sB,
                           void* C, int ldc, long long sC,
                           const float* R, long long sR, int K, int mode) {
    GArgs a;
    a.A = A; a.lda = lda; a.sA = sA;
    a.B = B; a.ldb = ldb; a.sB = sB;
    a.C = C; a.ldc = ldc; a.sC = sC;
    a.R = R; a.sR = sR; a.K = K; a.mode = mode;
    a.flags = 0; a.scale = 0.f; a.mask = nullptr;
    a.Bm[0] = a.Bm[1] = a.Bm[2] = nullptr;
    a.Cm[0] = a.Cm[1] = a.Cm[2] = nullptr;
    a.nMulti = 0;
    return a;
}

extern "C" void kernel_launch(void* const* d_in, const int* in_sizes, int n_in,
                              void* d_out, int out_size) {
    const float* x_in    = (const float*)d_in[0];
    const float* Wq      = (const float*)d_in[1];
    const float* Wk      = (const float*)d_in[2];
    const float* Wv      = (const float*)d_in[3];
    const float* Wo      = (const float*)d_in[4];
    const float* lamb    = (const float*)d_in[5];
    const float* lambdas = (const float*)d_in[6];
    const float* Wfc     = (const float*)d_in[7];
    const float* Wp      = (const float*)d_in[8];
    const int*   levels  = (const int*)d_in[9];
    const int*   sample  = (const int*)d_in[10];

    float *x, *x0, *xl, *fc2;
    __half *xn, *q, *k, *v, *v1, *vt, *y, *h, *p;
    __half *wq, *wk, *wv, *wo, *wfc, *wp;
    int* cpad;
    unsigned char* mask;
    cudaGetSymbolAddress((void**)&x,  g_x);
    cudaGetSymbolAddress((void**)&x0, g_x0);
    cudaGetSymbolAddress((void**)&xl, g_xl);
    cudaGetSymbolAddress((void**)&xn, g_xn);
    cudaGetSymbolAddress((void**)&q,  g_q);
    cudaGetSymbolAddress((void**)&k,  g_k);
    cudaGetSymbolAddress((void**)&v,  g_v);
    cudaGetSymbolAddress((void**)&v1, g_v1);
    cudaGetSymbolAddress((void**)&vt, g_vt);
    cudaGetSymbolAddress((void**)&y,  g_y);
    cudaGetSymbolAddress((void**)&h,  g_h);
    cudaGetSymbolAddress((void**)&p,  g_p);
    cudaGetSymbolAddress((void**)&fc2, g_fc2);
    cudaGetSymbolAddress((void**)&cpad, g_cpad);
    cudaGetSymbolAddress((void**)&mask, g_mask);
    cudaGetSymbolAddress((void**)&wq, g_wq);
    cudaGetSymbolAddress((void**)&wk, g_wk);
    cudaGetSymbolAddress((void**)&wv, g_wv);
    cudaGetSymbolAddress((void**)&wo, g_wo);
    cudaGetSymbolAddress((void**)&wfc, g_wfc);
    cudaGetSymbolAddress((void**)&wp, g_wp);

    const int SM128 = (128 + 128) * 72 * 2 * 2;  // 73728 bytes
    const int SM64  = (128 + 64) * 72 * 2 * 2;   // 55296 bytes
    cudaFuncSetAttribute(gemm4<128>, cudaFuncAttributeMaxDynamicSharedMemorySize, SM128);
    cudaFuncSetAttribute(gemm4<64>,  cudaFuncAttributeMaxDynamicSharedMemorySize, SM64);

    const int EW4 = (S * D / 4) / 256;
    const float scale = 1.0f / 8.0f;             // HD^-0.5

    // convert all weights to fp16 once per replay (serial, wide accesses)
    {
        int n8a = NL * D * D / 8;
        int n8b = NL * DFF * D / 8;
        tohalf2_k<<<(n8a + 255) / 256, 256>>>((const float4*)Wq, (uint4*)wq, n8a);
        tohalf2_k<<<(n8a + 255) / 256, 256>>>((const float4*)Wk, (uint4*)wk, n8a);
        tohalf2_k<<<(n8a + 255) / 256, 256>>>((const float4*)Wv, (uint4*)wv, n8a);
        tohalf2_k<<<(n8a + 255) / 256, 256>>>((const float4*)Wo, (uint4*)wo, n8a);
        tohalf2_k<<<(n8b + 255) / 256, 256>>>((const float4*)Wfc, (uint4*)wfc, n8b);
        tohalf2_k<<<(n8b + 255) / 256, 256>>>((const float4*)Wp, (uint4*)wp, n8b);
    }

    build_prefix_k<<<1, 32>>>(levels, cpad);
    build_mask_k<<<(S * S) / 256, 256>>>(levels, sample, cpad, mask);

    rms_rows_f_k<<<S, 256>>>(x_in, x);
    {
        int n4 = S * D / 4;
        copyu2_k<<<n4 / 256, 256>>>((const uint2*)x, (uint2*)(x0));
        copyu2_k<<<n4 / 256, 256>>>((const uint2*)(x + S * D / 2), (uint2*)(x0 + S * D / 2));
    }

    for (int i = 0; i < NL; i++) {
        const __half* Wqi = wq + (size_t)i * D * D;
        const __half* Wki = wk + (size_t)i * D * D;
        const __half* Wvi = wv + (size_t)i * D * D;
        const __half* Woi = wo + (size_t)i * D * D;
        const __half* Wfi = wfc + (size_t)i * DFF * D;
        const __half* Wpi = wp + (size_t)i * D * DFF;

        // xl/xn prep; layers >=1 also fold in previous layer's FC2 partials
        if (i == 0)
            xlrms_k<<<S, 256>>>((const float4*)x, (const float4*)x0, lambdas, i,
                                (float4*)xl, xn);
        else
            xlrms_red_k<<<S, 256>>>((float4*)x, (const float4*)fc2, (const float4*)x0,
                                    lambdas, i, (float4*)xl, xn);

        // fused QKV (fp16 out)
        {
            GArgs a = mkargs(xn, D, 0, nullptr, D, 0, nullptr, D, 0, nullptr, 0, D, 5);
            a.Bm[0] = Wqi; a.Bm[1] = Wki; a.Bm[2] = Wvi;
            a.Cm[0] = q;   a.Cm[1] = k;   a.Cm[2] = v;
            a.nMulti = 3;
            gemm4<128><<<dim3(D / 128, S / 128, 3), 128, SM128>>>(a);
        }

        if (i == 0) copyu2_k<<<EW4, 256>>>((const uint2*)v, (uint2*)v1);

        rmsrope2_k<<<dim3((S * H) / 8, 2), 256>>>(q, k);

        // vt = transpose((1-la)*v + la*v1)
        transmix_k<<<dim3(32, 32), dim3(32, 8)>>>(v, v1, lamb, i, vt);

        // p[h] = mask .* exp(scale * q_h k_h^T), lower-triangular blocks (fp16)
        {
            GArgs a = mkargs(q, D, HD, k, D, HD, p, S, (long long)S * S, nullptr, 0, HD, 3);
            a.flags = 1; a.scale = scale; a.mask = mask;
            gemm4<128><<<dim3(1, 1, H * 36), 128, SM128>>>(a);
        }

        // y[:,h] = fp16((p_h @ V_h) / rowsum), rowsum computed in-kernel (mode 7)
        {
            GArgs a = mkargs(p, S, (long long)S * S, vt, S, (long long)HD * S,
                             y, D, HD, nullptr, 0, S, 7);
            a.flags = 2;
            gemm4<64><<<dim3(1, S / 128, H), 128, SM64>>>(a);
        }

        // x = xl + y @ Wo^T  (fp32 out)
        {
            GArgs a = mkargs(y, D, 0, Woi, D, 0, x, D, 0, xl, 0, D, 1);
            gemm4<64><<<dim3(D / 64, S / 128, 1), 128, SM64>>>(a);
        }

        // h = fp16(relu(rms(x) @ Wfc^T)^2)
        rms_rows_h_k<<<S, 256>>>(x, xn);
        {
            GArgs a = mkargs(xn, D, 0, Wfi, D, 0, h, DFF, 0, nullptr, 0, D, 2);
            gemm4<128><<<dim3(DFF / 128, S / 128, 1), 128, SM128>>>(a);
        }

        // FC2 split-K x4 partials (reduced by next layer's xlrms_red / final rms)
        {
            GArgs a = mkargs(h, DFF, 0, Wpi, DFF, 0, fc2, D, (long long)S * D,
                             nullptr, 0, DFF / 4, 0);
            a.flags = 4;
            gemm4<128><<<dim3(D / 128, S / 128, 4), 128, SM128>>>(a);
        }
    }

    // out = rms(x + FC2 partials of last layer)
    final_red_rms_k<<<S, 256>>>((const float4*)x, (const float4*)fc2, (float4*)d_out);
}

// round 13
// speedup vs baseline: 1.1053x; 1.0119x over previous
#include <cuda_runtime.h>
#include <cuda_fp16.h>
#include <math.h>
#include <stdint.h>

#define S 1024
#define D 1024
#define H 16
#define HD 64
#define NL 6
#define DFF 4096
#define EPS 1.1920929e-07f

// ---------------- scratch (device globals; no allocation) ----------------
__device__ float  g_x [S * D];
__device__ float  g_x0[S * D];
__device__ float  g_xl[S * D];
__device__ __half g_xn[S * D];
__device__ __half g_q [S * D];
__device__ __half g_k [S * D];
__device__ __half g_v [S * D];
__device__ __half g_v1[S * D];
__device__ __half g_vt[S * D];
__device__ __half g_y [S * D];
__device__ __half g_h [S * DFF];
__device__ __half g_p [(size_t)H * S * S];
__device__ float  g_fc2[4 * S * D];
__device__ int    g_cpad[S + 1];
__device__ unsigned char g_mask[(size_t)S * S];
// fp16 weight copies (converted once per replay, overlapped on stream 2)
__device__ __half g_wq[NL * D * D];
__device__ __half g_wk[NL * D * D];
__device__ __half g_wv[NL * D * D];
__device__ __half g_wo[NL * D * D];
__device__ __half g_wfc[(size_t)NL * DFF * D];
__device__ __half g_wp [(size_t)NL * DFF * D];

// ---------------- small kernels ----------------

// wide conversion: 32B read / 16B write per thread
__global__ void tohalf2_k(const float4* __restrict__ in, uint4* __restrict__ out, int n8) {
    int i = blockIdx.x * blockDim.x + threadIdx.x;
    if (i < n8) {
        float4 a = in[2 * i];
        float4 b = in[2 * i + 1];
        __half2 h0 = __floats2half2_rn(a.x, a.y);
        __half2 h1 = __floats2half2_rn(a.z, a.w);
        __half2 h2 = __floats2half2_rn(b.x, b.y);
        __half2 h3 = __floats2half2_rn(b.z, b.w);
        uint4 r;
        r.x = *(uint32_t*)&h0;
        r.y = *(uint32_t*)&h1;
        r.z = *(uint32_t*)&h2;
        r.w = *(uint32_t*)&h3;
        out[i] = r;
    }
}

__global__ void build_prefix_k(const int* __restrict__ levels, int* __restrict__ cpad) {
    if (threadIdx.x == 0) {
        cpad[0] = 0;
        for (int i = 0; i < S; i++) cpad[i + 1] = cpad[i] + (levels[i] == 0 ? 1 : 0);
    }
}

__global__ void build_mask_k(const int* __restrict__ levels, const int* __restrict__ sample,
                             const int* __restrict__ cpad, unsigned char* __restrict__ mask) {
    int idx = blockIdx.x * blockDim.x + threadIdx.x;
    int q = idx >> 10;
    int k = idx & 1023;
    bool causal = q >= k;
    bool same = sample[q] == sample[k];
    int cnt = cpad[q] - cpad[k + 1];
    bool markov = (levels[k] == 0) && (cnt > 0);
    mask[idx] = (causal && same && !markov) ? 1 : 0;
}

// RMS over fp32 rows of length D -> fp32 out — one row per block
__global__ void rms_rows_f_k(const float* __restrict__ in, float* __restrict__ out) {
    int row = blockIdx.x;
    const float4* p = (const float4*)(in + (size_t)row * D);
    float4* o = (float4*)(out + (size_t)row * D);
    int tid = threadIdx.x;
    float4 t = p[tid];
    float ss = t.x * t.x + t.y * t.y + t.z * t.z + t.w * t.w;
    __shared__ float red[256];
    red[tid] = ss;
    __syncthreads();
    for (int s = 128; s > 0; s >>= 1) {
        if (tid < s) red[tid] += red[tid + s];
        __syncthreads();
    }
    float sc = rsqrtf(red[0] / (float)D + EPS);
    o[tid] = make_float4(t.x * sc, t.y * sc, t.z * sc, t.w * sc);
}

// RMS over fp32 rows of length D -> fp16 out
__global__ void rms_rows_h_k(const float* __restrict__ in, __half* __restrict__ out) {
    int row = blockIdx.x;
    const float4* p = (const float4*)(in + (size_t)row * D);
    uint2* o = (uint2*)(out + (size_t)row * D);
    int tid = threadIdx.x;
    float4 t = p[tid];
    float ss = t.x * t.x + t.y * t.y + t.z * t.z + t.w * t.w;
    __shared__ float red[256];
    red[tid] = ss;
    __syncthreads();
    for (int s = 128; s > 0; s >>= 1) {
        if (tid < s) red[tid] += red[tid + s];
        __syncthreads();
    }
    float sc = rsqrtf(red[0] / (float)D + EPS);
    __half2 a = __floats2half2_rn(t.x * sc, t.y * sc);
    __half2 b = __floats2half2_rn(t.z * sc, t.w * sc);
    uint2 r;
    r.x = *(uint32_t*)&a;
    r.y = *(uint32_t*)&b;
    o[tid] = r;
}

// fused: xl = l0*x + l1*x0 ; xn = fp16(rms(xl)). One row per block. (layer 0)
__global__ void xlrms_k(const float4* __restrict__ x, const float4* __restrict__ x0,
                        const float* __restrict__ lambdas, int layer,
                        float4* __restrict__ xl, __half* __restrict__ xn) {
    int row = blockIdx.x;
    int tid = threadIdx.x;
    int i = row * 256 + tid;
    float l0 = lambdas[layer * 2 + 0];
    float l1 = lambdas[layer * 2 + 1];
    float4 a = x[i], b = x0[i];
    float4 t = make_float4(l0 * a.x + l1 * b.x, l0 * a.y + l1 * b.y,
                           l0 * a.z + l1 * b.z, l0 * a.w + l1 * b.w);
    xl[i] = t;
    float ss = t.x * t.x + t.y * t.y + t.z * t.z + t.w * t.w;
    __shared__ float red[256];
    red[tid] = ss;
    __syncthreads();
    for (int s = 128; s > 0; s >>= 1) {
        if (tid < s) red[tid] += red[tid + s];
        __syncthreads();
    }
    float sc = rsqrtf(red[0] / (float)D + EPS);
    __half2 h0 = __floats2half2_rn(t.x * sc, t.y * sc);
    __half2 h1 = __floats2half2_rn(t.z * sc, t.w * sc);
    uint2 r;
    r.x = *(uint32_t*)&h0;
    r.y = *(uint32_t*)&h1;
    ((uint2*)xn)[i] = r;
}

// fused: x += 4 FC2 partials (store); xl = l0*x + l1*x0; xn = fp16(rms(xl)). (layers 1..5)
__global__ void xlrms_red_k(float4* __restrict__ x, const float4* __restrict__ part,
                            const float4* __restrict__ x0,
                            const float* __restrict__ lambdas, int layer,
                            float4* __restrict__ xl, __half* __restrict__ xn) {
    int row = blockIdx.x;
    int tid = threadIdx.x;
    int i = row * 256 + tid;
    const int N4 = S * D / 4;
    float4 xv = x[i];
    #pragma unroll
    for (int j = 0; j < 4; j++) {
        float4 t = part[(size_t)j * N4 + i];
        xv.x += t.x; xv.y += t.y; xv.z += t.z; xv.w += t.w;
    }
    x[i] = xv;
    float l0 = lambdas[layer * 2 + 0];
    float l1 = lambdas[layer * 2 + 1];
    float4 b = x0[i];
    float4 t = make_float4(l0 * xv.x + l1 * b.x, l0 * xv.y + l1 * b.y,
                           l0 * xv.z + l1 * b.z, l0 * xv.w + l1 * b.w);
    xl[i] = t;
    float ss = t.x * t.x + t.y * t.y + t.z * t.z + t.w * t.w;
    __shared__ float red[256];
    red[tid] = ss;
    __syncthreads();
    for (int s = 128; s > 0; s >>= 1) {
        if (tid < s) red[tid] += red[tid + s];
        __syncthreads();
    }
    float sc = rsqrtf(red[0] / (float)D + EPS);
    __half2 h0 = __floats2half2_rn(t.x * sc, t.y * sc);
    __half2 h1 = __floats2half2_rn(t.z * sc, t.w * sc);
    uint2 r;
    r.x = *(uint32_t*)&h0;
    r.y = *(uint32_t*)&h1;
    ((uint2*)xn)[i] = r;
}

// final: out = rms(x + 4 FC2 partials)
__global__ void final_red_rms_k(const float4* __restrict__ x, const float4* __restrict__ part,
                                float4* __restrict__ out) {
    int row = blockIdx.x;
    int tid = threadIdx.x;
    int i = row * 256 + tid;
    const int N4 = S * D / 4;
    float4 xv = x[i];
    #pragma unroll
    for (int j = 0; j < 4; j++) {
        float4 t = part[(size_t)j * N4 + i];
        xv.x += t.x; xv.y += t.y; xv.z += t.z; xv.w += t.w;
    }
    float ss = xv.x * xv.x + xv.y * xv.y + xv.z * xv.z + xv.w * xv.w;
    __shared__ float red[256];
    red[tid] = ss;
    __syncthreads();
    for (int s = 128; s > 0; s >>= 1) {
        if (tid < s) red[tid] += red[tid + s];
        __syncthreads();
    }
    float sc = rsqrtf(red[0] / (float)D + EPS);
    out[i] = make_float4(xv.x * sc, xv.y * sc, xv.z * sc, xv.w * sc);
}

// fused per-(s,h) RMS + RoPE on fp16 q and k (blockIdx.y selects tensor)
__global__ void rmsrope2_k(__half* __restrict__ q, __half* __restrict__ k) {
    __half* t = blockIdx.y ? k : q;
    int warp = (blockIdx.x * blockDim.x + threadIdx.x) >> 5;
    int lane = threadIdx.x & 31;
    int s = warp >> 4;
    __half* p = t + (size_t)warp * 64;
    float a = __half2float(p[lane]);
    float b = __half2float(p[lane + 32]);
    float ss = a * a + b * b;
    #pragma unroll
    for (int o = 16; o; o >>= 1) ss += __shfl_xor_sync(0xFFFFFFFFu, ss, o);
    float sc = rsqrtf(ss / 64.f + EPS);
    a *= sc; b *= sc;
    float inv = powf(10000.f, -((float)(2 * lane)) / 64.f);
    float fr = (float)s * inv;
    float cs, sn;
    sincosf(fr, &sn, &cs);
    p[lane]      = __float2half_rn(a * cs + b * sn);
    p[lane + 32] = __float2half_rn(-a * sn + b * cs);
}

__global__ void copyu2_k(const uint2* __restrict__ in, uint2* __restrict__ out) {
    int i = blockIdx.x * blockDim.x + threadIdx.x;
    out[i] = in[i];
}

// fused v-mix + transpose: vt[c][r] = (1-la)*v[r][c] + la*v1[r][c]
__global__ void transmix_k(const __half* __restrict__ v, const __half* __restrict__ v1,
                           const float* __restrict__ lamb, int layer,
                           __half* __restrict__ vt) {
    __shared__ __half tile[32][34];
    float la = lamb[layer];
    float om = 1.f - la;
    int x = blockIdx.x * 32 + threadIdx.x;
    int y0 = blockIdx.y * 32 + threadIdx.y;
    #pragma unroll
    for (int j = 0; j < 32; j += 8) {
        size_t idx = (size_t)(y0 + j) * D + x;
        float mv = om * __half2float(v[idx]) + la * __half2float(v1[idx]);
        tile[threadIdx.y + j][threadIdx.x] = __float2half_rn(mv);
    }
    __syncthreads();
    int x2 = blockIdx.y * 32 + threadIdx.x;
    int y2 = blockIdx.x * 32 + threadIdx.y;
    #pragma unroll
    for (int j = 0; j < 32; j += 8)
        vt[(size_t)(y2 + j) * D + x2] = tile[threadIdx.x][threadIdx.y + j];
}

// ---------------- pipelined fp16 mma.sync GEMM (m16n8k16, ldmatrix), 4 warps ----------------
// C[M,N] = A[M,K] * B[N,K]^T  (NT; fp16 row-major, K contiguous)
// modes: 0 fp32 raw | 1 fp32 acc+R | 2 fp16 relu(acc)^2 | 3 fp16 mask?exp(acc*scale):0
//        5 fp16 raw | 7 fp16 acc/rowsum(A)  (rowsum computed in-kernel from staged A tiles)
// flags: 1 = triangular launch (z=h*36+t); 2 = K limited to row0+BM; 4 = split-K over z

struct GArgs {
    const __half* A; int lda; long long sA;
    const __half* B; int ldb; long long sB;
    void* C; int ldc; long long sC;
    const float* R; long long sR;
    int K; int mode; int flags; float scale;
    const unsigned char* mask;
    const __half* Bm[3]; void* Cm[3]; int nMulti;
};

#define LDMX4(r0, r1, r2, r3, addr) \
    asm volatile("ldmatrix.sync.aligned.m8n8.x4.shared.b16 {%0,%1,%2,%3}, [%4];" \
                 : "=r"(r0), "=r"(r1), "=r"(r2), "=r"(r3) : "r"(addr))

template<int BM, int BN>
__global__ __launch_bounds__(128, 2) void gemm4(GArgs a) {
    constexpr int BK = 64;                    // halves per K-tile (128 bytes/row)
    constexpr int SROW = 72;                  // padded row in halves (144B)
    constexpr int SSZ = (BM + BN) * SROW;     // halves per stage
    constexpr int WM = BM / 2, WN = BN / 2;   // 2x2 warp grid
    constexpr int FM = WM / 16, FN = WN / 8;
    constexpr int CA = BM / 16, CB = BN / 16; // cp.async 16B chunks per thread
    extern __shared__ __half sh[];
    __shared__ float rowsumsh[BM];

    int tid = threadIdx.x, lane = tid & 31, warp = tid >> 5;
    int row0, col0, koff = 0;
    const __half *A, *B;
    char* C;
    const float* R = nullptr;
    int z = blockIdx.z;

    if (a.flags & 1) {
        int t = z % 36, h = z / 36;
        int by = 0;
        while ((by + 1) * (by + 2) / 2 <= t) by++;
        int bx = t - by * (by + 1) / 2;
        row0 = by * BM; col0 = bx * BN;
        A = a.A + (size_t)h * a.sA;
        B = a.B + (size_t)h * a.sB;
        C = (char*)a.C + (size_t)h * a.sC * 2;      // fp16 C
    } else {
        row0 = blockIdx.y * BM; col0 = blockIdx.x * BN;
        if (a.flags & 4) {
            A = a.A; B = a.B;
            C = (char*)a.C + (size_t)z * a.sC * 4;  // fp32 partials
            koff = z * a.K;
        } else if (a.nMulti) {
            A = a.A; B = a.Bm[z]; C = (char*)a.Cm[z];
        } else {
            A = a.A + (size_t)z * a.sA;
            B = a.B + (size_t)z * a.sB;
            int esz = (a.mode == 0 || a.mode == 1) ? 4 : 2;
            C = (char*)a.C + (size_t)z * a.sC * esz;
            if (a.R) R = a.R + (size_t)z * a.sR;
        }
    }

    int K = a.K;
    if (a.flags & 2) { int kl = row0 + BM; if (kl < K) K = kl; }
    int KT = K / BK;

    auto issue = [&](int kt, int st) {
        __half* dstA = sh + st * SSZ;
        #pragma unroll
        for (int i = 0; i < CA; i++) {
            int id = tid + 128 * i;
            int r = id >> 3, c = id & 7;
            unsigned u = (unsigned)__cvta_generic_to_shared(dstA + r * SROW + c * 8);
            const __half* gp = A + (size_t)(row0 + r) * a.lda + koff + kt * BK + c * 8;
            asm volatile("cp.async.cg.shared.global [%0], [%1], 16;\n" :: "r"(u), "l"(gp));
        }
        __half* dstB = sh + st * SSZ + BM * SROW;
        #pragma unroll
        for (int i = 0; i < CB; i++) {
            int id = tid + 128 * i;
            int r = id >> 3, c = id & 7;
            unsigned u = (unsigned)__cvta_generic_to_shared(dstB + r * SROW + c * 8);
            const __half* gp = B + (size_t)(col0 + r) * a.ldb + koff + kt * BK + c * 8;
            asm volatile("cp.async.cg.shared.global [%0], [%1], 16;\n" :: "r"(u), "l"(gp));
        }
        asm volatile("cp.async.commit_group;\n");
    };

    float acc[FM][FN][4] = {};
    float rsum_acc = 0.f;

    issue(0, 0);
    if (KT > 1) issue(1, 1);

    int wm0 = (warp & 1) * WM, wn0 = (warp >> 1) * WN;
    int g = lane >> 2, tig = lane & 3;

    uint32_t shb = (uint32_t)__cvta_generic_to_shared(sh);
    int laneq = lane & 7, lane8 = (lane >> 3) & 1, lane16 = lane >> 4;
    uint32_t aoff = (uint32_t)((wm0 + laneq + 8 * lane8) * SROW + 8 * lane16);
    uint32_t boff = (uint32_t)((wn0 + laneq + 8 * lane16) * SROW + 8 * lane8);

    for (int kt = 0; kt < KT; kt++) {
        if (kt + 2 <= KT) asm volatile("cp.async.wait_group 1;\n");
        else              asm volatile("cp.async.wait_group 0;\n");
        __syncthreads();

        uint32_t sAb = shb + (uint32_t)((kt & 1) * SSZ) * 2;
        uint32_t sBb = sAb + BM * SROW * 2;

        // in-kernel A row sums for PV normalization (reads staged tile before overwrite)
        if (a.mode == 7) {
            if (BM == 128) {
                const __half2* rowp = (const __half2*)(sh + (kt & 1) * SSZ + tid * SROW);
                float s = 0.f;
                #pragma unroll
                for (int j = 0; j < 32; j++) {
                    float2 f = __half22float2(rowp[j]);
                    s += f.x + f.y;
                }
                rsum_acc += s;
            } else {  // BM==64: two threads per row
                const __half2* rowp = (const __half2*)(sh + (kt & 1) * SSZ +
                                                       (tid >> 1) * SROW + (tid & 1) * 32);
                float s = 0.f;
                #pragma unroll
                for (int j = 0; j < 16; j++) {
                    float2 f = __half22float2(rowp[j]);
                    s += f.x + f.y;
                }
                rsum_acc += s;
            }
        }

        #pragma unroll
        for (int s16 = 0; s16 < BK; s16 += 16) {
            uint32_t af[FM][4], bf[FN][2];
            #pragma unroll
            for (int fm = 0; fm < FM; fm++) {
                LDMX4(af[fm][0], af[fm][1], af[fm][2], af[fm][3],
                      sAb + (aoff + fm * 16 * SROW + s16) * 2);
            }
            #pragma unroll
            for (int fp = 0; fp < FN / 2; fp++) {
                LDMX4(bf[2 * fp][0], bf[2 * fp][1], bf[2 * fp + 1][0], bf[2 * fp + 1][1],
                      sBb + (boff + fp * 16 * SROW + s16) * 2);
            }
            #pragma unroll
            for (int fm = 0; fm < FM; fm++)
                #pragma unroll
                for (int fn = 0; fn < FN; fn++) {
                    asm volatile(
                        "mma.sync.aligned.m16n8k16.row.col.f32.f16.f16.f32 "
                        "{%0,%1,%2,%3}, {%4,%5,%6,%7}, {%8,%9}, {%0,%1,%2,%3};\n"
                        : "+f"(acc[fm][fn][0]), "+f"(acc[fm][fn][1]),
                          "+f"(acc[fm][fn][2]), "+f"(acc[fm][fn][3])
                        : "r"(af[fm][0]), "r"(af[fm][1]), "r"(af[fm][2]), "r"(af[fm][3]),
                          "r"(bf[fn][0]), "r"(bf[fn][1]));
                }
        }
        __syncthreads();
        if (kt + 2 < KT) issue(kt + 2, kt & 1);
    }

    if (a.mode == 7) {
        if (BM == 128) {
            rowsumsh[tid] = rsum_acc;
        } else {
            float s = rsum_acc + __shfl_xor_sync(0xFFFFFFFFu, rsum_acc, 1);
            if (!(tid & 1)) rowsumsh[tid >> 1] = s;
        }
        __syncthreads();
    }

    // epilogue
    #pragma unroll
    for (int fm = 0; fm < FM; fm++) {
        #pragma unroll
        for (int fn = 0; fn < FN; fn++) {
            int r0 = row0 + wm0 + fm * 16 + g;
            int c  = col0 + wn0 + fn * 8 + 2 * tig;
            #pragma unroll
            for (int half = 0; half < 2; half++) {
                int r = r0 + 8 * half;
                float v0 = acc[fm][fn][2 * half + 0];
                float v1 = acc[fm][fn][2 * half + 1];
                size_t off = (size_t)r * a.ldc + c;
                if (a.mode == 0) {
                    ((float*)C)[off] = v0;
                    ((float*)C)[off + 1] = v1;
                } else if (a.mode == 1) {
                    ((float*)C)[off] = v0 + R[off];
                    ((float*)C)[off + 1] = v1 + R[off + 1];
                } else {
                    if (a.mode == 2) {
                        v0 = fmaxf(v0, 0.f); v0 *= v0;
                        v1 = fmaxf(v1, 0.f); v1 *= v1;
                    } else if (a.mode == 3) {
                        const unsigned char* m = a.mask + (size_t)r * S + c;
                        v0 = m[0] ? __expf(v0 * a.scale) : 0.f;
                        v1 = m[1] ? __expf(v1 * a.scale) : 0.f;
                    } else if (a.mode == 7) {
                        float rsv = 1.0f / rowsumsh[r - row0];
                        v0 *= rsv;
                        v1 *= rsv;
                    }
                    __half2 hv = __floats2half2_rn(v0, v1);
                    *(__half2*)((__half*)C + off) = hv;
                }
            }
        }
    }
}

// ---------------- host orchestration ----------------

static inline GArgs mkargs(const __half* A, int lda, long long sA,
                           const __half* B, int ldb, long long sB,
                           void* C, int ldc, long long sC,
                           const float* R, long long sR, int K, int mode) {
    GArgs a;
    a.A = A; a.lda = lda; a.sA = sA;
    a.B = B; a.ldb = ldb; a.sB = sB;
    a.C = C; a.ldc = ldc; a.sC = sC;
    a.R = R; a.sR = sR; a.K = K; a.mode = mode;
    a.flags = 0; a.scale = 0.f; a.mask = nullptr;
    a.Bm[0] = a.Bm[1] = a.Bm[2] = nullptr;
    a.Cm[0] = a.Cm[1] = a.Cm[2] = nullptr;
    a.nMulti = 0;
    return a;
}

extern "C" void kernel_launch(void* const* d_in, const int* in_sizes, int n_in,
                              void* d_out, int out_size) {
    const float* x_in    = (const float*)d_in[0];
    const float* Wq      = (const float*)d_in[1];
    const float* Wk      = (const float*)d_in[2];
    const float* Wv      = (const float*)d_in[3];
    const float* Wo      = (const float*)d_in[4];
    const float* lamb    = (const float*)d_in[5];
    const float* lambdas = (const float*)d_in[6];
    const float* Wfc     = (const float*)d_in[7];
    const float* Wp      = (const float*)d_in[8];
    const int*   levels  = (const int*)d_in[9];
    const int*   sample  = (const int*)d_in[10];

    float *x, *x0, *xl, *fc2;
    __half *xn, *q, *k, *v, *v1, *vt, *y, *h, *p;
    __half *wq, *wk, *wv, *wo, *wfc, *wp;
    int* cpad;
    unsigned char* mask;
    cudaGetSymbolAddress((void**)&x,  g_x);
    cudaGetSymbolAddress((void**)&x0, g_x0);
    cudaGetSymbolAddress((void**)&xl, g_xl);
    cudaGetSymbolAddress((void**)&xn, g_xn);
    cudaGetSymbolAddress((void**)&q,  g_q);
    cudaGetSymbolAddress((void**)&k,  g_k);
    cudaGetSymbolAddress((void**)&v,  g_v);
    cudaGetSymbolAddress((void**)&v1, g_v1);
    cudaGetSymbolAddress((void**)&vt, g_vt);
    cudaGetSymbolAddress((void**)&y,  g_y);
    cudaGetSymbolAddress((void**)&h,  g_h);
    cudaGetSymbolAddress((void**)&p,  g_p);
    cudaGetSymbolAddress((void**)&fc2, g_fc2);
    cudaGetSymbolAddress((void**)&cpad, g_cpad);
    cudaGetSymbolAddress((void**)&mask, g_mask);
    cudaGetSymbolAddress((void**)&wq, g_wq);
    cudaGetSymbolAddress((void**)&wk, g_wk);
    cudaGetSymbolAddress((void**)&wv, g_wv);
    cudaGetSymbolAddress((void**)&wo, g_wo);
    cudaGetSymbolAddress((void**)&wfc, g_wfc);
    cudaGetSymbolAddress((void**)&wp, g_wp);

    const int SMAA = (128 + 128) * 72 * 2 * 2;  // 73728 bytes
    const int SMAB = (128 + 64) * 72 * 2 * 2;   // 55296 bytes
    const int SMBB = (64 + 64) * 72 * 2 * 2;    // 36864 bytes
    cudaFuncSetAttribute(gemm4<128,128>, cudaFuncAttributeMaxDynamicSharedMemorySize, SMAA);
    cudaFuncSetAttribute(gemm4<128,64>,  cudaFuncAttributeMaxDynamicSharedMemorySize, SMAB);
    cudaFuncSetAttribute(gemm4<64,64>,   cudaFuncAttributeMaxDynamicSharedMemorySize, SMBB);

    const int EW4 = (S * D / 4) / 256;
    const float scale = 1.0f / 8.0f;             // HD^-0.5

    // ---- stream-2 weight conversion, overlapped (isolated at -16us, R8 vs R9) ----
    cudaStream_t s2;
    cudaStreamCreateWithFlags(&s2, cudaStreamNonBlocking);
    cudaEvent_t evRoot, evQKV, evWo, evWfc, evWp;
    cudaEventCreateWithFlags(&evRoot, cudaEventDisableTiming);
    cudaEventCreateWithFlags(&evQKV,  cudaEventDisableTiming);
    cudaEventCreateWithFlags(&evWo,   cudaEventDisableTiming);
    cudaEventCreateWithFlags(&evWfc,  cudaEventDisableTiming);
    cudaEventCreateWithFlags(&evWp,   cudaEventDisableTiming);

    cudaEventRecord(evRoot, 0);
    cudaStreamWaitEvent(s2, evRoot, 0);
    {
        int n8a = NL * D * D / 8;
        int n8b = NL * DFF * D / 8;
        tohalf2_k<<<(n8a + 255) / 256, 256, 0, s2>>>((const float4*)Wq, (uint4*)wq, n8a);
        tohalf2_k<<<(n8a + 255) / 256, 256, 0, s2>>>((const float4*)Wk, (uint4*)wk, n8a);
        tohalf2_k<<<(n8a + 255) / 256, 256, 0, s2>>>((const float4*)Wv, (uint4*)wv, n8a);
        cudaEventRecord(evQKV, s2);
        tohalf2_k<<<(n8a + 255) / 256, 256, 0, s2>>>((const float4*)Wo, (uint4*)wo, n8a);
        cudaEventRecord(evWo, s2);
        tohalf2_k<<<(n8b + 255) / 256, 256, 0, s2>>>((const float4*)Wfc, (uint4*)wfc, n8b);
        cudaEventRecord(evWfc, s2);
        tohalf2_k<<<(n8b + 255) / 256, 256, 0, s2>>>((const float4*)Wp, (uint4*)wp, n8b);
        cudaEventRecord(evWp, s2);
    }

    build_prefix_k<<<1, 32>>>(levels, cpad);
    build_mask_k<<<(S * S) / 256, 256>>>(levels, sample, cpad, mask);

    rms_rows_f_k<<<S, 256>>>(x_in, x);
    {
        int n4 = S * D / 4;
        copyu2_k<<<n4 / 256, 256>>>((const uint2*)x, (uint2*)(x0));
        copyu2_k<<<n4 / 256, 256>>>((const uint2*)(x + S * D / 2), (uint2*)(x0 + S * D / 2));
    }

    for (int i = 0; i < NL; i++) {
        const __half* Wqi = wq + (size_t)i * D * D;
        const __half* Wki = wk + (size_t)i * D * D;
        const __half* Wvi = wv + (size_t)i * D * D;
        const __half* Woi = wo + (size_t)i * D * D;
        const __half* Wfi = wfc + (size_t)i * DFF * D;
        const __half* Wpi = wp + (size_t)i * D * DFF;

        // xl/xn prep; layers >=1 also fold in previous layer's FC2 partials
        if (i == 0)
            xlrms_k<<<S, 256>>>((const float4*)x, (const float4*)x0, lambdas, i,
                                (float4*)xl, xn);
        else
            xlrms_red_k<<<S, 256>>>((float4*)x, (const float4*)fc2, (const float4*)x0,
                                    lambdas, i, (float4*)xl, xn);

        // fused QKV (fp16 out)
        if (i == 0) cudaStreamWaitEvent(0, evQKV, 0);
        {
            GArgs a = mkargs(xn, D, 0, nullptr, D, 0, nullptr, D, 0, nullptr, 0, D, 5);
            a.Bm[0] = Wqi; a.Bm[1] = Wki; a.Bm[2] = Wvi;
            a.Cm[0] = q;   a.Cm[1] = k;   a.Cm[2] = v;
            a.nMulti = 3;
            gemm4<128,128><<<dim3(D / 128, S / 128, 3), 128, SMAA>>>(a);
        }

        if (i == 0) copyu2_k<<<EW4, 256>>>((const uint2*)v, (uint2*)v1);

        rmsrope2_k<<<dim3((S * H) / 8, 2), 256>>>(q, k);

        // vt = transpose((1-la)*v + la*v1)
        transmix_k<<<dim3(32, 32), dim3(32, 8)>>>(v, v1, lamb, i, vt);

        // p[h] = mask .* exp(scale * q_h k_h^T), lower-triangular blocks (fp16)
        {
            GArgs a = mkargs(q, D, HD, k, D, HD, p, S, (long long)S * S, nullptr, 0, HD, 3);
            a.flags = 1; a.scale = scale; a.mask = mask;
            gemm4<128,128><<<dim3(1, 1, H * 36), 128, SMAA>>>(a);
        }

        // y[:,h] = fp16((p_h @ V_h) / rowsum) — BM=64 halves the triangular critical path
        {
            GArgs a = mkargs(p, S, (long long)S * S, vt, S, (long long)HD * S,
                             y, D, HD, nullptr, 0, S, 7);
            a.flags = 2;
            gemm4<64,64><<<dim3(1, S / 64, H), 128, SMBB>>>(a);
        }

        // x = xl + y @ Wo^T  (fp32 out)
        if (i == 0) cudaStreamWaitEvent(0, evWo, 0);
        {
            GArgs a = mkargs(y, D, 0, Woi, D, 0, x, D, 0, xl, 0, D, 1);
            gemm4<128,64><<<dim3(D / 64, S / 128, 1), 128, SMAB>>>(a);
        }

        // h = fp16(relu(rms(x) @ Wfc^T)^2)
        rms_rows_h_k<<<S, 256>>>(x, xn);
        if (i == 0) cudaStreamWaitEvent(0, evWfc, 0);
        {
            GArgs a = mkargs(xn, D, 0, Wfi, D, 0, h, DFF, 0, nullptr, 0, D, 2);
            gemm4<128,128><<<dim3(DFF / 128, S / 128, 1), 128, SMAA>>>(a);
        }

        // FC2 split-K x4 partials (reduced by next layer's xlrms_red / final rms)
        if (i == 0) cudaStreamWaitEvent(0, evWp, 0);
        {
            GArgs a = mkargs(h, DFF, 0, Wpi, DFF, 0, fc2, D, (long long)S * D,
                             nullptr, 0, DFF / 4, 0);
            a.flags = 4;
            gemm4<128,128><<<dim3(D / 128, S / 128, 4), 128, SMAA>>>(a);
        }
    }

    // out = rms(x + FC2 partials of last layer)
    final_red_rms_k<<<S, 256>>>((const float4*)x, (const float4*)fc2, (float4*)d_out);
}

// round 14
// speedup vs baseline: 1.1372x; 1.0289x over previous
#include <cuda_runtime.h>
#include <cuda_fp16.h>
#include <math.h>
#include <stdint.h>

#define S 1024
#define D 1024
#define H 16
#define HD 64
#define NL 6
#define DFF 4096
#define EPS 1.1920929e-07f

// ---------------- scratch (device globals; no allocation) ----------------
__device__ float  g_x [S * D];
__device__ float  g_x0[S * D];
__device__ float  g_xl[S * D];
__device__ __half g_xn[S * D];
__device__ __half g_q [S * D];
__device__ __half g_k [S * D];
__device__ __half g_v [S * D];
__device__ __half g_v1[S * D];
__device__ __half g_vt[S * D];
__device__ __half g_y [S * D];
__device__ __half g_h [S * DFF];
__device__ __half g_p [(size_t)H * S * S];
__device__ float  g_fc2[4 * S * D];
__device__ int    g_cpad[S + 1];
__device__ unsigned char g_mask[(size_t)S * S];
// fp16 weight copies (converted once per replay, overlapped on stream 2)
__device__ __half g_wq[NL * D * D];
__device__ __half g_wk[NL * D * D];
__device__ __half g_wv[NL * D * D];
__device__ __half g_wo[NL * D * D];
__device__ __half g_wfc[(size_t)NL * DFF * D];
__device__ __half g_wp [(size_t)NL * DFF * D];

// ---------------- small kernels ----------------

// wide conversion: 32B read / 16B write per thread
__global__ void tohalf2_k(const float4* __restrict__ in, uint4* __restrict__ out, int n8) {
    int i = blockIdx.x * blockDim.x + threadIdx.x;
    if (i < n8) {
        float4 a = in[2 * i];
        float4 b = in[2 * i + 1];
        __half2 h0 = __floats2half2_rn(a.x, a.y);
        __half2 h1 = __floats2half2_rn(a.z, a.w);
        __half2 h2 = __floats2half2_rn(b.x, b.y);
        __half2 h3 = __floats2half2_rn(b.z, b.w);
        uint4 r;
        r.x = *(uint32_t*)&h0;
        r.y = *(uint32_t*)&h1;
        r.z = *(uint32_t*)&h2;
        r.w = *(uint32_t*)&h3;
        out[i] = r;
    }
}

__global__ void build_prefix_k(const int* __restrict__ levels, int* __restrict__ cpad) {
    if (threadIdx.x == 0) {
        cpad[0] = 0;
        for (int i = 0; i < S; i++) cpad[i + 1] = cpad[i] + (levels[i] == 0 ? 1 : 0);
    }
}

__global__ void build_mask_k(const int* __restrict__ levels, const int* __restrict__ sample,
                             const int* __restrict__ cpad, unsigned char* __restrict__ mask) {
    int idx = blockIdx.x * blockDim.x + threadIdx.x;
    int q = idx >> 10;
    int k = idx & 1023;
    bool causal = q >= k;
    bool same = sample[q] == sample[k];
    int cnt = cpad[q] - cpad[k + 1];
    bool markov = (levels[k] == 0) && (cnt > 0);
    mask[idx] = (causal && same && !markov) ? 1 : 0;
}

// initial: x = rms(x_in); x0 = x  (both stored in one pass)
__global__ void rms_init_k(const float* __restrict__ in, float* __restrict__ x,
                           float* __restrict__ x0) {
    int row = blockIdx.x;
    const float4* p = (const float4*)(in + (size_t)row * D);
    float4* ox  = (float4*)(x  + (size_t)row * D);
    float4* ox0 = (float4*)(x0 + (size_t)row * D);
    int tid = threadIdx.x;
    float4 t = p[tid];
    float ss = t.x * t.x + t.y * t.y + t.z * t.z + t.w * t.w;
    __shared__ float red[256];
    red[tid] = ss;
    __syncthreads();
    for (int s = 128; s > 0; s >>= 1) {
        if (tid < s) red[tid] += red[tid + s];
        __syncthreads();
    }
    float sc = rsqrtf(red[0] / (float)D + EPS);
    float4 r = make_float4(t.x * sc, t.y * sc, t.z * sc, t.w * sc);
    ox[tid] = r;
    ox0[tid] = r;
}

// RMS over fp32 rows of length D -> fp16 out
__global__ void rms_rows_h_k(const float* __restrict__ in, __half* __restrict__ out) {
    int row = blockIdx.x;
    const float4* p = (const float4*)(in + (size_t)row * D);
    uint2* o = (uint2*)(out + (size_t)row * D);
    int tid = threadIdx.x;
    float4 t = p[tid];
    float ss = t.x * t.x + t.y * t.y + t.z * t.z + t.w * t.w;
    __shared__ float red[256];
    red[tid] = ss;
    __syncthreads();
    for (int s = 128; s > 0; s >>= 1) {
        if (tid < s) red[tid] += red[tid + s];
        __syncthreads();
    }
    float sc = rsqrtf(red[0] / (float)D + EPS);
    __half2 a = __floats2half2_rn(t.x * sc, t.y * sc);
    __half2 b = __floats2half2_rn(t.z * sc, t.w * sc);
    uint2 r;
    r.x = *(uint32_t*)&a;
    r.y = *(uint32_t*)&b;
    o[tid] = r;
}

// fused: xl = l0*x + l1*x0 ; xn = fp16(rms(xl)). One row per block. (layer 0)
__global__ void xlrms_k(const float4* __restrict__ x, const float4* __restrict__ x0,
                        const float* __restrict__ lambdas, int layer,
                        float4* __restrict__ xl, __half* __restrict__ xn) {
    int row = blockIdx.x;
    int tid = threadIdx.x;
    int i = row * 256 + tid;
    float l0 = lambdas[layer * 2 + 0];
    float l1 = lambdas[layer * 2 + 1];
    float4 a = x[i], b = x0[i];
    float4 t = make_float4(l0 * a.x + l1 * b.x, l0 * a.y + l1 * b.y,
                           l0 * a.z + l1 * b.z, l0 * a.w + l1 * b.w);
    xl[i] = t;
    float ss = t.x * t.x + t.y * t.y + t.z * t.z + t.w * t.w;
    __shared__ float red[256];
    red[tid] = ss;
    __syncthreads();
    for (int s = 128; s > 0; s >>= 1) {
        if (tid < s) red[tid] += red[tid + s];
        __syncthreads();
    }
    float sc = rsqrtf(red[0] / (float)D + EPS);
    __half2 h0 = __floats2half2_rn(t.x * sc, t.y * sc);
    __half2 h1 = __floats2half2_rn(t.z * sc, t.w * sc);
    uint2 r;
    r.x = *(uint32_t*)&h0;
    r.y = *(uint32_t*)&h1;
    ((uint2*)xn)[i] = r;
}

// fused: x += 4 FC2 partials (store); xl = l0*x + l1*x0; xn = fp16(rms(xl)). (layers 1..5)
__global__ void xlrms_red_k(float4* __restrict__ x, const float4* __restrict__ part,
                            const float4* __restrict__ x0,
                            const float* __restrict__ lambdas, int layer,
                            float4* __restrict__ xl, __half* __restrict__ xn) {
    int row = blockIdx.x;
    int tid = threadIdx.x;
    int i = row * 256 + tid;
    const int N4 = S * D / 4;
    float4 xv = x[i];
    #pragma unroll
    for (int j = 0; j < 4; j++) {
        float4 t = part[(size_t)j * N4 + i];
        xv.x += t.x; xv.y += t.y; xv.z += t.z; xv.w += t.w;
    }
    x[i] = xv;
    float l0 = lambdas[layer * 2 + 0];
    float l1 = lambdas[layer * 2 + 1];
    float4 b = x0[i];
    float4 t = make_float4(l0 * xv.x + l1 * b.x, l0 * xv.y + l1 * b.y,
                           l0 * xv.z + l1 * b.z, l0 * xv.w + l1 * b.w);
    xl[i] = t;
    float ss = t.x * t.x + t.y * t.y + t.z * t.z + t.w * t.w;
    __shared__ float red[256];
    red[tid] = ss;
    __syncthreads();
    for (int s = 128; s > 0; s >>= 1) {
        if (tid < s) red[tid] += red[tid + s];
        __syncthreads();
    }
    float sc = rsqrtf(red[0] / (float)D + EPS);
    __half2 h0 = __floats2half2_rn(t.x * sc, t.y * sc);
    __half2 h1 = __floats2half2_rn(t.z * sc, t.w * sc);
    uint2 r;
    r.x = *(uint32_t*)&h0;
    r.y = *(uint32_t*)&h1;
    ((uint2*)xn)[i] = r;
}

// final: out = rms(x + 4 FC2 partials)
__global__ void final_red_rms_k(const float4* __restrict__ x, const float4* __restrict__ part,
                                float4* __restrict__ out) {
    int row = blockIdx.x;
    int tid = threadIdx.x;
    int i = row * 256 + tid;
    const int N4 = S * D / 4;
    float4 xv = x[i];
    #pragma unroll
    for (int j = 0; j < 4; j++) {
        float4 t = part[(size_t)j * N4 + i];
        xv.x += t.x; xv.y += t.y; xv.z += t.z; xv.w += t.w;
    }
    float ss = xv.x * xv.x + xv.y * xv.y + xv.z * xv.z + xv.w * xv.w;
    __shared__ float red[256];
    red[tid] = ss;
    __syncthreads();
    for (int s = 128; s > 0; s >>= 1) {
        if (tid < s) red[tid] += red[tid + s];
        __syncthreads();
    }
    float sc = rsqrtf(red[0] / (float)D + EPS);
    out[i] = make_float4(xv.x * sc, xv.y * sc, xv.z * sc, xv.w * sc);
}

// fused per-(s,h) RMS + RoPE on fp16 q and k (blockIdx.y selects tensor)
__global__ void rmsrope2_k(__half* __restrict__ q, __half* __restrict__ k) {
    __half* t = blockIdx.y ? k : q;
    int warp = (blockIdx.x * blockDim.x + threadIdx.x) >> 5;
    int lane = threadIdx.x & 31;
    int s = warp >> 4;
    __half* p = t + (size_t)warp * 64;
    float a = __half2float(p[lane]);
    float b = __half2float(p[lane + 32]);
    float ss = a * a + b * b;
    #pragma unroll
    for (int o = 16; o; o >>= 1) ss += __shfl_xor_sync(0xFFFFFFFFu, ss, o);
    float sc = rsqrtf(ss / 64.f + EPS);
    a *= sc; b *= sc;
    float inv = powf(10000.f, -((float)(2 * lane)) / 64.f);
    float fr = (float)s * inv;
    float cs, sn;
    sincosf(fr, &sn, &cs);
    p[lane]      = __float2half_rn(a * cs + b * sn);
    p[lane + 32] = __float2half_rn(-a * sn + b * cs);
}

__global__ void copyu2_k(const uint2* __restrict__ in, uint2* __restrict__ out) {
    int i = blockIdx.x * blockDim.x + threadIdx.x;
    out[i] = in[i];
}

// fused v-mix + transpose: vt[c][r] = (1-la)*v[r][c] + la*v1[r][c]
__global__ void transmix_k(const __half* __restrict__ v, const __half* __restrict__ v1,
                           const float* __restrict__ lamb, int layer,
                           __half* __restrict__ vt) {
    __shared__ __half tile[32][34];
    float la = lamb[layer];
    float om = 1.f - la;
    int x = blockIdx.x * 32 + threadIdx.x;
    int y0 = blockIdx.y * 32 + threadIdx.y;
    #pragma unroll
    for (int j = 0; j < 32; j += 8) {
        size_t idx = (size_t)(y0 + j) * D + x;
        float mv = om * __half2float(v[idx]) + la * __half2float(v1[idx]);
        tile[threadIdx.y + j][threadIdx.x] = __float2half_rn(mv);
    }
    __syncthreads();
    int x2 = blockIdx.y * 32 + threadIdx.x;
    int y2 = blockIdx.x * 32 + threadIdx.y;
    #pragma unroll
    for (int j = 0; j < 32; j += 8)
        vt[(size_t)(y2 + j) * D + x2] = tile[threadIdx.x][threadIdx.y + j];
}

// ---------------- pipelined fp16 mma.sync GEMM (m16n8k16, ldmatrix), 4 warps ----------------
// C[M,N] = A[M,K] * B[N,K]^T  (NT; fp16 row-major, K contiguous)
// modes: 0 fp32 raw | 1 fp32 acc+R | 2 fp16 relu(acc)^2 | 3 fp16 mask?exp(acc*scale):0
//        5 fp16 raw | 7 fp16 acc/rowsum(A)  (rowsum computed in-kernel from staged A tiles)
// flags: 1 = triangular launch (z=h*36+t); 2 = K limited to row0+BM; 4 = split-K over z

struct GArgs {
    const __half* A; int lda; long long sA;
    const __half* B; int ldb; long long sB;
    void* C; int ldc; long long sC;
    const float* R; long long sR;
    int K; int mode; int flags; float scale;
    const unsigned char* mask;
    const __half* Bm[3]; void* Cm[3]; int nMulti;
};

#define LDMX4(r0, r1, r2, r3, addr) \
    asm volatile("ldmatrix.sync.aligned.m8n8.x4.shared.b16 {%0,%1,%2,%3}, [%4];" \
                 : "=r"(r0), "=r"(r1), "=r"(r2), "=r"(r3) : "r"(addr))

template<int BM, int BN>
__global__ __launch_bounds__(128, 2) void gemm4(GArgs a) {
    constexpr int BK = 64;                    // halves per K-tile (128 bytes/row)
    constexpr int SROW = 72;                  // padded row in halves (144B)
    constexpr int SSZ = (BM + BN) * SROW;     // halves per stage
    constexpr int WM = BM / 2, WN = BN / 2;   // 2x2 warp grid
    constexpr int FM = WM / 16, FN = WN / 8;
    constexpr int CA = BM / 16, CB = BN / 16; // cp.async 16B chunks per thread
    extern __shared__ __half sh[];
    __shared__ float rowsumsh[BM];

    int tid = threadIdx.x, lane = tid & 31, warp = tid >> 5;
    int row0, col0, koff = 0;
    const __half *A, *B;
    char* C;
    const float* R = nullptr;
    int z = blockIdx.z;

    if (a.flags & 1) {
        int t = z % 36, h = z / 36;
        int by = 0;
        while ((by + 1) * (by + 2) / 2 <= t) by++;
        int bx = t - by * (by + 1) / 2;
        row0 = by * BM; col0 = bx * BN;
        A = a.A + (size_t)h * a.sA;
        B = a.B + (size_t)h * a.sB;
        C = (char*)a.C + (size_t)h * a.sC * 2;      // fp16 C
    } else {
        row0 = blockIdx.y * BM; col0 = blockIdx.x * BN;
        if (a.flags & 4) {
            A = a.A; B = a.B;
            C = (char*)a.C + (size_t)z * a.sC * 4;  // fp32 partials
            koff = z * a.K;
        } else if (a.nMulti) {
            A = a.A; B = a.Bm[z]; C = (char*)a.Cm[z];
        } else {
            A = a.A + (size_t)z * a.sA;
            B = a.B + (size_t)z * a.sB;
            int esz = (a.mode == 0 || a.mode == 1) ? 4 : 2;
            C = (char*)a.C + (size_t)z * a.sC * esz;
            if (a.R) R = a.R + (size_t)z * a.sR;
        }
    }

    int K = a.K;
    if (a.flags & 2) { int kl = row0 + BM; if (kl < K) K = kl; }
    int KT = K / BK;

    auto issue = [&](int kt, int st) {
        __half* dstA = sh + st * SSZ;
        #pragma unroll
        for (int i = 0; i < CA; i++) {
            int id = tid + 128 * i;
            int r = id >> 3, c = id & 7;
            unsigned u = (unsigned)__cvta_generic_to_shared(dstA + r * SROW + c * 8);
            const __half* gp = A + (size_t)(row0 + r) * a.lda + koff + kt * BK + c * 8;
            asm volatile("cp.async.cg.shared.global [%0], [%1], 16;\n" :: "r"(u), "l"(gp));
        }
        __half* dstB = sh + st * SSZ + BM * SROW;
        #pragma unroll
        for (int i = 0; i < CB; i++) {
            int id = tid + 128 * i;
            int r = id >> 3, c = id & 7;
            unsigned u = (unsigned)__cvta_generic_to_shared(dstB + r * SROW + c * 8);
            const __half* gp = B + (size_t)(col0 + r) * a.ldb + koff + kt * BK + c * 8;
            asm volatile("cp.async.cg.shared.global [%0], [%1], 16;\n" :: "r"(u), "l"(gp));
        }
        asm volatile("cp.async.commit_group;\n");
    };

    float acc[FM][FN][4] = {};
    float rsum_acc = 0.f;

    issue(0, 0);
    if (KT > 1) issue(1, 1);

    int wm0 = (warp & 1) * WM, wn0 = (warp >> 1) * WN;
    int g = lane >> 2, tig = lane & 3;

    uint32_t shb = (uint32_t)__cvta_generic_to_shared(sh);
    int laneq = lane & 7, lane8 = (lane >> 3) & 1, lane16 = lane >> 4;
    uint32_t aoff = (uint32_t)((wm0 + laneq + 8 * lane8) * SROW + 8 * lane16);
    uint32_t boff = (uint32_t)((wn0 + laneq + 8 * lane16) * SROW + 8 * lane8);

    for (int kt = 0; kt < KT; kt++) {
        if (kt + 2 <= KT) asm volatile("cp.async.wait_group 1;\n");
        else              asm volatile("cp.async.wait_group 0;\n");
        __syncthreads();

        uint32_t sAb = shb + (uint32_t)((kt & 1) * SSZ) * 2;
        uint32_t sBb = sAb + BM * SROW * 2;

        // in-kernel A row sums for PV normalization (reads staged tile before overwrite)
        if (a.mode == 7) {
            if (BM == 128) {
                const __half2* rowp = (const __half2*)(sh + (kt & 1) * SSZ + tid * SROW);
                float s = 0.f;
                #pragma unroll
                for (int j = 0; j < 32; j++) {
                    float2 f = __half22float2(rowp[j]);
                    s += f.x + f.y;
                }
                rsum_acc += s;
            } else {  // BM==64: two threads per row
                const __half2* rowp = (const __half2*)(sh + (kt & 1) * SSZ +
                                                       (tid >> 1) * SROW + (tid & 1) * 32);
                float s = 0.f;
                #pragma unroll
                for (int j = 0; j < 16; j++) {
                    float2 f = __half22float2(rowp[j]);
                    s += f.x + f.y;
                }
                rsum_acc += s;
            }
        }

        #pragma unroll
        for (int s16 = 0; s16 < BK; s16 += 16) {
            uint32_t af[FM][4], bf[FN][2];
            #pragma unroll
            for (int fm = 0; fm < FM; fm++) {
                LDMX4(af[fm][0], af[fm][1], af[fm][2], af[fm][3],
                      sAb + (aoff + fm * 16 * SROW + s16) * 2);
            }
            #pragma unroll
            for (int fp = 0; fp < FN / 2; fp++) {
                LDMX4(bf[2 * fp][0], bf[2 * fp][1], bf[2 * fp + 1][0], bf[2 * fp + 1][1],
                      sBb + (boff + fp * 16 * SROW + s16) * 2);
            }
            #pragma unroll
            for (int fm = 0; fm < FM; fm++)
                #pragma unroll
                for (int fn = 0; fn < FN; fn++) {
                    asm volatile(
                        "mma.sync.aligned.m16n8k16.row.col.f32.f16.f16.f32 "
                        "{%0,%1,%2,%3}, {%4,%5,%6,%7}, {%8,%9}, {%0,%1,%2,%3};\n"
                        : "+f"(acc[fm][fn][0]), "+f"(acc[fm][fn][1]),
                          "+f"(acc[fm][fn][2]), "+f"(acc[fm][fn][3])
                        : "r"(af[fm][0]), "r"(af[fm][1]), "r"(af[fm][2]), "r"(af[fm][3]),
                          "r"(bf[fn][0]), "r"(bf[fn][1]));
                }
        }
        __syncthreads();
        if (kt + 2 < KT) issue(kt + 2, kt & 1);
    }

    if (a.mode == 7) {
        if (BM == 128) {
            rowsumsh[tid] = rsum_acc;
        } else {
            float s = rsum_acc + __shfl_xor_sync(0xFFFFFFFFu, rsum_acc, 1);
            if (!(tid & 1)) rowsumsh[tid >> 1] = s;
        }
        __syncthreads();
    }

    // epilogue
    #pragma unroll
    for (int fm = 0; fm < FM; fm++) {
        #pragma unroll
        for (int fn = 0; fn < FN; fn++) {
            int r0 = row0 + wm0 + fm * 16 + g;
            int c  = col0 + wn0 + fn * 8 + 2 * tig;
            #pragma unroll
            for (int half = 0; half < 2; half++) {
                int r = r0 + 8 * half;
                float v0 = acc[fm][fn][2 * half + 0];
                float v1 = acc[fm][fn][2 * half + 1];
                size_t off = (size_t)r * a.ldc + c;
                if (a.mode == 0) {
                    ((float*)C)[off] = v0;
                    ((float*)C)[off + 1] = v1;
                } else if (a.mode == 1) {
                    ((float*)C)[off] = v0 + R[off];
                    ((float*)C)[off + 1] = v1 + R[off + 1];
                } else {
                    if (a.mode == 2) {
                        v0 = fmaxf(v0, 0.f); v0 *= v0;
                        v1 = fmaxf(v1, 0.f); v1 *= v1;
                    } else if (a.mode == 3) {
                        const unsigned char* m = a.mask + (size_t)r * S + c;
                        v0 = m[0] ? __expf(v0 * a.scale) : 0.f;
                        v1 = m[1] ? __expf(v1 * a.scale) : 0.f;
                    } else if (a.mode == 7) {
                        float rsv = 1.0f / rowsumsh[r - row0];
                        v0 *= rsv;
                        v1 *= rsv;
                    }
                    __half2 hv = __floats2half2_rn(v0, v1);
                    *(__half2*)((__half*)C + off) = hv;
                }
            }
        }
    }
}

// ---------------- host orchestration ----------------

static inline GArgs mkargs(const __half* A, int lda, long long sA,
                           const __half* B, int ldb, long long sB,
                           void* C, int ldc, long long sC,
                           const float* R, long long sR, int K, int mode) {
    GArgs a;
    a.A = A; a.lda = lda; a.sA = sA;
    a.B = B; a.ldb = ldb; a.sB = sB;
    a.C = C; a.ldc = ldc; a.sC = sC;
    a.R = R; a.sR = sR; a.K = K; a.mode = mode;
    a.flags = 0; a.scale = 0.f; a.mask = nullptr;
    a.Bm[0] = a.Bm[1] = a.Bm[2] = nullptr;
    a.Cm[0] = a.Cm[1] = a.Cm[2] = nullptr;
    a.nMulti = 0;
    return a;
}

extern "C" void kernel_launch(void* const* d_in, const int* in_sizes, int n_in,
                              void* d_out, int out_size) {
    const float* x_in    = (const float*)d_in[0];
    const float* Wq      = (const float*)d_in[1];
    const float* Wk      = (const float*)d_in[2];
    const float* Wv      = (const float*)d_in[3];
    const float* Wo      = (const float*)d_in[4];
    const float* lamb    = (const float*)d_in[5];
    const float* lambdas = (const float*)d_in[6];
    const float* Wfc     = (const float*)d_in[7];
    const float* Wp      = (const float*)d_in[8];
    const int*   levels  = (const int*)d_in[9];
    const int*   sample  = (const int*)d_in[10];

    float *x, *x0, *xl, *fc2;
    __half *xn, *q, *k, *v, *v1, *vt, *y, *h, *p;
    __half *wq, *wk, *wv, *wo, *wfc, *wp;
    int* cpad;
    unsigned char* mask;
    cudaGetSymbolAddress((void**)&x,  g_x);
    cudaGetSymbolAddress((void**)&x0, g_x0);
    cudaGetSymbolAddress((void**)&xl, g_xl);
    cudaGetSymbolAddress((void**)&xn, g_xn);
    cudaGetSymbolAddress((void**)&q,  g_q);
    cudaGetSymbolAddress((void**)&k,  g_k);
    cudaGetSymbolAddress((void**)&v,  g_v);
    cudaGetSymbolAddress((void**)&v1, g_v1);
    cudaGetSymbolAddress((void**)&vt, g_vt);
    cudaGetSymbolAddress((void**)&y,  g_y);
    cudaGetSymbolAddress((void**)&h,  g_h);
    cudaGetSymbolAddress((void**)&p,  g_p);
    cudaGetSymbolAddress((void**)&fc2, g_fc2);
    cudaGetSymbolAddress((void**)&cpad, g_cpad);
    cudaGetSymbolAddress((void**)&mask, g_mask);
    cudaGetSymbolAddress((void**)&wq, g_wq);
    cudaGetSymbolAddress((void**)&wk, g_wk);
    cudaGetSymbolAddress((void**)&wv, g_wv);
    cudaGetSymbolAddress((void**)&wo, g_wo);
    cudaGetSymbolAddress((void**)&wfc, g_wfc);
    cudaGetSymbolAddress((void**)&wp, g_wp);

    const int SMAA = (128 + 128) * 72 * 2 * 2;  // 73728 bytes
    const int SMBB = (64 + 64) * 72 * 2 * 2;    // 36864 bytes
    cudaFuncSetAttribute(gemm4<128,128>, cudaFuncAttributeMaxDynamicSharedMemorySize, SMAA);
    cudaFuncSetAttribute(gemm4<64,64>,   cudaFuncAttributeMaxDynamicSharedMemorySize, SMBB);

    const int EW4 = (S * D / 4) / 256;
    const float scale = 1.0f / 8.0f;             // HD^-0.5

    // ---- stream-2 weight conversion, overlapped (isolated at -16us, R8 vs R9) ----
    cudaStream_t s2;
    cudaStreamCreateWithFlags(&s2, cudaStreamNonBlocking);
    cudaEvent_t evRoot, evQKV, evWo, evWfc, evWp;
    cudaEventCreateWithFlags(&evRoot, cudaEventDisableTiming);
    cudaEventCreateWithFlags(&evQKV,  cudaEventDisableTiming);
    cudaEventCreateWithFlags(&evWo,   cudaEventDisableTiming);
    cudaEventCreateWithFlags(&evWfc,  cudaEventDisableTiming);
    cudaEventCreateWithFlags(&evWp,   cudaEventDisableTiming);

    cudaEventRecord(evRoot, 0);
    cudaStreamWaitEvent(s2, evRoot, 0);
    {
        int n8a = NL * D * D / 8;
        int n8b = NL * DFF * D / 8;
        tohalf2_k<<<(n8a + 255) / 256, 256, 0, s2>>>((const float4*)Wq, (uint4*)wq, n8a);
        tohalf2_k<<<(n8a + 255) / 256, 256, 0, s2>>>((const float4*)Wk, (uint4*)wk, n8a);
        tohalf2_k<<<(n8a + 255) / 256, 256, 0, s2>>>((const float4*)Wv, (uint4*)wv, n8a);
        cudaEventRecord(evQKV, s2);
        tohalf2_k<<<(n8a + 255) / 256, 256, 0, s2>>>((const float4*)Wo, (uint4*)wo, n8a);
        cudaEventRecord(evWo, s2);
        tohalf2_k<<<(n8b + 255) / 256, 256, 0, s2>>>((const float4*)Wfc, (uint4*)wfc, n8b);
        cudaEventRecord(evWfc, s2);
        tohalf2_k<<<(n8b + 255) / 256, 256, 0, s2>>>((const float4*)Wp, (uint4*)wp, n8b);
        cudaEventRecord(evWp, s2);
    }

    build_prefix_k<<<1, 32>>>(levels, cpad);
    build_mask_k<<<(S * S) / 256, 256>>>(levels, sample, cpad, mask);

    // x = rms(x_in); x0 = x  (single pass)
    rms_init_k<<<S, 256>>>(x_in, x, x0);

    for (int i = 0; i < NL; i++) {
        const __half* Wqi = wq + (size_t)i * D * D;
        const __half* Wki = wk + (size_t)i * D * D;
        const __half* Wvi = wv + (size_t)i * D * D;
        const __half* Woi = wo + (size_t)i * D * D;
        const __half* Wfi = wfc + (size_t)i * DFF * D;
        const __half* Wpi = wp + (size_t)i * D * DFF;

        // xl/xn prep; layers >=1 also fold in previous layer's FC2 partials
        if (i == 0)
            xlrms_k<<<S, 256>>>((const float4*)x, (const float4*)x0, lambdas, i,
                                (float4*)xl, xn);
        else
            xlrms_red_k<<<S, 256>>>((float4*)x, (const float4*)fc2, (const float4*)x0,
                                    lambdas, i, (float4*)xl, xn);

        // fused QKV (fp16 out)
        if (i == 0) cudaStreamWaitEvent(0, evQKV, 0);
        {
            GArgs a = mkargs(xn, D, 0, nullptr, D, 0, nullptr, D, 0, nullptr, 0, D, 5);
            a.Bm[0] = Wqi; a.Bm[1] = Wki; a.Bm[2] = Wvi;
            a.Cm[0] = q;   a.Cm[1] = k;   a.Cm[2] = v;
            a.nMulti = 3;
            gemm4<128,128><<<dim3(D / 128, S / 128, 3), 128, SMAA>>>(a);
        }

        if (i == 0) copyu2_k<<<EW4, 256>>>((const uint2*)v, (uint2*)v1);

        rmsrope2_k<<<dim3((S * H) / 8, 2), 256>>>(q, k);

        // vt = transpose((1-la)*v + la*v1)
        transmix_k<<<dim3(32, 32), dim3(32, 8)>>>(v, v1, lamb, i, vt);

        // p[h] = mask .* exp(scale * q_h k_h^T), lower-triangular blocks (fp16)
        {
            GArgs a = mkargs(q, D, HD, k, D, HD, p, S, (long long)S * S, nullptr, 0, HD, 3);
            a.flags = 1; a.scale = scale; a.mask = mask;
            gemm4<128,128><<<dim3(1, 1, H * 36), 128, SMAA>>>(a);
        }

        // y[:,h] = fp16((p_h @ V_h) / rowsum) — BM=64 halves the triangular critical path
        {
            GArgs a = mkargs(p, S, (long long)S * S, vt, S, (long long)HD * S,
                             y, D, HD, nullptr, 0, S, 7);
            a.flags = 2;
            gemm4<64,64><<<dim3(1, S / 64, H), 128, SMBB>>>(a);
        }

        // x = xl + y @ Wo^T  (fp32 out; 64x64 tiles -> 256 CTAs, full wave)
        if (i == 0) cudaStreamWaitEvent(0, evWo, 0);
        {
            GArgs a = mkargs(y, D, 0, Woi, D, 0, x, D, 0, xl, 0, D, 1);
            gemm4<64,64><<<dim3(D / 64, S / 64, 1), 128, SMBB>>>(a);
        }

        // h = fp16(relu(rms(x) @ Wfc^T)^2)
        rms_rows_h_k<<<S, 256>>>(x, xn);
        if (i == 0) cudaStreamWaitEvent(0, evWfc, 0);
        {
            GArgs a = mkargs(xn, D, 0, Wfi, D, 0, h, DFF, 0, nullptr, 0, D, 2);
            gemm4<128,128><<<dim3(DFF / 128, S / 128, 1), 128, SMAA>>>(a);
        }

        // FC2 split-K x4 partials (reduced by next layer's xlrms_red / final rms)
        if (i == 0) cudaStreamWaitEvent(0, evWp, 0);
        {
            GArgs a = mkargs(h, DFF, 0, Wpi, DFF, 0, fc2, D, (long long)S * D,
                             nullptr, 0, DFF / 4, 0);
            a.flags = 4;
            gemm4<128,128><<<dim3(D / 128, S / 128, 4), 128, SMAA>>>(a);
        }
    }

    // out = rms(x + FC2 partials of last layer)
    final_red_rms_k<<<S, 256>>>((const float4*)x, (const float4*)fc2, (float4*)d_out);
}

// round 15
// speedup vs baseline: 1.1491x; 1.0105x over previous
#include <cuda_runtime.h>
#include <cuda_fp16.h>
#include <math.h>
#include <stdint.h>

#define S 1024
#define D 1024
#define H 16
#define HD 64
#define NL 6
#define DFF 4096
#define EPS 1.1920929e-07f

// ---------------- scratch (device globals; no allocation) ----------------
__device__ float  g_x [S * D];
__device__ float  g_x0[S * D];
__device__ float  g_xl[S * D];
__device__ __half g_xn[S * D];
__device__ __half g_q [S * D];
__device__ __half g_k [S * D];
__device__ __half g_v [S * D];
__device__ __half g_v1[S * D];
__device__ __half g_vt[S * D];
__device__ __half g_y [S * D];
__device__ __half g_h [S * DFF];
__device__ __half g_p [(size_t)H * S * S];
__device__ float  g_fc2[4 * S * D];
__device__ int    g_cpad[S + 1];
__device__ unsigned char g_mask[(size_t)S * S];
// fp16 weight copies (converted once per replay, overlapped on stream 2)
__device__ __half g_wq[NL * D * D];
__device__ __half g_wk[NL * D * D];
__device__ __half g_wv[NL * D * D];
__device__ __half g_wo[NL * D * D];
__device__ __half g_wfc[(size_t)NL * DFF * D];
__device__ __half g_wp [(size_t)NL * DFF * D];

// ---------------- small kernels ----------------

// wide conversion: 32B read / 16B write per thread
__global__ void tohalf2_k(const float4* __restrict__ in, uint4* __restrict__ out, int n8) {
    int i = blockIdx.x * blockDim.x + threadIdx.x;
    if (i < n8) {
        float4 a = in[2 * i];
        float4 b = in[2 * i + 1];
        __half2 h0 = __floats2half2_rn(a.x, a.y);
        __half2 h1 = __floats2half2_rn(a.z, a.w);
        __half2 h2 = __floats2half2_rn(b.x, b.y);
        __half2 h3 = __floats2half2_rn(b.z, b.w);
        uint4 r;
        r.x = *(uint32_t*)&h0;
        r.y = *(uint32_t*)&h1;
        r.z = *(uint32_t*)&h2;
        r.w = *(uint32_t*)&h3;
        out[i] = r;
    }
}

__global__ void build_prefix_k(const int* __restrict__ levels, int* __restrict__ cpad) {
    if (threadIdx.x == 0) {
        cpad[0] = 0;
        for (int i = 0; i < S; i++) cpad[i + 1] = cpad[i] + (levels[i] == 0 ? 1 : 0);
    }
}

__global__ void build_mask_k(const int* __restrict__ levels, const int* __restrict__ sample,
                             const int* __restrict__ cpad, unsigned char* __restrict__ mask) {
    int idx = blockIdx.x * blockDim.x + threadIdx.x;
    int q = idx >> 10;
    int k = idx & 1023;
    bool causal = q >= k;
    bool same = sample[q] == sample[k];
    int cnt = cpad[q] - cpad[k + 1];
    bool markov = (levels[k] == 0) && (cnt > 0);
    mask[idx] = (causal && same && !markov) ? 1 : 0;
}

// initial: x = rms(x_in); x0 = x  (both stored in one pass)
__global__ void rms_init_k(const float* __restrict__ in, float* __restrict__ x,
                           float* __restrict__ x0) {
    int row = blockIdx.x;
    const float4* p = (const float4*)(in + (size_t)row * D);
    float4* ox  = (float4*)(x  + (size_t)row * D);
    float4* ox0 = (float4*)(x0 + (size_t)row * D);
    int tid = threadIdx.x;
    float4 t = p[tid];
    float ss = t.x * t.x + t.y * t.y + t.z * t.z + t.w * t.w;
    __shared__ float red[256];
    red[tid] = ss;
    __syncthreads();
    for (int s = 128; s > 0; s >>= 1) {
        if (tid < s) red[tid] += red[tid + s];
        __syncthreads();
    }
    float sc = rsqrtf(red[0] / (float)D + EPS);
    float4 r = make_float4(t.x * sc, t.y * sc, t.z * sc, t.w * sc);
    ox[tid] = r;
    ox0[tid] = r;
}

// RMS over fp32 rows of length D -> fp16 out
__global__ void rms_rows_h_k(const float* __restrict__ in, __half* __restrict__ out) {
    int row = blockIdx.x;
    const float4* p = (const float4*)(in + (size_t)row * D);
    uint2* o = (uint2*)(out + (size_t)row * D);
    int tid = threadIdx.x;
    float4 t = p[tid];
    float ss = t.x * t.x + t.y * t.y + t.z * t.z + t.w * t.w;
    __shared__ float red[256];
    red[tid] = ss;
    __syncthreads();
    for (int s = 128; s > 0; s >>= 1) {
        if (tid < s) red[tid] += red[tid + s];
        __syncthreads();
    }
    float sc = rsqrtf(red[0] / (float)D + EPS);
    __half2 a = __floats2half2_rn(t.x * sc, t.y * sc);
    __half2 b = __floats2half2_rn(t.z * sc, t.w * sc);
    uint2 r;
    r.x = *(uint32_t*)&a;
    r.y = *(uint32_t*)&b;
    o[tid] = r;
}

// fused: xl = l0*x + l1*x0 ; xn = fp16(rms(xl)). One row per block. (layer 0)
__global__ void xlrms_k(const float4* __restrict__ x, const float4* __restrict__ x0,
                        const float* __restrict__ lambdas, int layer,
                        float4* __restrict__ xl, __half* __restrict__ xn) {
    int row = blockIdx.x;
    int tid = threadIdx.x;
    int i = row * 256 + tid;
    float l0 = lambdas[layer * 2 + 0];
    float l1 = lambdas[layer * 2 + 1];
    float4 a = x[i], b = x0[i];
    float4 t = make_float4(l0 * a.x + l1 * b.x, l0 * a.y + l1 * b.y,
                           l0 * a.z + l1 * b.z, l0 * a.w + l1 * b.w);
    xl[i] = t;
    float ss = t.x * t.x + t.y * t.y + t.z * t.z + t.w * t.w;
    __shared__ float red[256];
    red[tid] = ss;
    __syncthreads();
    for (int s = 128; s > 0; s >>= 1) {
        if (tid < s) red[tid] += red[tid + s];
        __syncthreads();
    }
    float sc = rsqrtf(red[0] / (float)D + EPS);
    __half2 h0 = __floats2half2_rn(t.x * sc, t.y * sc);
    __half2 h1 = __floats2half2_rn(t.z * sc, t.w * sc);
    uint2 r;
    r.x = *(uint32_t*)&h0;
    r.y = *(uint32_t*)&h1;
    ((uint2*)xn)[i] = r;
}

// fused: x += 4 FC2 partials (store); xl = l0*x + l1*x0; xn = fp16(rms(xl)). (layers 1..5)
__global__ void xlrms_red_k(float4* __restrict__ x, const float4* __restrict__ part,
                            const float4* __restrict__ x0,
                            const float* __restrict__ lambdas, int layer,
                            float4* __restrict__ xl, __half* __restrict__ xn) {
    int row = blockIdx.x;
    int tid = threadIdx.x;
    int i = row * 256 + tid;
    const int N4 = S * D / 4;
    float4 xv = x[i];
    #pragma unroll
    for (int j = 0; j < 4; j++) {
        float4 t = part[(size_t)j * N4 + i];
        xv.x += t.x; xv.y += t.y; xv.z += t.z; xv.w += t.w;
    }
    x[i] = xv;
    float l0 = lambdas[layer * 2 + 0];
    float l1 = lambdas[layer * 2 + 1];
    float4 b = x0[i];
    float4 t = make_float4(l0 * xv.x + l1 * b.x, l0 * xv.y + l1 * b.y,
                           l0 * xv.z + l1 * b.z, l0 * xv.w + l1 * b.w);
    xl[i] = t;
    float ss = t.x * t.x + t.y * t.y + t.z * t.z + t.w * t.w;
    __shared__ float red[256];
    red[tid] = ss;
    __syncthreads();
    for (int s = 128; s > 0; s >>= 1) {
        if (tid < s) red[tid] += red[tid + s];
        __syncthreads();
    }
    float sc = rsqrtf(red[0] / (float)D + EPS);
    __half2 h0 = __floats2half2_rn(t.x * sc, t.y * sc);
    __half2 h1 = __floats2half2_rn(t.z * sc, t.w * sc);
    uint2 r;
    r.x = *(uint32_t*)&h0;
    r.y = *(uint32_t*)&h1;
    ((uint2*)xn)[i] = r;
}

// final: out = rms(x + 4 FC2 partials)
__global__ void final_red_rms_k(const float4* __restrict__ x, const float4* __restrict__ part,
                                float4* __restrict__ out) {
    int row = blockIdx.x;
    int tid = threadIdx.x;
    int i = row * 256 + tid;
    const int N4 = S * D / 4;
    float4 xv = x[i];
    #pragma unroll
    for (int j = 0; j < 4; j++) {
        float4 t = part[(size_t)j * N4 + i];
        xv.x += t.x; xv.y += t.y; xv.z += t.z; xv.w += t.w;
    }
    float ss = xv.x * xv.x + xv.y * xv.y + xv.z * xv.z + xv.w * xv.w;
    __shared__ float red[256];
    red[tid] = ss;
    __syncthreads();
    for (int s = 128; s > 0; s >>= 1) {
        if (tid < s) red[tid] += red[tid + s];
        __syncthreads();
    }
    float sc = rsqrtf(red[0] / (float)D + EPS);
    out[i] = make_float4(xv.x * sc, xv.y * sc, xv.z * sc, xv.w * sc);
}

// fused per-(s,h) RMS + RoPE on fp16 q and k (blockIdx.y selects tensor)
__global__ void rmsrope2_k(__half* __restrict__ q, __half* __restrict__ k) {
    __half* t = blockIdx.y ? k : q;
    int warp = (blockIdx.x * blockDim.x + threadIdx.x) >> 5;
    int lane = threadIdx.x & 31;
    int s = warp >> 4;
    __half* p = t + (size_t)warp * 64;
    float a = __half2float(p[lane]);
    float b = __half2float(p[lane + 32]);
    float ss = a * a + b * b;
    #pragma unroll
    for (int o = 16; o; o >>= 1) ss += __shfl_xor_sync(0xFFFFFFFFu, ss, o);
    float sc = rsqrtf(ss / 64.f + EPS);
    a *= sc; b *= sc;
    float inv = powf(10000.f, -((float)(2 * lane)) / 64.f);
    float fr = (float)s * inv;
    float cs, sn;
    sincosf(fr, &sn, &cs);
    p[lane]      = __float2half_rn(a * cs + b * sn);
    p[lane + 32] = __float2half_rn(-a * sn + b * cs);
}

__global__ void copyu2_k(const uint2* __restrict__ in, uint2* __restrict__ out) {
    int i = blockIdx.x * blockDim.x + threadIdx.x;
    out[i] = in[i];
}

// fused v-mix + transpose: vt[c][r] = (1-la)*v[r][c] + la*v1[r][c]
__global__ void transmix_k(const __half* __restrict__ v, const __half* __restrict__ v1,
                           const float* __restrict__ lamb, int layer,
                           __half* __restrict__ vt) {
    __shared__ __half tile[32][34];
    float la = lamb[layer];
    float om = 1.f - la;
    int x = blockIdx.x * 32 + threadIdx.x;
    int y0 = blockIdx.y * 32 + threadIdx.y;
    #pragma unroll
    for (int j = 0; j < 32; j += 8) {
        size_t idx = (size_t)(y0 + j) * D + x;
        float mv = om * __half2float(v[idx]) + la * __half2float(v1[idx]);
        tile[threadIdx.y + j][threadIdx.x] = __float2half_rn(mv);
    }
    __syncthreads();
    int x2 = blockIdx.y * 32 + threadIdx.x;
    int y2 = blockIdx.x * 32 + threadIdx.y;
    #pragma unroll
    for (int j = 0; j < 32; j += 8)
        vt[(size_t)(y2 + j) * D + x2] = tile[threadIdx.x][threadIdx.y + j];
}

// ---------------- pipelined fp16 mma.sync GEMM (m16n8k16, ldmatrix), 4 warps ----------------
// C[M,N] = A[M,K] * B[N,K]^T  (NT; fp16 row-major, K contiguous)
// modes: 0 fp32 raw | 1 fp32 acc+R | 2 fp16 relu(acc)^2 | 3 fp16 mask?exp(acc*scale):0
//        5 fp16 raw | 7 fp16 acc/rowsum(A)  (rowsum computed in-kernel from staged A tiles)
// flags: 1 = triangular launch (z=h*36+t); 2 = K limited to row0+BM; 4 = split-K over z

struct GArgs {
    const __half* A; int lda; long long sA;
    const __half* B; int ldb; long long sB;
    void* C; int ldc; long long sC;
    const float* R; long long sR;
    int K; int mode; int flags; float scale;
    const unsigned char* mask;
    const __half* Bm[3]; void* Cm[3]; int nMulti;
};

#define LDMX4(r0, r1, r2, r3, addr) \
    asm volatile("ldmatrix.sync.aligned.m8n8.x4.shared.b16 {%0,%1,%2,%3}, [%4];" \
                 : "=r"(r0), "=r"(r1), "=r"(r2), "=r"(r3) : "r"(addr))

template<int BM, int BN>
__global__ __launch_bounds__(128, 2) void gemm4(GArgs a) {
    constexpr int BK = 64;                    // halves per K-tile (128 bytes/row)
    constexpr int SROW = 72;                  // padded row in halves (144B)
    constexpr int SSZ = (BM + BN) * SROW;     // halves per stage
    constexpr int WM = BM / 2, WN = BN / 2;   // 2x2 warp grid
    constexpr int FM = WM / 16, FN = WN / 8;
    constexpr int CA = BM / 16, CB = BN / 16; // cp.async 16B chunks per thread
    extern __shared__ __half sh[];
    __shared__ float rowsumsh[BM];

    int tid = threadIdx.x, lane = tid & 31, warp = tid >> 5;
    int row0, col0, koff = 0;
    const __half *A, *B;
    char* C;
    const float* R = nullptr;
    int z = blockIdx.z;

    if (a.flags & 1) {
        int t = z % 36, h = z / 36;
        int by = 0;
        while ((by + 1) * (by + 2) / 2 <= t) by++;
        int bx = t - by * (by + 1) / 2;
        row0 = by * BM; col0 = bx * BN;
        A = a.A + (size_t)h * a.sA;
        B = a.B + (size_t)h * a.sB;
        C = (char*)a.C + (size_t)h * a.sC * 2;      // fp16 C
    } else {
        row0 = blockIdx.y * BM; col0 = blockIdx.x * BN;
        if (a.flags & 4) {
            A = a.A; B = a.B;
            C = (char*)a.C + (size_t)z * a.sC * 4;  // fp32 partials
            koff = z * a.K;
        } else if (a.nMulti) {
            A = a.A; B = a.Bm[z]; C = (char*)a.Cm[z];
        } else {
            A = a.A + (size_t)z * a.sA;
            B = a.B + (size_t)z * a.sB;
            int esz = (a.mode == 0 || a.mode == 1) ? 4 : 2;
            C = (char*)a.C + (size_t)z * a.sC * esz;
            if (a.R) R = a.R + (size_t)z * a.sR;
        }
    }

    int K = a.K;
    if (a.flags & 2) { int kl = row0 + BM; if (kl < K) K = kl; }
    int KT = K / BK;

    auto issue = [&](int kt, int st) {
        __half* dstA = sh + st * SSZ;
        #pragma unroll
        for (int i = 0; i < CA; i++) {
            int id = tid + 128 * i;
            int r = id >> 3, c = id & 7;
            unsigned u = (unsigned)__cvta_generic_to_shared(dstA + r * SROW + c * 8);
            const __half* gp = A + (size_t)(row0 + r) * a.lda + koff + kt * BK + c * 8;
            asm volatile("cp.async.cg.shared.global [%0], [%1], 16;\n" :: "r"(u), "l"(gp));
        }
        __half* dstB = sh + st * SSZ + BM * SROW;
        #pragma unroll
        for (int i = 0; i < CB; i++) {
            int id = tid + 128 * i;
            int r = id >> 3, c = id & 7;
            unsigned u = (unsigned)__cvta_generic_to_shared(dstB + r * SROW + c * 8);
            const __half* gp = B + (size_t)(col0 + r) * a.ldb + koff + kt * BK + c * 8;
            asm volatile("cp.async.cg.shared.global [%0], [%1], 16;\n" :: "r"(u), "l"(gp));
        }
        asm volatile("cp.async.commit_group;\n");
    };

    float acc[FM][FN][4] = {};
    float rsum_acc = 0.f;

    issue(0, 0);
    if (KT > 1) issue(1, 1);

    int wm0 = (warp & 1) * WM, wn0 = (warp >> 1) * WN;
    int g = lane >> 2, tig = lane & 3;

    uint32_t shb = (uint32_t)__cvta_generic_to_shared(sh);
    int laneq = lane & 7, lane8 = (lane >> 3) & 1, lane16 = lane >> 4;
    uint32_t aoff = (uint32_t)((wm0 + laneq + 8 * lane8) * SROW + 8 * lane16);
    uint32_t boff = (uint32_t)((wn0 + laneq + 8 * lane16) * SROW + 8 * lane8);

    for (int kt = 0; kt < KT; kt++) {
        if (kt + 2 <= KT) asm volatile("cp.async.wait_group 1;\n");
        else              asm volatile("cp.async.wait_group 0;\n");
        __syncthreads();

        uint32_t sAb = shb + (uint32_t)((kt & 1) * SSZ) * 2;
        uint32_t sBb = sAb + BM * SROW * 2;

        // in-kernel A row sums for PV normalization (reads staged tile before overwrite)
        if (a.mode == 7) {
            if (BM == 128) {
                const __half2* rowp = (const __half2*)(sh + (kt & 1) * SSZ + tid * SROW);
                float s = 0.f;
                #pragma unroll
                for (int j = 0; j < 32; j++) {
                    float2 f = __half22float2(rowp[j]);
                    s += f.x + f.y;
                }
                rsum_acc += s;
            } else {  // BM==64: two threads per row
                const __half2* rowp = (const __half2*)(sh + (kt & 1) * SSZ +
                                                       (tid >> 1) * SROW + (tid & 1) * 32);
                float s = 0.f;
                #pragma unroll
                for (int j = 0; j < 16; j++) {
                    float2 f = __half22float2(rowp[j]);
                    s += f.x + f.y;
                }
                rsum_acc += s;
            }
        }

        #pragma unroll
        for (int s16 = 0; s16 < BK; s16 += 16) {
            uint32_t af[FM][4], bf[FN][2];
            #pragma unroll
            for (int fm = 0; fm < FM; fm++) {
                LDMX4(af[fm][0], af[fm][1], af[fm][2], af[fm][3],
                      sAb + (aoff + fm * 16 * SROW + s16) * 2);
            }
            #pragma unroll
            for (int fp = 0; fp < FN / 2; fp++) {
                LDMX4(bf[2 * fp][0], bf[2 * fp][1], bf[2 * fp + 1][0], bf[2 * fp + 1][1],
                      sBb + (boff + fp * 16 * SROW + s16) * 2);
            }
            #pragma unroll
            for (int fm = 0; fm < FM; fm++)
                #pragma unroll
                for (int fn = 0; fn < FN; fn++) {
                    asm volatile(
                        "mma.sync.aligned.m16n8k16.row.col.f32.f16.f16.f32 "
                        "{%0,%1,%2,%3}, {%4,%5,%6,%7}, {%8,%9}, {%0,%1,%2,%3};\n"
                        : "+f"(acc[fm][fn][0]), "+f"(acc[fm][fn][1]),
                          "+f"(acc[fm][fn][2]), "+f"(acc[fm][fn][3])
                        : "r"(af[fm][0]), "r"(af[fm][1]), "r"(af[fm][2]), "r"(af[fm][3]),
                          "r"(bf[fn][0]), "r"(bf[fn][1]));
                }
        }
        __syncthreads();
        if (kt + 2 < KT) issue(kt + 2, kt & 1);
    }

    if (a.mode == 7) {
        if (BM == 128) {
            rowsumsh[tid] = rsum_acc;
        } else {
            float s = rsum_acc + __shfl_xor_sync(0xFFFFFFFFu, rsum_acc, 1);
            if (!(tid & 1)) rowsumsh[tid >> 1] = s;
        }
        __syncthreads();
    }

    // epilogue
    #pragma unroll
    for (int fm = 0; fm < FM; fm++) {
        #pragma unroll
        for (int fn = 0; fn < FN; fn++) {
            int r0 = row0 + wm0 + fm * 16 + g;
            int c  = col0 + wn0 + fn * 8 + 2 * tig;
            #pragma unroll
            for (int half = 0; half < 2; half++) {
                int r = r0 + 8 * half;
                float v0 = acc[fm][fn][2 * half + 0];
                float v1 = acc[fm][fn][2 * half + 1];
                size_t off = (size_t)r * a.ldc + c;
                if (a.mode == 0) {
                    ((float*)C)[off] = v0;
                    ((float*)C)[off + 1] = v1;
                } else if (a.mode == 1) {
                    ((float*)C)[off] = v0 + R[off];
                    ((float*)C)[off + 1] = v1 + R[off + 1];
                } else {
                    if (a.mode == 2) {
                        v0 = fmaxf(v0, 0.f); v0 *= v0;
                        v1 = fmaxf(v1, 0.f); v1 *= v1;
                    } else if (a.mode == 3) {
                        const unsigned char* m = a.mask + (size_t)r * S + c;
                        v0 = m[0] ? __expf(v0 * a.scale) : 0.f;
                        v1 = m[1] ? __expf(v1 * a.scale) : 0.f;
                    } else if (a.mode == 7) {
                        float rsv = 1.0f / rowsumsh[r - row0];
                        v0 *= rsv;
                        v1 *= rsv;
                    }
                    __half2 hv = __floats2half2_rn(v0, v1);
                    *(__half2*)((__half*)C + off) = hv;
                }
            }
        }
    }
}

// ---------------- host orchestration ----------------

static inline GArgs mkargs(const __half* A, int lda, long long sA,
                           const __half* B, int ldb, long long sB,
                           void* C, int ldc, long long sC,
                           const float* R, long long sR, int K, int mode) {
    GArgs a;
    a.A = A; a.lda = lda; a.sA = sA;
    a.B = B; a.ldb = ldb; a.sB = sB;
    a.C = C; a.ldc = ldc; a.sC = sC;
    a.R = R; a.sR = sR; a.K = K; a.mode = mode;
    a.flags = 0; a.scale = 0.f; a.mask = nullptr;
    a.Bm[0] = a.Bm[1] = a.Bm[2] = nullptr;
    a.Cm[0] = a.Cm[1] = a.Cm[2] = nullptr;
    a.nMulti = 0;
    return a;
}

extern "C" void kernel_launch(void* const* d_in, const int* in_sizes, int n_in,
                              void* d_out, int out_size) {
    const float* x_in    = (const float*)d_in[0];
    const float* Wq      = (const float*)d_in[1];
    const float* Wk      = (const float*)d_in[2];
    const float* Wv      = (const float*)d_in[3];
    const float* Wo      = (const float*)d_in[4];
    const float* lamb    = (const float*)d_in[5];
    const float* lambdas = (const float*)d_in[6];
    const float* Wfc     = (const float*)d_in[7];
    const float* Wp      = (const float*)d_in[8];
    const int*   levels  = (const int*)d_in[9];
    const int*   sample  = (const int*)d_in[10];

    float *x, *x0, *xl, *fc2;
    __half *xn, *q, *k, *v, *v1, *vt, *y, *h, *p;
    __half *wq, *wk, *wv, *wo, *wfc, *wp;
    int* cpad;
    unsigned char* mask;
    cudaGetSymbolAddress((void**)&x,  g_x);
    cudaGetSymbolAddress((void**)&x0, g_x0);
    cudaGetSymbolAddress((void**)&xl, g_xl);
    cudaGetSymbolAddress((void**)&xn, g_xn);
    cudaGetSymbolAddress((void**)&q,  g_q);
    cudaGetSymbolAddress((void**)&k,  g_k);
    cudaGetSymbolAddress((void**)&v,  g_v);
    cudaGetSymbolAddress((void**)&v1, g_v1);
    cudaGetSymbolAddress((void**)&vt, g_vt);
    cudaGetSymbolAddress((void**)&y,  g_y);
    cudaGetSymbolAddress((void**)&h,  g_h);
    cudaGetSymbolAddress((void**)&p,  g_p);
    cudaGetSymbolAddress((void**)&fc2, g_fc2);
    cudaGetSymbolAddress((void**)&cpad, g_cpad);
    cudaGetSymbolAddress((void**)&mask, g_mask);
    cudaGetSymbolAddress((void**)&wq, g_wq);
    cudaGetSymbolAddress((void**)&wk, g_wk);
    cudaGetSymbolAddress((void**)&wv, g_wv);
    cudaGetSymbolAddress((void**)&wo, g_wo);
    cudaGetSymbolAddress((void**)&wfc, g_wfc);
    cudaGetSymbolAddress((void**)&wp, g_wp);

    const int SMAA = (128 + 128) * 72 * 2 * 2;  // 73728 bytes
    const int SMAB = (128 + 64) * 72 * 2 * 2;   // 55296 bytes
    const int SMBB = (64 + 64) * 72 * 2 * 2;    // 36864 bytes
    cudaFuncSetAttribute(gemm4<128,128>, cudaFuncAttributeMaxDynamicSharedMemorySize, SMAA);
    cudaFuncSetAttribute(gemm4<128,64>,  cudaFuncAttributeMaxDynamicSharedMemorySize, SMAB);
    cudaFuncSetAttribute(gemm4<64,64>,   cudaFuncAttributeMaxDynamicSharedMemorySize, SMBB);

    const int EW4 = (S * D / 4) / 256;
    const float scale = 1.0f / 8.0f;             // HD^-0.5

    // ---- stream-2 weight conversion, overlapped (isolated at -16us, R8 vs R9) ----
    cudaStream_t s2;
    cudaStreamCreateWithFlags(&s2, cudaStreamNonBlocking);
    cudaEvent_t evRoot, evQKV, evWo, evWfc, evWp;
    cudaEventCreateWithFlags(&evRoot, cudaEventDisableTiming);
    cudaEventCreateWithFlags(&evQKV,  cudaEventDisableTiming);
    cudaEventCreateWithFlags(&evWo,   cudaEventDisableTiming);
    cudaEventCreateWithFlags(&evWfc,  cudaEventDisableTiming);
    cudaEventCreateWithFlags(&evWp,   cudaEventDisableTiming);

    cudaEventRecord(evRoot, 0);
    cudaStreamWaitEvent(s2, evRoot, 0);
    {
        int n8a = NL * D * D / 8;
        int n8b = NL * DFF * D / 8;
        tohalf2_k<<<(n8a + 255) / 256, 256, 0, s2>>>((const float4*)Wq, (uint4*)wq, n8a);
        tohalf2_k<<<(n8a + 255) / 256, 256, 0, s2>>>((const float4*)Wk, (uint4*)wk, n8a);
        tohalf2_k<<<(n8a + 255) / 256, 256, 0, s2>>>((const float4*)Wv, (uint4*)wv, n8a);
        cudaEventRecord(evQKV, s2);
        tohalf2_k<<<(n8a + 255) / 256, 256, 0, s2>>>((const float4*)Wo, (uint4*)wo, n8a);
        cudaEventRecord(evWo, s2);
        tohalf2_k<<<(n8b + 255) / 256, 256, 0, s2>>>((const float4*)Wfc, (uint4*)wfc, n8b);
        cudaEventRecord(evWfc, s2);
        tohalf2_k<<<(n8b + 255) / 256, 256, 0, s2>>>((const float4*)Wp, (uint4*)wp, n8b);
        cudaEventRecord(evWp, s2);
    }

    build_prefix_k<<<1, 32>>>(levels, cpad);
    build_mask_k<<<(S * S) / 256, 256>>>(levels, sample, cpad, mask);

    // x = rms(x_in); x0 = x  (single pass)
    rms_init_k<<<S, 256>>>(x_in, x, x0);

    for (int i = 0; i < NL; i++) {
        const __half* Wqi = wq + (size_t)i * D * D;
        const __half* Wki = wk + (size_t)i * D * D;
        const __half* Wvi = wv + (size_t)i * D * D;
        const __half* Woi = wo + (size_t)i * D * D;
        const __half* Wfi = wfc + (size_t)i * DFF * D;
        const __half* Wpi = wp + (size_t)i * D * DFF;

        // xl/xn prep; layers >=1 also fold in previous layer's FC2 partials
        if (i == 0)
            xlrms_k<<<S, 256>>>((const float4*)x, (const float4*)x0, lambdas, i,
                                (float4*)xl, xn);
        else
            xlrms_red_k<<<S, 256>>>((float4*)x, (const float4*)fc2, (const float4*)x0,
                                    lambdas, i, (float4*)xl, xn);

        // fused QKV (fp16 out; BN=64 -> 384 CTAs, balanced waves)
        if (i == 0) cudaStreamWaitEvent(0, evQKV, 0);
        {
            GArgs a = mkargs(xn, D, 0, nullptr, D, 0, nullptr, D, 0, nullptr, 0, D, 5);
            a.Bm[0] = Wqi; a.Bm[1] = Wki; a.Bm[2] = Wvi;
            a.Cm[0] = q;   a.Cm[1] = k;   a.Cm[2] = v;
            a.nMulti = 3;
            gemm4<128,64><<<dim3(D / 64, S / 128, 3), 128, SMAB>>>(a);
        }

        if (i == 0) copyu2_k<<<EW4, 256>>>((const uint2*)v, (uint2*)v1);

        rmsrope2_k<<<dim3((S * H) / 8, 2), 256>>>(q, k);

        // vt = transpose((1-la)*v + la*v1)
        transmix_k<<<dim3(32, 32), dim3(32, 8)>>>(v, v1, lamb, i, vt);

        // p[h] = mask .* exp(scale * q_h k_h^T), lower-triangular blocks (fp16)
        {
            GArgs a = mkargs(q, D, HD, k, D, HD, p, S, (long long)S * S, nullptr, 0, HD, 3);
            a.flags = 1; a.scale = scale; a.mask = mask;
            gemm4<128,128><<<dim3(1, 1, H * 36), 128, SMAA>>>(a);
        }

        // y[:,h] = fp16((p_h @ V_h) / rowsum) — BM=64 halves the triangular critical path
        {
            GArgs a = mkargs(p, S, (long long)S * S, vt, S, (long long)HD * S,
                             y, D, HD, nullptr, 0, S, 7);
            a.flags = 2;
            gemm4<64,64><<<dim3(1, S / 64, H), 128, SMBB>>>(a);
        }

        // x = xl + y @ Wo^T  (fp32 out; 64x64 tiles -> 256 CTAs, full wave)
        if (i == 0) cudaStreamWaitEvent(0, evWo, 0);
        {
            GArgs a = mkargs(y, D, 0, Woi, D, 0, x, D, 0, xl, 0, D, 1);
            gemm4<64,64><<<dim3(D / 64, S / 64, 1), 128, SMBB>>>(a);
        }

        // h = fp16(relu(rms(x) @ Wfc^T)^2)
        rms_rows_h_k<<<S, 256>>>(x, xn);
        if (i == 0) cudaStreamWaitEvent(0, evWfc, 0);
        {
            GArgs a = mkargs(xn, D, 0, Wfi, D, 0, h, DFF, 0, nullptr, 0, D, 2);
            gemm4<128,128><<<dim3(DFF / 128, S / 128, 1), 128, SMAA>>>(a);
        }

        // FC2 split-K x4 partials (reduced by next layer's xlrms_red / final rms)
        if (i == 0) cudaStreamWaitEvent(0, evWp, 0);
        {
            GArgs a = mkargs(h, DFF, 0, Wpi, DFF, 0, fc2, D, (long long)S * D,
                             nullptr, 0, DFF / 4, 0);
            a.flags = 4;
            gemm4<128,128><<<dim3(D / 128, S / 128, 4), 128, SMAA>>>(a);
        }
    }

    // out = rms(x + FC2 partials of last layer)
    final_red_rms_k<<<S, 256>>>((const float4*)x, (const float4*)fc2, (float4*)d_out);
}

// round 16
// speedup vs baseline: 1.2120x; 1.0547x over previous
#include <cuda_runtime.h>
#include <cuda_fp16.h>
#include <math.h>
#include <stdint.h>

#define S 1024
#define D 1024
#define H 16
#define HD 64
#define NL 6
#define DFF 4096
#define EPS 1.1920929e-07f

// ---------------- scratch (device globals; no allocation) ----------------
__device__ float  g_x [S * D];
__device__ float  g_x0[S * D];
__device__ float  g_xl[S * D];
__device__ __half g_xn[S * D];
__device__ __half g_q [S * D];
__device__ __half g_k [S * D];
__device__ __half g_v [S * D];
__device__ __half g_v1[S * D];
__device__ __half g_vt[S * D];
__device__ __half g_y [S * D];
__device__ __half g_h [S * DFF];
__device__ __half g_p [(size_t)H * S * S];
__device__ float  g_fc2[4 * S * D];
__device__ int    g_cpad[S + 1];
__device__ unsigned char g_mask[(size_t)S * S];
// fp16 weight copies (converted once per replay, overlapped on stream 2)
__device__ __half g_wq[NL * D * D];
__device__ __half g_wk[NL * D * D];
__device__ __half g_wv[NL * D * D];
__device__ __half g_wo[NL * D * D];
__device__ __half g_wfc[(size_t)NL * DFF * D];
__device__ __half g_wp [(size_t)NL * DFF * D];

// ---------------- small kernels ----------------

__global__ void tohalf2_k(const float4* __restrict__ in, uint4* __restrict__ out, int n8) {
    int i = blockIdx.x * blockDim.x + threadIdx.x;
    if (i < n8) {
        float4 a = in[2 * i];
        float4 b = in[2 * i + 1];
        __half2 h0 = __floats2half2_rn(a.x, a.y);
        __half2 h1 = __floats2half2_rn(a.z, a.w);
        __half2 h2 = __floats2half2_rn(b.x, b.y);
        __half2 h3 = __floats2half2_rn(b.z, b.w);
        uint4 r;
        r.x = *(uint32_t*)&h0;
        r.y = *(uint32_t*)&h1;
        r.z = *(uint32_t*)&h2;
        r.w = *(uint32_t*)&h3;
        out[i] = r;
    }
}

__global__ void build_prefix_k(const int* __restrict__ levels, int* __restrict__ cpad) {
    if (threadIdx.x == 0) {
        cpad[0] = 0;
        for (int i = 0; i < S; i++) cpad[i + 1] = cpad[i] + (levels[i] == 0 ? 1 : 0);
    }
}

__global__ void build_mask_k(const int* __restrict__ levels, const int* __restrict__ sample,
                             const int* __restrict__ cpad, unsigned char* __restrict__ mask) {
    int idx = blockIdx.x * blockDim.x + threadIdx.x;
    int q = idx >> 10;
    int k = idx & 1023;
    bool causal = q >= k;
    bool same = sample[q] == sample[k];
    int cnt = cpad[q] - cpad[k + 1];
    bool markov = (levels[k] == 0) && (cnt > 0);
    mask[idx] = (causal && same && !markov) ? 1 : 0;
}

// initial: x = rms(x_in); x0 = x
__global__ void rms_init_k(const float* __restrict__ in, float* __restrict__ x,
                           float* __restrict__ x0) {
    int row = blockIdx.x;
    const float4* p = (const float4*)(in + (size_t)row * D);
    float4* ox  = (float4*)(x  + (size_t)row * D);
    float4* ox0 = (float4*)(x0 + (size_t)row * D);
    int tid = threadIdx.x;
    float4 t = p[tid];
    float ss = t.x * t.x + t.y * t.y + t.z * t.z + t.w * t.w;
    __shared__ float red[256];
    red[tid] = ss;
    __syncthreads();
    for (int s = 128; s > 0; s >>= 1) {
        if (tid < s) red[tid] += red[tid + s];
        __syncthreads();
    }
    float sc = rsqrtf(red[0] / (float)D + EPS);
    float4 r = make_float4(t.x * sc, t.y * sc, t.z * sc, t.w * sc);
    ox[tid] = r;
    ox0[tid] = r;
}

// RMS over fp32 rows of length D -> fp16 out
__global__ void rms_rows_h_k(const float* __restrict__ in, __half* __restrict__ out) {
    int row = blockIdx.x;
    const float4* p = (const float4*)(in + (size_t)row * D);
    uint2* o = (uint2*)(out + (size_t)row * D);
    int tid = threadIdx.x;
    float4 t = p[tid];
    float ss = t.x * t.x + t.y * t.y + t.z * t.z + t.w * t.w;
    __shared__ float red[256];
    red[tid] = ss;
    __syncthreads();
    for (int s = 128; s > 0; s >>= 1) {
        if (tid < s) red[tid] += red[tid + s];
        __syncthreads();
    }
    float sc = rsqrtf(red[0] / (float)D + EPS);
    __half2 a = __floats2half2_rn(t.x * sc, t.y * sc);
    __half2 b = __floats2half2_rn(t.z * sc, t.w * sc);
    uint2 r;
    r.x = *(uint32_t*)&a;
    r.y = *(uint32_t*)&b;
    o[tid] = r;
}

// fused: xl = l0*x + l1*x0 ; xn = fp16(rms(xl)). (layer 0)
__global__ void xlrms_k(const float4* __restrict__ x, const float4* __restrict__ x0,
                        const float* __restrict__ lambdas, int layer,
                        float4* __restrict__ xl, __half* __restrict__ xn) {
    int row = blockIdx.x;
    int tid = threadIdx.x;
    int i = row * 256 + tid;
    float l0 = lambdas[layer * 2 + 0];
    float l1 = lambdas[layer * 2 + 1];
    float4 a = x[i], b = x0[i];
    float4 t = make_float4(l0 * a.x + l1 * b.x, l0 * a.y + l1 * b.y,
                           l0 * a.z + l1 * b.z, l0 * a.w + l1 * b.w);
    xl[i] = t;
    float ss = t.x * t.x + t.y * t.y + t.z * t.z + t.w * t.w;
    __shared__ float red[256];
    red[tid] = ss;
    __syncthreads();
    for (int s = 128; s > 0; s >>= 1) {
        if (tid < s) red[tid] += red[tid + s];
        __syncthreads();
    }
    float sc = rsqrtf(red[0] / (float)D + EPS);
    __half2 h0 = __floats2half2_rn(t.x * sc, t.y * sc);
    __half2 h1 = __floats2half2_rn(t.z * sc, t.w * sc);
    uint2 r;
    r.x = *(uint32_t*)&h0;
    r.y = *(uint32_t*)&h1;
    ((uint2*)xn)[i] = r;
}

// fused: x += 4 FC2 partials; xl = l0*x + l1*x0; xn = fp16(rms(xl)). (layers 1..5)
__global__ void xlrms_red_k(float4* __restrict__ x, const float4* __restrict__ part,
                            const float4* __restrict__ x0,
                            const float* __restrict__ lambdas, int layer,
                            float4* __restrict__ xl, __half* __restrict__ xn) {
    int row = blockIdx.x;
    int tid = threadIdx.x;
    int i = row * 256 + tid;
    const int N4 = S * D / 4;
    float4 xv = x[i];
    #pragma unroll
    for (int j = 0; j < 4; j++) {
        float4 t = part[(size_t)j * N4 + i];
        xv.x += t.x; xv.y += t.y; xv.z += t.z; xv.w += t.w;
    }
    x[i] = xv;
    float l0 = lambdas[layer * 2 + 0];
    float l1 = lambdas[layer * 2 + 1];
    float4 b = x0[i];
    float4 t = make_float4(l0 * xv.x + l1 * b.x, l0 * xv.y + l1 * b.y,
                           l0 * xv.z + l1 * b.z, l0 * xv.w + l1 * b.w);
    xl[i] = t;
    float ss = t.x * t.x + t.y * t.y + t.z * t.z + t.w * t.w;
    __shared__ float red[256];
    red[tid] = ss;
    __syncthreads();
    for (int s = 128; s > 0; s >>= 1) {
        if (tid < s) red[tid] += red[tid + s];
        __syncthreads();
    }
    float sc = rsqrtf(red[0] / (float)D + EPS);
    __half2 h0 = __floats2half2_rn(t.x * sc, t.y * sc);
    __half2 h1 = __floats2half2_rn(t.z * sc, t.w * sc);
    uint2 r;
    r.x = *(uint32_t*)&h0;
    r.y = *(uint32_t*)&h1;
    ((uint2*)xn)[i] = r;
}

// final: out = rms(x + 4 FC2 partials)
__global__ void final_red_rms_k(const float4* __restrict__ x, const float4* __restrict__ part,
                                float4* __restrict__ out) {
    int row = blockIdx.x;
    int tid = threadIdx.x;
    int i = row * 256 + tid;
    const int N4 = S * D / 4;
    float4 xv = x[i];
    #pragma unroll
    for (int j = 0; j < 4; j++) {
        float4 t = part[(size_t)j * N4 + i];
        xv.x += t.x; xv.y += t.y; xv.z += t.z; xv.w += t.w;
    }
    float ss = xv.x * xv.x + xv.y * xv.y + xv.z * xv.z + xv.w * xv.w;
    __shared__ float red[256];
    red[tid] = ss;
    __syncthreads();
    for (int s = 128; s > 0; s >>= 1) {
        if (tid < s) red[tid] += red[tid + s];
        __syncthreads();
    }
    float sc = rsqrtf(red[0] / (float)D + EPS);
    out[i] = make_float4(xv.x * sc, xv.y * sc, xv.z * sc, xv.w * sc);
}

// fused per-(s,h) RMS + RoPE on fp16 q and k (blockIdx.y selects tensor)
__global__ void rmsrope2_k(__half* __restrict__ q, __half* __restrict__ k) {
    __half* t = blockIdx.y ? k : q;
    int warp = (blockIdx.x * blockDim.x + threadIdx.x) >> 5;
    int lane = threadIdx.x & 31;
    int s = warp >> 4;
    __half* p = t + (size_t)warp * 64;
    float a = __half2float(p[lane]);
    float b = __half2float(p[lane + 32]);
    float ss = a * a + b * b;
    #pragma unroll
    for (int o = 16; o; o >>= 1) ss += __shfl_xor_sync(0xFFFFFFFFu, ss, o);
    float sc = rsqrtf(ss / 64.f + EPS);
    a *= sc; b *= sc;
    float inv = powf(10000.f, -((float)(2 * lane)) / 64.f);
    float fr = (float)s * inv;
    float cs, sn;
    sincosf(fr, &sn, &cs);
    p[lane]      = __float2half_rn(a * cs + b * sn);
    p[lane + 32] = __float2half_rn(-a * sn + b * cs);
}

__global__ void copyu2_k(const uint2* __restrict__ in, uint2* __restrict__ out) {
    int i = blockIdx.x * blockDim.x + threadIdx.x;
    out[i] = in[i];
}

// fused v-mix + transpose: vt[c][r] = (1-la)*v[r][c] + la*v1[r][c]
__global__ void transmix_k(const __half* __restrict__ v, const __half* __restrict__ v1,
                           const float* __restrict__ lamb, int layer,
                           __half* __restrict__ vt) {
    __shared__ __half tile[32][34];
    float la = lamb[layer];
    float om = 1.f - la;
    int x = blockIdx.x * 32 + threadIdx.x;
    int y0 = blockIdx.y * 32 + threadIdx.y;
    #pragma unroll
    for (int j = 0; j < 32; j += 8) {
        size_t idx = (size_t)(y0 + j) * D + x;
        float mv = om * __half2float(v[idx]) + la * __half2float(v1[idx]);
        tile[threadIdx.y + j][threadIdx.x] = __float2half_rn(mv);
    }
    __syncthreads();
    int x2 = blockIdx.y * 32 + threadIdx.x;
    int y2 = blockIdx.x * 32 + threadIdx.y;
    #pragma unroll
    for (int j = 0; j < 32; j += 8)
        vt[(size_t)(y2 + j) * D + x2] = tile[threadIdx.x][threadIdx.y + j];
}

// ---------------- pipelined fp16 mma.sync GEMM (m16n8k16, ldmatrix), 4 warps ----------------
// C[M,N] = A[M,K] * B[N,K]^T  (NT; fp16 row-major, K contiguous)
// modes: 0 fp32 raw | 1 fp32 acc+R | 2 fp16 relu(acc)^2 | 3 fp16 mask?exp(acc*scale):0
//        5 fp16 raw | 7 fp16 acc/rowsum(A)  (rowsum computed in-kernel from staged A tiles)
// flags: 1 = triangular launch (z=h*36+t); 2 = K limited to row0+BM; 4 = split-K over z

struct GArgs {
    const __half* A; int lda; long long sA;
    const __half* B; int ldb; long long sB;
    void* C; int ldc; long long sC;
    const float* R; long long sR;
    int K; int mode; int flags; float scale;
    const unsigned char* mask;
    const __half* Bm[3]; void* Cm[3]; int nMulti;
};

#define LDMX4(r0, r1, r2, r3, addr) \
    asm volatile("ldmatrix.sync.aligned.m8n8.x4.shared.b16 {%0,%1,%2,%3}, [%4];" \
                 : "=r"(r0), "=r"(r1), "=r"(r2), "=r"(r3) : "r"(addr))

template<int BM, int BN>
__global__ __launch_bounds__(128, 2) void gemm4(GArgs a) {
    constexpr int BK = 64;                    // halves per K-tile (128 bytes/row)
    constexpr int SROW = 72;                  // padded row in halves (144B)
    constexpr int SSZ = (BM + BN) * SROW;     // halves per stage
    constexpr int WM = BM / 2, WN = BN / 2;   // 2x2 warp grid
    constexpr int FM = WM / 16, FN = WN / 8;
    constexpr int CA = BM / 16, CB = BN / 16; // cp.async 16B chunks per thread
    extern __shared__ __half sh[];
    __shared__ float rowsumsh[BM];

    int tid = threadIdx.x, lane = tid & 31, warp = tid >> 5;
    int row0, col0, koff = 0;
    const __half *A, *B;
    char* C;
    const float* R = nullptr;
    int z = blockIdx.z;

    if (a.flags & 1) {
        int t = z % 36, h = z / 36;
        int by = 0;
        while ((by + 1) * (by + 2) / 2 <= t) by++;
        int bx = t - by * (by + 1) / 2;
        row0 = by * BM; col0 = bx * BN;
        A = a.A + (size_t)h * a.sA;
        B = a.B + (size_t)h * a.sB;
        C = (char*)a.C + (size_t)h * a.sC * 2;      // fp16 C
    } else {
        row0 = blockIdx.y * BM; col0 = blockIdx.x * BN;
        if (a.flags & 4) {
            A = a.A; B = a.B;
            C = (char*)a.C + (size_t)z * a.sC * 4;  // fp32 partials
            koff = z * a.K;
        } else if (a.nMulti) {
            A = a.A; B = a.Bm[z]; C = (char*)a.Cm[z];
        } else {
            A = a.A + (size_t)z * a.sA;
            B = a.B + (size_t)z * a.sB;
            int esz = (a.mode == 0 || a.mode == 1) ? 4 : 2;
            C = (char*)a.C + (size_t)z * a.sC * esz;
            if (a.R) R = a.R + (size_t)z * a.sR;
        }
    }

    int K = a.K;
    if (a.flags & 2) { int kl = row0 + BM; if (kl < K) K = kl; }
    int KT = K / BK;

    auto issue = [&](int kt, int st) {
        __half* dstA = sh + st * SSZ;
        #pragma unroll
        for (int i = 0; i < CA; i++) {
            int id = tid + 128 * i;
            int r = id >> 3, c = id & 7;
            unsigned u = (unsigned)__cvta_generic_to_shared(dstA + r * SROW + c * 8);
            const __half* gp = A + (size_t)(row0 + r) * a.lda + koff + kt * BK + c * 8;
            asm volatile("cp.async.cg.shared.global [%0], [%1], 16;\n" :: "r"(u), "l"(gp));
        }
        __half* dstB = sh + st * SSZ + BM * SROW;
        #pragma unroll
        for (int i = 0; i < CB; i++) {
            int id = tid + 128 * i;
            int r = id >> 3, c = id & 7;
            unsigned u = (unsigned)__cvta_generic_to_shared(dstB + r * SROW + c * 8);
            const __half* gp = B + (size_t)(col0 + r) * a.ldb + koff + kt * BK + c * 8;
            asm volatile("cp.async.cg.shared.global [%0], [%1], 16;\n" :: "r"(u), "l"(gp));
        }
        asm volatile("cp.async.commit_group;\n");
    };

    float acc[FM][FN][4] = {};
    float rsum_acc = 0.f;

    issue(0, 0);
    if (KT > 1) issue(1, 1);

    int wm0 = (warp & 1) * WM, wn0 = (warp >> 1) * WN;
    int g = lane >> 2, tig = lane & 3;

    uint32_t shb = (uint32_t)__cvta_generic_to_shared(sh);
    int laneq = lane & 7, lane8 = (lane >> 3) & 1, lane16 = lane >> 4;
    uint32_t aoff = (uint32_t)((wm0 + laneq + 8 * lane8) * SROW + 8 * lane16);
    uint32_t boff = (uint32_t)((wn0 + laneq + 8 * lane16) * SROW + 8 * lane8);

    for (int kt = 0; kt < KT; kt++) {
        if (kt + 2 <= KT) asm volatile("cp.async.wait_group 1;\n");
        else              asm volatile("cp.async.wait_group 0;\n");
        __syncthreads();

        uint32_t sAb = shb + (uint32_t)((kt & 1) * SSZ) * 2;
        uint32_t sBb = sAb + BM * SROW * 2;

        // in-kernel A row sums for PV normalization (reads staged tile before overwrite)
        if (a.mode == 7) {
            if (BM == 128) {
                const __half2* rowp = (const __half2*)(sh + (kt & 1) * SSZ + tid * SROW);
                float s = 0.f;
                #pragma unroll
                for (int j = 0; j < 32; j++) {
                    float2 f = __half22float2(rowp[j]);
                    s += f.x + f.y;
                }
                rsum_acc += s;
            } else {  // BM==64: two threads per row
                const __half2* rowp = (const __half2*)(sh + (kt & 1) * SSZ +
                                                       (tid >> 1) * SROW + (tid & 1) * 32);
                float s = 0.f;
                #pragma unroll
                for (int j = 0; j < 16; j++) {
                    float2 f = __half22float2(rowp[j]);
                    s += f.x + f.y;
                }
                rsum_acc += s;
            }
        }

        #pragma unroll
        for (int s16 = 0; s16 < BK; s16 += 16) {
            uint32_t af[FM][4], bf[FN][2];
            #pragma unroll
            for (int fm = 0; fm < FM; fm++) {
                LDMX4(af[fm][0], af[fm][1], af[fm][2], af[fm][3],
                      sAb + (aoff + fm * 16 * SROW + s16) * 2);
            }
            #pragma unroll
            for (int fp = 0; fp < FN / 2; fp++) {
                LDMX4(bf[2 * fp][0], bf[2 * fp][1], bf[2 * fp + 1][0], bf[2 * fp + 1][1],
                      sBb + (boff + fp * 16 * SROW + s16) * 2);
            }
            #pragma unroll
            for (int fm = 0; fm < FM; fm++)
                #pragma unroll
                for (int fn = 0; fn < FN; fn++) {
                    asm volatile(
                        "mma.sync.aligned.m16n8k16.row.col.f32.f16.f16.f32 "
                        "{%0,%1,%2,%3}, {%4,%5,%6,%7}, {%8,%9}, {%0,%1,%2,%3};\n"
                        : "+f"(acc[fm][fn][0]), "+f"(acc[fm][fn][1]),
                          "+f"(acc[fm][fn][2]), "+f"(acc[fm][fn][3])
                        : "r"(af[fm][0]), "r"(af[fm][1]), "r"(af[fm][2]), "r"(af[fm][3]),
                          "r"(bf[fn][0]), "r"(bf[fn][1]));
                }
        }
        __syncthreads();
        if (kt + 2 < KT) issue(kt + 2, kt & 1);
    }

    if (a.mode == 7) {
        if (BM == 128) {
            rowsumsh[tid] = rsum_acc;
        } else {
            float s = rsum_acc + __shfl_xor_sync(0xFFFFFFFFu, rsum_acc, 1);
            if (!(tid & 1)) rowsumsh[tid >> 1] = s;
        }
        __syncthreads();
    }

    // mode 3: stage this CTA's mask tile into (now-dead) smem with coalesced loads
    unsigned char* msh = (unsigned char*)sh;
    if (a.mode == 3) {
        constexpr int NCH = (BM * BN / 16) / 128;    // uint4 chunks per thread
        constexpr int CPR = BN / 16;                 // chunks per row
        #pragma unroll
        for (int i = 0; i < NCH; i++) {
            int id = tid + 128 * i;
            int r = id / CPR, c = id % CPR;
            ((uint4*)msh)[id] =
                *(const uint4*)(a.mask + (size_t)(row0 + r) * S + col0 + c * 16);
        }
        __syncthreads();
    }

    // epilogue
    #pragma unroll
    for (int fm = 0; fm < FM; fm++) {
        #pragma unroll
        for (int fn = 0; fn < FN; fn++) {
            int r0 = row0 + wm0 + fm * 16 + g;
            int c  = col0 + wn0 + fn * 8 + 2 * tig;
            #pragma unroll
            for (int half = 0; half < 2; half++) {
                int r = r0 + 8 * half;
                float v0 = acc[fm][fn][2 * half + 0];
                float v1 = acc[fm][fn][2 * half + 1];
                size_t off = (size_t)r * a.ldc + c;
                if (a.mode == 0) {
                    ((float*)C)[off] = v0;
                    ((float*)C)[off + 1] = v1;
                } else if (a.mode == 1) {
                    ((float*)C)[off] = v0 + R[off];
                    ((float*)C)[off + 1] = v1 + R[off + 1];
                } else {
                    if (a.mode == 2) {
                        v0 = fmaxf(v0, 0.f); v0 *= v0;
                        v1 = fmaxf(v1, 0.f); v1 *= v1;
                    } else if (a.mode == 3) {
                        const unsigned char* m = msh + (r - row0) * BN + (c - col0);
                        v0 = m[0] ? __expf(v0 * a.scale) : 0.f;
                        v1 = m[1] ? __expf(v1 * a.scale) : 0.f;
                    } else if (a.mode == 7) {
                        float rsv = 1.0f / rowsumsh[r - row0];
                        v0 *= rsv;
                        v1 *= rsv;
                    }
                    __half2 hv = __floats2half2_rn(v0, v1);
                    *(__half2*)((__half*)C + off) = hv;
                }
            }
        }
    }
}

// ---------------- host orchestration ----------------

static inline GArgs mkargs(const __half* A, int lda, long long sA,
                           const __half* B, int ldb, long long sB,
                           void* C, int ldc, long long sC,
                           const float* R, long long sR, int K, int mode) {
    GArgs a;
    a.A = A; a.lda = lda; a.sA = sA;
    a.B = B; a.ldb = ldb; a.sB = sB;
    a.C = C; a.ldc = ldc; a.sC = sC;
    a.R = R; a.sR = sR; a.K = K; a.mode = mode;
    a.flags = 0; a.scale = 0.f; a.mask = nullptr;
    a.Bm[0] = a.Bm[1] = a.Bm[2] = nullptr;
    a.Cm[0] = a.Cm[1] = a.Cm[2] = nullptr;
    a.nMulti = 0;
    return a;
}

extern "C" void kernel_launch(void* const* d_in, const int* in_sizes, int n_in,
                              void* d_out, int out_size) {
    const float* x_in    = (const float*)d_in[0];
    const float* Wq      = (const float*)d_in[1];
    const float* Wk      = (const float*)d_in[2];
    const float* Wv      = (const float*)d_in[3];
    const float* Wo      = (const float*)d_in[4];
    const float* lamb    = (const float*)d_in[5];
    const float* lambdas = (const float*)d_in[6];
    const float* Wfc     = (const float*)d_in[7];
    const float* Wp      = (const float*)d_in[8];
    const int*   levels  = (const int*)d_in[9];
    const int*   sample  = (const int*)d_in[10];

    float *x, *x0, *xl, *fc2;
    __half *xn, *q, *k, *v, *v1, *vt, *y, *h, *p;
    __half *wq, *wk, *wv, *wo, *wfc, *wp;
    int* cpad;
    unsigned char* mask;
    cudaGetSymbolAddress((void**)&x,  g_x);
    cudaGetSymbolAddress((void**)&x0, g_x0);
    cudaGetSymbolAddress((void**)&xl, g_xl);
    cudaGetSymbolAddress((void**)&xn, g_xn);
    cudaGetSymbolAddress((void**)&q,  g_q);
    cudaGetSymbolAddress((void**)&k,  g_k);
    cudaGetSymbolAddress((void**)&v,  g_v);
    cudaGetSymbolAddress((void**)&v1, g_v1);
    cudaGetSymbolAddress((void**)&vt, g_vt);
    cudaGetSymbolAddress((void**)&y,  g_y);
    cudaGetSymbolAddress((void**)&h,  g_h);
    cudaGetSymbolAddress((void**)&p,  g_p);
    cudaGetSymbolAddress((void**)&fc2, g_fc2);
    cudaGetSymbolAddress((void**)&cpad, g_cpad);
    cudaGetSymbolAddress((void**)&mask, g_mask);
    cudaGetSymbolAddress((void**)&wq, g_wq);
    cudaGetSymbolAddress((void**)&wk, g_wk);
    cudaGetSymbolAddress((void**)&wv, g_wv);
    cudaGetSymbolAddress((void**)&wo, g_wo);
    cudaGetSymbolAddress((void**)&wfc, g_wfc);
    cudaGetSymbolAddress((void**)&wp, g_wp);

    const int SMAA = (128 + 128) * 72 * 2 * 2;  // 73728 bytes
    const int SMAB = (128 + 64) * 72 * 2 * 2;   // 55296 bytes
    const int SMBB = (64 + 64) * 72 * 2 * 2;    // 36864 bytes
    cudaFuncSetAttribute(gemm4<128,128>, cudaFuncAttributeMaxDynamicSharedMemorySize, SMAA);
    cudaFuncSetAttribute(gemm4<128,64>,  cudaFuncAttributeMaxDynamicSharedMemorySize, SMAB);
    cudaFuncSetAttribute(gemm4<64,64>,   cudaFuncAttributeMaxDynamicSharedMemorySize, SMBB);

    const int EW4 = (S * D / 4) / 256;
    const float scale = 1.0f / 8.0f;             // HD^-0.5

    // ---- stream-2 weight conversion, overlapped ----
    cudaStream_t s2;
    cudaStreamCreateWithFlags(&s2, cudaStreamNonBlocking);
    cudaEvent_t evRoot, evQKV, evWo, evWfc, evWp;
    cudaEventCreateWithFlags(&evRoot, cudaEventDisableTiming);
    cudaEventCreateWithFlags(&evQKV,  cudaEventDisableTiming);
    cudaEventCreateWithFlags(&evWo,   cudaEventDisableTiming);
    cudaEventCreateWithFlags(&evWfc,  cudaEventDisableTiming);
    cudaEventCreateWithFlags(&evWp,   cudaEventDisableTiming);

    cudaEventRecord(evRoot, 0);
    cudaStreamWaitEvent(s2, evRoot, 0);
    {
        int n8a = NL * D * D / 8;
        int n8b = NL * DFF * D / 8;
        tohalf2_k<<<(n8a + 255) / 256, 256, 0, s2>>>((const float4*)Wq, (uint4*)wq, n8a);
        tohalf2_k<<<(n8a + 255) / 256, 256, 0, s2>>>((const float4*)Wk, (uint4*)wk, n8a);
        tohalf2_k<<<(n8a + 255) / 256, 256, 0, s2>>>((const float4*)Wv, (uint4*)wv, n8a);
        cudaEventRecord(evQKV, s2);
        tohalf2_k<<<(n8a + 255) / 256, 256, 0, s2>>>((const float4*)Wo, (uint4*)wo, n8a);
        cudaEventRecord(evWo, s2);
        tohalf2_k<<<(n8b + 255) / 256, 256, 0, s2>>>((const float4*)Wfc, (uint4*)wfc, n8b);
        cudaEventRecord(evWfc, s2);
        tohalf2_k<<<(n8b + 255) / 256, 256, 0, s2>>>((const float4*)Wp, (uint4*)wp, n8b);
        cudaEventRecord(evWp, s2);
    }

    build_prefix_k<<<1, 32>>>(levels, cpad);
    build_mask_k<<<(S * S) / 256, 256>>>(levels, sample, cpad, mask);

    // x = rms(x_in); x0 = x  (single pass)
    rms_init_k<<<S, 256>>>(x_in, x, x0);

    for (int i = 0; i < NL; i++) {
        const __half* Wqi = wq + (size_t)i * D * D;
        const __half* Wki = wk + (size_t)i * D * D;
        const __half* Wvi = wv + (size_t)i * D * D;
        const __half* Woi = wo + (size_t)i * D * D;
        const __half* Wfi = wfc + (size_t)i * DFF * D;
        const __half* Wpi = wp + (size_t)i * D * DFF;

        // xl/xn prep; layers >=1 also fold in previous layer's FC2 partials
        if (i == 0)
            xlrms_k<<<S, 256>>>((const float4*)x, (const float4*)x0, lambdas, i,
                                (float4*)xl, xn);
        else
            xlrms_red_k<<<S, 256>>>((float4*)x, (const float4*)fc2, (const float4*)x0,
                                    lambdas, i, (float4*)xl, xn);

        // fused QKV (fp16 out; BN=64 -> 384 CTAs, balanced waves)
        if (i == 0) cudaStreamWaitEvent(0, evQKV, 0);
        {
            GArgs a = mkargs(xn, D, 0, nullptr, D, 0, nullptr, D, 0, nullptr, 0, D, 5);
            a.Bm[0] = Wqi; a.Bm[1] = Wki; a.Bm[2] = Wvi;
            a.Cm[0] = q;   a.Cm[1] = k;   a.Cm[2] = v;
            a.nMulti = 3;
            gemm4<128,64><<<dim3(D / 64, S / 128, 3), 128, SMAB>>>(a);
        }

        if (i == 0) copyu2_k<<<EW4, 256>>>((const uint2*)v, (uint2*)v1);

        rmsrope2_k<<<dim3((S * H) / 8, 2), 256>>>(q, k);

        // vt = transpose((1-la)*v + la*v1)
        transmix_k<<<dim3(32, 32), dim3(32, 8)>>>(v, v1, lamb, i, vt);

        // p[h] = mask .* exp(scale * q_h k_h^T), lower-triangular blocks (fp16);
        // mask tile staged through smem
        {
            GArgs a = mkargs(q, D, HD, k, D, HD, p, S, (long long)S * S, nullptr, 0, HD, 3);
            a.flags = 1; a.scale = scale; a.mask = mask;
            gemm4<128,128><<<dim3(1, 1, H * 36), 128, SMAA>>>(a);
        }

        // y[:,h] = fp16((p_h @ V_h) / rowsum), rowsum in-kernel (mode 7)
        {
            GArgs a = mkargs(p, S, (long long)S * S, vt, S, (long long)HD * S,
                             y, D, HD, nullptr, 0, S, 7);
            a.flags = 2;
            gemm4<64,64><<<dim3(1, S / 64, H), 128, SMBB>>>(a);
        }

        // x = xl + y @ Wo^T  (fp32 out; 256 CTAs full wave)
        if (i == 0) cudaStreamWaitEvent(0, evWo, 0);
        {
            GArgs a = mkargs(y, D, 0, Woi, D, 0, x, D, 0, xl, 0, D, 1);
            gemm4<64,64><<<dim3(D / 64, S / 64, 1), 128, SMBB>>>(a);
        }

        // h = fp16(relu(rms(x) @ Wfc^T)^2)
        rms_rows_h_k<<<S, 256>>>(x, xn);
        if (i == 0) cudaStreamWaitEvent(0, evWfc, 0);
        {
            GArgs a = mkargs(xn, D, 0, Wfi, D, 0, h, DFF, 0, nullptr, 0, D, 2);
            gemm4<128,128><<<dim3(DFF / 128, S / 128, 1), 128, SMAA>>>(a);
        }

        // FC2 split-K x4 partials (reduced by next layer's xlrms_red / final rms)
        if (i == 0) cudaStreamWaitEvent(0, evWp, 0);
        {
            GArgs a = mkargs(h, DFF, 0, Wpi, DFF, 0, fc2, D, (long long)S * D,
                             nullptr, 0, DFF / 4, 0);
            a.flags = 4;
            gemm4<128,128><<<dim3(D / 128, S / 128, 4), 128, SMAA>>>(a);
        }
    }

    // out = rms(x + FC2 partials of last layer)
    final_red_rms_k<<<S, 256>>>((const float4*)x, (const float4*)fc2, (float4*)d_out);
}

// round 17
// speedup vs baseline: 1.2648x; 1.0435x over previous
#include <cuda_runtime.h>
#include <cuda_fp16.h>
#include <math.h>
#include <stdint.h>

#define S 1024
#define D 1024
#define H 16
#define HD 64
#define NL 6
#define DFF 4096
#define EPS 1.1920929e-07f

// ---------------- scratch (device globals; no allocation) ----------------
__device__ float  g_x [S * D];
__device__ float  g_x0[S * D];
__device__ float  g_xl[S * D];
__device__ __half g_xn[S * D];
__device__ __half g_q [S * D];
__device__ __half g_k [S * D];
__device__ __half g_v [S * D];
__device__ __half g_v1[S * D];
__device__ __half g_vt[S * D];
__device__ __half g_y [S * D];
__device__ __half g_h [S * DFF];
__device__ float  g_fc2[4 * S * D];
__device__ int    g_cpad[S + 1];
__device__ unsigned char g_mask[(size_t)S * S];
// fp16 weight copies (converted once per replay, overlapped on stream 2)
__device__ __half g_wq[NL * D * D];
__device__ __half g_wk[NL * D * D];
__device__ __half g_wv[NL * D * D];
__device__ __half g_wo[NL * D * D];
__device__ __half g_wfc[(size_t)NL * DFF * D];
__device__ __half g_wp [(size_t)NL * DFF * D];

// ---------------- small kernels ----------------

__global__ void tohalf2_k(const float4* __restrict__ in, uint4* __restrict__ out, int n8) {
    int i = blockIdx.x * blockDim.x + threadIdx.x;
    if (i < n8) {
        float4 a = in[2 * i];
        float4 b = in[2 * i + 1];
        __half2 h0 = __floats2half2_rn(a.x, a.y);
        __half2 h1 = __floats2half2_rn(a.z, a.w);
        __half2 h2 = __floats2half2_rn(b.x, b.y);
        __half2 h3 = __floats2half2_rn(b.z, b.w);
        uint4 r;
        r.x = *(uint32_t*)&h0;
        r.y = *(uint32_t*)&h1;
        r.z = *(uint32_t*)&h2;
        r.w = *(uint32_t*)&h3;
        out[i] = r;
    }
}

__global__ void build_prefix_k(const int* __restrict__ levels, int* __restrict__ cpad) {
    if (threadIdx.x == 0) {
        cpad[0] = 0;
        for (int i = 0; i < S; i++) cpad[i + 1] = cpad[i] + (levels[i] == 0 ? 1 : 0);
    }
}

__global__ void build_mask_k(const int* __restrict__ levels, const int* __restrict__ sample,
                             const int* __restrict__ cpad, unsigned char* __restrict__ mask) {
    int idx = blockIdx.x * blockDim.x + threadIdx.x;
    int q = idx >> 10;
    int k = idx & 1023;
    bool causal = q >= k;
    bool same = sample[q] == sample[k];
    int cnt = cpad[q] - cpad[k + 1];
    bool markov = (levels[k] == 0) && (cnt > 0);
    mask[idx] = (causal && same && !markov) ? 1 : 0;
}

// initial: x = rms(x_in); x0 = x
__global__ void rms_init_k(const float* __restrict__ in, float* __restrict__ x,
                           float* __restrict__ x0) {
    int row = blockIdx.x;
    const float4* p = (const float4*)(in + (size_t)row * D);
    float4* ox  = (float4*)(x  + (size_t)row * D);
    float4* ox0 = (float4*)(x0 + (size_t)row * D);
    int tid = threadIdx.x;
    float4 t = p[tid];
    float ss = t.x * t.x + t.y * t.y + t.z * t.z + t.w * t.w;
    __shared__ float red[256];
    red[tid] = ss;
    __syncthreads();
    for (int s = 128; s > 0; s >>= 1) {
        if (tid < s) red[tid] += red[tid + s];
        __syncthreads();
    }
    float sc = rsqrtf(red[0] / (float)D + EPS);
    float4 r = make_float4(t.x * sc, t.y * sc, t.z * sc, t.w * sc);
    ox[tid] = r;
    ox0[tid] = r;
}

// RMS over fp32 rows of length D -> fp16 out
__global__ void rms_rows_h_k(const float* __restrict__ in, __half* __restrict__ out) {
    int row = blockIdx.x;
    const float4* p = (const float4*)(in + (size_t)row * D);
    uint2* o = (uint2*)(out + (size_t)row * D);
    int tid = threadIdx.x;
    float4 t = p[tid];
    float ss = t.x * t.x + t.y * t.y + t.z * t.z + t.w * t.w;
    __shared__ float red[256];
    red[tid] = ss;
    __syncthreads();
    for (int s = 128; s > 0; s >>= 1) {
        if (tid < s) red[tid] += red[tid + s];
        __syncthreads();
    }
    float sc = rsqrtf(red[0] / (float)D + EPS);
    __half2 a = __floats2half2_rn(t.x * sc, t.y * sc);
    __half2 b = __floats2half2_rn(t.z * sc, t.w * sc);
    uint2 r;
    r.x = *(uint32_t*)&a;
    r.y = *(uint32_t*)&b;
    o[tid] = r;
}

// fused: xl = l0*x + l1*x0 ; xn = fp16(rms(xl)). (layer 0)
__global__ void xlrms_k(const float4* __restrict__ x, const float4* __restrict__ x0,
                        const float* __restrict__ lambdas, int layer,
                        float4* __restrict__ xl, __half* __restrict__ xn) {
    int row = blockIdx.x;
    int tid = threadIdx.x;
    int i = row * 256 + tid;
    float l0 = lambdas[layer * 2 + 0];
    float l1 = lambdas[layer * 2 + 1];
    float4 a = x[i], b = x0[i];
    float4 t = make_float4(l0 * a.x + l1 * b.x, l0 * a.y + l1 * b.y,
                           l0 * a.z + l1 * b.z, l0 * a.w + l1 * b.w);
    xl[i] = t;
    float ss = t.x * t.x + t.y * t.y + t.z * t.z + t.w * t.w;
    __shared__ float red[256];
    red[tid] = ss;
    __syncthreads();
    for (int s = 128; s > 0; s >>= 1) {
        if (tid < s) red[tid] += red[tid + s];
        __syncthreads();
    }
    float sc = rsqrtf(red[0] / (float)D + EPS);
    __half2 h0 = __floats2half2_rn(t.x * sc, t.y * sc);
    __half2 h1 = __floats2half2_rn(t.z * sc, t.w * sc);
    uint2 r;
    r.x = *(uint32_t*)&h0;
    r.y = *(uint32_t*)&h1;
    ((uint2*)xn)[i] = r;
}

// fused: x += 4 FC2 partials; xl = l0*x + l1*x0; xn = fp16(rms(xl)). (layers 1..5)
__global__ void xlrms_red_k(float4* __restrict__ x, const float4* __restrict__ part,
                            const float4* __restrict__ x0,
                            const float* __restrict__ lambdas, int layer,
                            float4* __restrict__ xl, __half* __restrict__ xn) {
    int row = blockIdx.x;
    int tid = threadIdx.x;
    int i = row * 256 + tid;
    const int N4 = S * D / 4;
    float4 xv = x[i];
    #pragma unroll
    for (int j = 0; j < 4; j++) {
        float4 t = part[(size_t)j * N4 + i];
        xv.x += t.x; xv.y += t.y; xv.z += t.z; xv.w += t.w;
    }
    x[i] = xv;
    float l0 = lambdas[layer * 2 + 0];
    float l1 = lambdas[layer * 2 + 1];
    float4 b = x0[i];
    float4 t = make_float4(l0 * xv.x + l1 * b.x, l0 * xv.y + l1 * b.y,
                           l0 * xv.z + l1 * b.z, l0 * xv.w + l1 * b.w);
    xl[i] = t;
    float ss = t.x * t.x + t.y * t.y + t.z * t.z + t.w * t.w;
    __shared__ float red[256];
    red[tid] = ss;
    __syncthreads();
    for (int s = 128; s > 0; s >>= 1) {
        if (tid < s) red[tid] += red[tid + s];
        __syncthreads();
    }
    float sc = rsqrtf(red[0] / (float)D + EPS);
    __half2 h0 = __floats2half2_rn(t.x * sc, t.y * sc);
    __half2 h1 = __floats2half2_rn(t.z * sc, t.w * sc);
    uint2 r;
    r.x = *(uint32_t*)&h0;
    r.y = *(uint32_t*)&h1;
    ((uint2*)xn)[i] = r;
}

// final: out = rms(x + 4 FC2 partials)
__global__ void final_red_rms_k(const float4* __restrict__ x, const float4* __restrict__ part,
                                float4* __restrict__ out) {
    int row = blockIdx.x;
    int tid = threadIdx.x;
    int i = row * 256 + tid;
    const int N4 = S * D / 4;
    float4 xv = x[i];
    #pragma unroll
    for (int j = 0; j < 4; j++) {
        float4 t = part[(size_t)j * N4 + i];
        xv.x += t.x; xv.y += t.y; xv.z += t.z; xv.w += t.w;
    }
    float ss = xv.x * xv.x + xv.y * xv.y + xv.z * xv.z + xv.w * xv.w;
    __shared__ float red[256];
    red[tid] = ss;
    __syncthreads();
    for (int s = 128; s > 0; s >>= 1) {
        if (tid < s) red[tid] += red[tid + s];
        __syncthreads();
    }
    float sc = rsqrtf(red[0] / (float)D + EPS);
    out[i] = make_float4(xv.x * sc, xv.y * sc, xv.z * sc, xv.w * sc);
}

// fused per-(s,h) RMS + RoPE on fp16 q and k (blockIdx.y selects tensor)
__global__ void rmsrope2_k(__half* __restrict__ q, __half* __restrict__ k) {
    __half* t = blockIdx.y ? k : q;
    int warp = (blockIdx.x * blockDim.x + threadIdx.x) >> 5;
    int lane = threadIdx.x & 31;
    int s = warp >> 4;
    __half* p = t + (size_t)warp * 64;
    float a = __half2float(p[lane]);
    float b = __half2float(p[lane + 32]);
    float ss = a * a + b * b;
    #pragma unroll
    for (int o = 16; o; o >>= 1) ss += __shfl_xor_sync(0xFFFFFFFFu, ss, o);
    float sc = rsqrtf(ss / 64.f + EPS);
    a *= sc; b *= sc;
    float inv = powf(10000.f, -((float)(2 * lane)) / 64.f);
    float fr = (float)s * inv;
    float cs, sn;
    sincosf(fr, &sn, &cs);
    p[lane]      = __float2half_rn(a * cs + b * sn);
    p[lane + 32] = __float2half_rn(-a * sn + b * cs);
}

__global__ void copyu2_k(const uint2* __restrict__ in, uint2* __restrict__ out) {
    int i = blockIdx.x * blockDim.x + threadIdx.x;
    out[i] = in[i];
}

// fused v-mix + transpose: vt[c][r] = (1-la)*v[r][c] + la*v1[r][c]
__global__ void transmix_k(const __half* __restrict__ v, const __half* __restrict__ v1,
                           const float* __restrict__ lamb, int layer,
                           __half* __restrict__ vt) {
    __shared__ __half tile[32][34];
    float la = lamb[layer];
    float om = 1.f - la;
    int x = blockIdx.x * 32 + threadIdx.x;
    int y0 = blockIdx.y * 32 + threadIdx.y;
    #pragma unroll
    for (int j = 0; j < 32; j += 8) {
        size_t idx = (size_t)(y0 + j) * D + x;
        float mv = om * __half2float(v[idx]) + la * __half2float(v1[idx]);
        tile[threadIdx.y + j][threadIdx.x] = __float2half_rn(mv);
    }
    __syncthreads();
    int x2 = blockIdx.y * 32 + threadIdx.x;
    int y2 = blockIdx.x * 32 + threadIdx.y;
    #pragma unroll
    for (int j = 0; j < 32; j += 8)
        vt[(size_t)(y2 + j) * D + x2] = tile[threadIdx.x][threadIdx.y + j];
}

#define LDMX4(r0, r1, r2, r3, addr) \
    asm volatile("ldmatrix.sync.aligned.m8n8.x4.shared.b16 {%0,%1,%2,%3}, [%4];" \
                 : "=r"(r0), "=r"(r1), "=r"(r2), "=r"(r3) : "r"(addr))

#define MMA16816(acc, a0, a1, a2, a3, b0, b1) \
    asm volatile("mma.sync.aligned.m16n8k16.row.col.f32.f16.f16.f32 " \
                 "{%0,%1,%2,%3}, {%4,%5,%6,%7}, {%8,%9}, {%0,%1,%2,%3};\n" \
                 : "+f"((acc)[0]), "+f"((acc)[1]), "+f"((acc)[2]), "+f"((acc)[3]) \
                 : "r"(a0), "r"(a1), "r"(a2), "r"(a3), "r"(b0), "r"(b1))

// ---------------- fused flash attention: y = softmax'(mask, q k^T) @ V ----------------
// grid (S/64 row-blocks, H heads); 128 threads; warp = 16 q-rows x full 64 cols.
// Streams k-blocks 0..rb with double-buffered k/v/mask tiles; p never hits memory.
__global__ __launch_bounds__(128, 2) void flash_k(
    const __half* __restrict__ qg, const __half* __restrict__ kg,
    const __half* __restrict__ vtg, const unsigned char* __restrict__ maskg,
    __half* __restrict__ yg, float scale) {
    constexpr int SROW = 72;
    constexpr int QS = 64 * SROW;             // halves
    constexpr int STG = 128 * SROW;           // k + v per stage, halves
    extern __shared__ __half sh[];
    unsigned char* msh = (unsigned char*)(sh + QS + 2 * STG);  // 2 x 4096 bytes

    int tid = threadIdx.x, lane = tid & 31, warp = tid >> 5;
    int rb = blockIdx.x, h = blockIdx.y;
    int r0 = rb * 64;
    int nkb = rb + 1;
    const __half* qbase = qg + (size_t)r0 * D + h * HD;
    const __half* kbase = kg + h * HD;
    const __half* vtbase = vtg + (size_t)(h * HD) * S;

    auto issue_kv = [&](int kb, int st) {
        __half* dstK = sh + QS + st * STG;
        __half* dstV = dstK + 64 * SROW;
        int kp0 = kb * 64;
        #pragma unroll
        for (int i = 0; i < 4; i++) {
            int id = tid + 128 * i;
            int r = id >> 3, c = id & 7;
            unsigned uK = (unsigned)__cvta_generic_to_shared(dstK + r * SROW + c * 8);
            asm volatile("cp.async.cg.shared.global [%0], [%1], 16;\n"
                         :: "r"(uK), "l"(kbase + (size_t)(kp0 + r) * D + c * 8));
            unsigned uV = (unsigned)__cvta_generic_to_shared(dstV + r * SROW + c * 8);
            asm volatile("cp.async.cg.shared.global [%0], [%1], 16;\n"
                         :: "r"(uV), "l"(vtbase + (size_t)r * S + kp0 + c * 8));
        }
        unsigned char* dstM = msh + st * 4096;
        #pragma unroll
        for (int i = 0; i < 2; i++) {
            int id = tid + 128 * i;
            int r = id >> 2, c = id & 3;
            unsigned uM = (unsigned)__cvta_generic_to_shared(dstM + r * 64 + c * 16);
            asm volatile("cp.async.cg.shared.global [%0], [%1], 16;\n"
                         :: "r"(uM), "l"(maskg + (size_t)(r0 + r) * S + kp0 + c * 16));
        }
    };

    // q tile + stage 0 as group 1; stage 1 as group 2
    #pragma unroll
    for (int i = 0; i < 4; i++) {
        int id = tid + 128 * i;
        int r = id >> 3, c = id & 7;
        unsigned u = (unsigned)__cvta_generic_to_shared(sh + r * SROW + c * 8);
        asm volatile("cp.async.cg.shared.global [%0], [%1], 16;\n"
                     :: "r"(u), "l"(qbase + (size_t)r * D + c * 8));
    }
    issue_kv(0, 0);
    asm volatile("cp.async.commit_group;\n");
    if (nkb > 1) { issue_kv(1, 1); asm volatile("cp.async.commit_group;\n"); }

    int g = lane >> 2, tig = lane & 3;
    int laneq = lane & 7, lane8 = (lane >> 3) & 1, lane16 = lane >> 4;
    uint32_t shb = (uint32_t)__cvta_generic_to_shared(sh);
    int wm0 = warp * 16;
    uint32_t aoff = (uint32_t)((wm0 + laneq + 8 * lane8) * SROW + 8 * lane16);
    uint32_t boff = (uint32_t)((laneq + 8 * lane16) * SROW + 8 * lane8);

    float yacc[8][4] = {};
    float rs0 = 0.f, rs1 = 0.f;

    for (int kb = 0; kb < nkb; kb++) {
        if (kb + 2 <= nkb) asm volatile("cp.async.wait_group 1;\n");
        else               asm volatile("cp.async.wait_group 0;\n");
        __syncthreads();
        int st = kb & 1;
        uint32_t kB = shb + (uint32_t)(QS + st * STG) * 2;
        uint32_t vB = kB + 64 * SROW * 2;
        const unsigned char* mp = msh + st * 4096;

        // S tile = q @ k^T  (warp: 16 rows x 64 cols)
        float accs[8][4] = {};
        #pragma unroll
        for (int s16 = 0; s16 < 64; s16 += 16) {
            uint32_t af[4], bf[8][2];
            LDMX4(af[0], af[1], af[2], af[3], shb + (aoff + s16) * 2);
            #pragma unroll
            for (int fp = 0; fp < 4; fp++)
                LDMX4(bf[2 * fp][0], bf[2 * fp][1], bf[2 * fp + 1][0], bf[2 * fp + 1][1],
                      kB + (boff + fp * 16 * SROW + s16) * 2);
            #pragma unroll
            for (int fn = 0; fn < 8; fn++)
                MMA16816(accs[fn], af[0], af[1], af[2], af[3], bf[fn][0], bf[fn][1]);
        }

        // mask + exp + rowsum; pack to fp16 A fragments for the PV mma
        uint32_t pf[4][4];
        #pragma unroll
        for (int s = 0; s < 4; s++) {
            #pragma unroll
            for (int hv = 0; hv < 2; hv++) {
                int fn = 2 * s + hv;
                int c = fn * 8 + 2 * tig;
                const unsigned char* m0 = mp + (wm0 + g) * 64 + c;
                const unsigned char* m1 = mp + (wm0 + g + 8) * 64 + c;
                float v0 = m0[0] ? __expf(accs[fn][0] * scale) : 0.f;
                float v1 = m0[1] ? __expf(accs[fn][1] * scale) : 0.f;
                float v2 = m1[0] ? __expf(accs[fn][2] * scale) : 0.f;
                float v3 = m1[1] ? __expf(accs[fn][3] * scale) : 0.f;
                rs0 += v0 + v1;
                rs1 += v2 + v3;
                __half2 h01 = __floats2half2_rn(v0, v1);
                __half2 h23 = __floats2half2_rn(v2, v3);
                pf[s][2 * hv]     = *(uint32_t*)&h01;
                pf[s][2 * hv + 1] = *(uint32_t*)&h23;
            }
        }

        // y += P @ V
        #pragma unroll
        for (int s = 0; s < 4; s++) {
            uint32_t bf[8][2];
            #pragma unroll
            for (int fp = 0; fp < 4; fp++)
                LDMX4(bf[2 * fp][0], bf[2 * fp][1], bf[2 * fp + 1][0], bf[2 * fp + 1][1],
                      vB + (boff + fp * 16 * SROW + 16 * s) * 2);
            #pragma unroll
            for (int fn = 0; fn < 8; fn++)
                MMA16816(yacc[fn], pf[s][0], pf[s][1], pf[s][2], pf[s][3],
                         bf[fn][0], bf[fn][1]);
        }
        __syncthreads();
        if (kb + 2 < nkb) { issue_kv(kb + 2, st); asm volatile("cp.async.commit_group;\n"); }
    }

    rs0 += __shfl_xor_sync(0xFFFFFFFFu, rs0, 1);
    rs0 += __shfl_xor_sync(0xFFFFFFFFu, rs0, 2);
    rs1 += __shfl_xor_sync(0xFFFFFFFFu, rs1, 1);
    rs1 += __shfl_xor_sync(0xFFFFFFFFu, rs1, 2);
    float i0 = 1.f / rs0, i1 = 1.f / rs1;

    #pragma unroll
    for (int fn = 0; fn < 8; fn++) {
        int c = h * HD + fn * 8 + 2 * tig;
        size_t off0 = (size_t)(r0 + wm0 + g) * D + c;
        size_t off1 = (size_t)(r0 + wm0 + g + 8) * D + c;
        __half2 h0 = __floats2half2_rn(yacc[fn][0] * i0, yacc[fn][1] * i0);
        __half2 h1 = __floats2half2_rn(yacc[fn][2] * i1, yacc[fn][3] * i1);
        *(__half2*)(yg + off0) = h0;
        *(__half2*)(yg + off1) = h1;
    }
}

// ---------------- pipelined fp16 mma.sync GEMM (m16n8k16, ldmatrix), 4 warps ----------------
// modes: 0 fp32 raw | 1 fp32 acc+R | 2 fp16 relu(acc)^2 | 5 fp16 raw
// flags: 4 = split-K over z

struct GArgs {
    const __half* A; int lda; long long sA;
    const __half* B; int ldb; long long sB;
    void* C; int ldc; long long sC;
    const float* R; long long sR;
    int K; int mode; int flags; float scale;
    const __half* Bm[3]; void* Cm[3]; int nMulti;
};

template<int BM, int BN>
__global__ __launch_bounds__(128, 2) void gemm4(GArgs a) {
    constexpr int BK = 64;
    constexpr int SROW = 72;
    constexpr int SSZ = (BM + BN) * SROW;
    constexpr int WM = BM / 2, WN = BN / 2;
    constexpr int FM = WM / 16, FN = WN / 8;
    constexpr int CA = BM / 16, CB = BN / 16;
    extern __shared__ __half sh[];

    int tid = threadIdx.x, lane = tid & 31, warp = tid >> 5;
    int row0 = blockIdx.y * BM, col0 = blockIdx.x * BN, koff = 0;
    const __half *A, *B;
    char* C;
    const float* R = nullptr;
    int z = blockIdx.z;

    if (a.flags & 4) {
        A = a.A; B = a.B;
        C = (char*)a.C + (size_t)z * a.sC * 4;  // fp32 partials
        koff = z * a.K;
    } else if (a.nMulti) {
        A = a.A; B = a.Bm[z]; C = (char*)a.Cm[z];
    } else {
        A = a.A + (size_t)z * a.sA;
        B = a.B + (size_t)z * a.sB;
        int esz = (a.mode == 0 || a.mode == 1) ? 4 : 2;
        C = (char*)a.C + (size_t)z * a.sC * esz;
        if (a.R) R = a.R + (size_t)z * a.sR;
    }

    int K = a.K;
    int KT = K / BK;

    auto issue = [&](int kt, int st) {
        __half* dstA = sh + st * SSZ;
        #pragma unroll
        for (int i = 0; i < CA; i++) {
            int id = tid + 128 * i;
            int r = id >> 3, c = id & 7;
            unsigned u = (unsigned)__cvta_generic_to_shared(dstA + r * SROW + c * 8);
            const __half* gp = A + (size_t)(row0 + r) * a.lda + koff + kt * BK + c * 8;
            asm volatile("cp.async.cg.shared.global [%0], [%1], 16;\n" :: "r"(u), "l"(gp));
        }
        __half* dstB = sh + st * SSZ + BM * SROW;
        #pragma unroll
        for (int i = 0; i < CB; i++) {
            int id = tid + 128 * i;
            int r = id >> 3, c = id & 7;
            unsigned u = (unsigned)__cvta_generic_to_shared(dstB + r * SROW + c * 8);
            const __half* gp = B + (size_t)(col0 + r) * a.ldb + koff + kt * BK + c * 8;
            asm volatile("cp.async.cg.shared.global [%0], [%1], 16;\n" :: "r"(u), "l"(gp));
        }
        asm volatile("cp.async.commit_group;\n");
    };

    float acc[FM][FN][4] = {};

    issue(0, 0);
    if (KT > 1) issue(1, 1);

    int wm0 = (warp & 1) * WM, wn0 = (warp >> 1) * WN;
    int g = lane >> 2, tig = lane & 3;

    uint32_t shb = (uint32_t)__cvta_generic_to_shared(sh);
    int laneq = lane & 7, lane8 = (lane >> 3) & 1, lane16 = lane >> 4;
    uint32_t aoff = (uint32_t)((wm0 + laneq + 8 * lane8) * SROW + 8 * lane16);
    uint32_t boff = (uint32_t)((wn0 + laneq + 8 * lane16) * SROW + 8 * lane8);

    for (int kt = 0; kt < KT; kt++) {
        if (kt + 2 <= KT) asm volatile("cp.async.wait_group 1;\n");
        else              asm volatile("cp.async.wait_group 0;\n");
        __syncthreads();

        uint32_t sAb = shb + (uint32_t)((kt & 1) * SSZ) * 2;
        uint32_t sBb = sAb + BM * SROW * 2;

        #pragma unroll
        for (int s16 = 0; s16 < BK; s16 += 16) {
            uint32_t af[FM][4], bf[FN][2];
            #pragma unroll
            for (int fm = 0; fm < FM; fm++) {
                LDMX4(af[fm][0], af[fm][1], af[fm][2], af[fm][3],
                      sAb + (aoff + fm * 16 * SROW + s16) * 2);
            }
            #pragma unroll
            for (int fp = 0; fp < FN / 2; fp++) {
                LDMX4(bf[2 * fp][0], bf[2 * fp][1], bf[2 * fp + 1][0], bf[2 * fp + 1][1],
                      sBb + (boff + fp * 16 * SROW + s16) * 2);
            }
            #pragma unroll
            for (int fm = 0; fm < FM; fm++)
                #pragma unroll
                for (int fn = 0; fn < FN; fn++)
                    MMA16816(acc[fm][fn], af[fm][0], af[fm][1], af[fm][2], af[fm][3],
                             bf[fn][0], bf[fn][1]);
        }
        __syncthreads();
        if (kt + 2 < KT) issue(kt + 2, kt & 1);
    }

    // epilogue
    #pragma unroll
    for (int fm = 0; fm < FM; fm++) {
        #pragma unroll
        for (int fn = 0; fn < FN; fn++) {
            int r0 = row0 + wm0 + fm * 16 + g;
            int c  = col0 + wn0 + fn * 8 + 2 * tig;
            #pragma unroll
            for (int half = 0; half < 2; half++) {
                int r = r0 + 8 * half;
                float v0 = acc[fm][fn][2 * half + 0];
                float v1 = acc[fm][fn][2 * half + 1];
                size_t off = (size_t)r * a.ldc + c;
                if (a.mode == 0) {
                    ((float*)C)[off] = v0;
                    ((float*)C)[off + 1] = v1;
                } else if (a.mode == 1) {
                    ((float*)C)[off] = v0 + R[off];
                    ((float*)C)[off + 1] = v1 + R[off + 1];
                } else {
                    if (a.mode == 2) {
                        v0 = fmaxf(v0, 0.f); v0 *= v0;
                        v1 = fmaxf(v1, 0.f); v1 *= v1;
                    }
                    __half2 hv = __floats2half2_rn(v0, v1);
                    *(__half2*)((__half*)C + off) = hv;
                }
            }
        }
    }
}

// ---------------- host orchestration ----------------

static inline GArgs mkargs(const __half* A, int lda, long long sA,
                           const __half* B, int ldb, long long sB,
                           void* C, int ldc, long long sC,
                           const float* R, long long sR, int K, int mode) {
    GArgs a;
    a.A = A; a.lda = lda; a.sA = sA;
    a.B = B; a.ldb = ldb; a.sB = sB;
    a.C = C; a.ldc = ldc; a.sC = sC;
    a.R = R; a.sR = sR; a.K = K; a.mode = mode;
    a.flags = 0; a.scale = 0.f;
    a.Bm[0] = a.Bm[1] = a.Bm[2] = nullptr;
    a.Cm[0] = a.Cm[1] = a.Cm[2] = nullptr;
    a.nMulti = 0;
    return a;
}

extern "C" void kernel_launch(void* const* d_in, const int* in_sizes, int n_in,
                              void* d_out, int out_size) {
    const float* x_in    = (const float*)d_in[0];
    const float* Wq      = (const float*)d_in[1];
    const float* Wk      = (const float*)d_in[2];
    const float* Wv      = (const float*)d_in[3];
    const float* Wo      = (const float*)d_in[4];
    const float* lamb    = (const float*)d_in[5];
    const float* lambdas = (const float*)d_in[6];
    const float* Wfc     = (const float*)d_in[7];
    const float* Wp      = (const float*)d_in[8];
    const int*   levels  = (const int*)d_in[9];
    const int*   sample  = (const int*)d_in[10];

    float *x, *x0, *xl, *fc2;
    __half *xn, *q, *k, *v, *v1, *vt, *y, *h;
    __half *wq, *wk, *wv, *wo, *wfc, *wp;
    int* cpad;
    unsigned char* mask;
    cudaGetSymbolAddress((void**)&x,  g_x);
    cudaGetSymbolAddress((void**)&x0, g_x0);
    cudaGetSymbolAddress((void**)&xl, g_xl);
    cudaGetSymbolAddress((void**)&xn, g_xn);
    cudaGetSymbolAddress((void**)&q,  g_q);
    cudaGetSymbolAddress((void**)&k,  g_k);
    cudaGetSymbolAddress((void**)&v,  g_v);
    cudaGetSymbolAddress((void**)&v1, g_v1);
    cudaGetSymbolAddress((void**)&vt, g_vt);
    cudaGetSymbolAddress((void**)&y,  g_y);
    cudaGetSymbolAddress((void**)&h,  g_h);
    cudaGetSymbolAddress((void**)&fc2, g_fc2);
    cudaGetSymbolAddress((void**)&cpad, g_cpad);
    cudaGetSymbolAddress((void**)&mask, g_mask);
    cudaGetSymbolAddress((void**)&wq, g_wq);
    cudaGetSymbolAddress((void**)&wk, g_wk);
    cudaGetSymbolAddress((void**)&wv, g_wv);
    cudaGetSymbolAddress((void**)&wo, g_wo);
    cudaGetSymbolAddress((void**)&wfc, g_wfc);
    cudaGetSymbolAddress((void**)&wp, g_wp);

    const int SMAA = (128 + 128) * 72 * 2 * 2;  // 73728 bytes
    const int SMAB = (128 + 64) * 72 * 2 * 2;   // 55296 bytes
    const int SMBB = (64 + 64) * 72 * 2 * 2;    // 36864 bytes
    const int SMFL = (64 * 72 + 2 * 128 * 72) * 2 + 2 * 4096;  // 54272 bytes
    cudaFuncSetAttribute(gemm4<128,128>, cudaFuncAttributeMaxDynamicSharedMemorySize, SMAA);
    cudaFuncSetAttribute(gemm4<128,64>,  cudaFuncAttributeMaxDynamicSharedMemorySize, SMAB);
    cudaFuncSetAttribute(gemm4<64,64>,   cudaFuncAttributeMaxDynamicSharedMemorySize, SMBB);
    cudaFuncSetAttribute(flash_k,        cudaFuncAttributeMaxDynamicSharedMemorySize, SMFL);

    const int EW4 = (S * D / 4) / 256;
    const float scale = 1.0f / 8.0f;             // HD^-0.5

    // ---- stream-2 weight conversion, overlapped ----
    cudaStream_t s2;
    cudaStreamCreateWithFlags(&s2, cudaStreamNonBlocking);
    cudaEvent_t evRoot, evQKV, evWo, evWfc, evWp;
    cudaEventCreateWithFlags(&evRoot, cudaEventDisableTiming);
    cudaEventCreateWithFlags(&evQKV,  cudaEventDisableTiming);
    cudaEventCreateWithFlags(&evWo,   cudaEventDisableTiming);
    cudaEventCreateWithFlags(&evWfc,  cudaEventDisableTiming);
    cudaEventCreateWithFlags(&evWp,   cudaEventDisableTiming);

    cudaEventRecord(evRoot, 0);
    cudaStreamWaitEvent(s2, evRoot, 0);
    {
        int n8a = NL * D * D / 8;
        int n8b = NL * DFF * D / 8;
        tohalf2_k<<<(n8a + 255) / 256, 256, 0, s2>>>((const float4*)Wq, (uint4*)wq, n8a);
        tohalf2_k<<<(n8a + 255) / 256, 256, 0, s2>>>((const float4*)Wk, (uint4*)wk, n8a);
        tohalf2_k<<<(n8a + 255) / 256, 256, 0, s2>>>((const float4*)Wv, (uint4*)wv, n8a);
        cudaEventRecord(evQKV, s2);
        tohalf2_k<<<(n8a + 255) / 256, 256, 0, s2>>>((const float4*)Wo, (uint4*)wo, n8a);
        cudaEventRecord(evWo, s2);
        tohalf2_k<<<(n8b + 255) / 256, 256, 0, s2>>>((const float4*)Wfc, (uint4*)wfc, n8b);
        cudaEventRecord(evWfc, s2);
        tohalf2_k<<<(n8b + 255) / 256, 256, 0, s2>>>((const float4*)Wp, (uint4*)wp, n8b);
        cudaEventRecord(evWp, s2);
    }

    build_prefix_k<<<1, 32>>>(levels, cpad);
    build_mask_k<<<(S * S) / 256, 256>>>(levels, sample, cpad, mask);

    rms_init_k<<<S, 256>>>(x_in, x, x0);

    for (int i = 0; i < NL; i++) {
        const __half* Wqi = wq + (size_t)i * D * D;
        const __half* Wki = wk + (size_t)i * D * D;
        const __half* Wvi = wv + (size_t)i * D * D;
        const __half* Woi = wo + (size_t)i * D * D;
        const __half* Wfi = wfc + (size_t)i * DFF * D;
        const __half* Wpi = wp + (size_t)i * D * DFF;

        if (i == 0)
            xlrms_k<<<S, 256>>>((const float4*)x, (const float4*)x0, lambdas, i,
                                (float4*)xl, xn);
        else
            xlrms_red_k<<<S, 256>>>((float4*)x, (const float4*)fc2, (const float4*)x0,
                                    lambdas, i, (float4*)xl, xn);

        // fused QKV (fp16 out; BN=64 -> 384 CTAs)
        if (i == 0) cudaStreamWaitEvent(0, evQKV, 0);
        {
            GArgs a = mkargs(xn, D, 0, nullptr, D, 0, nullptr, D, 0, nullptr, 0, D, 5);
            a.Bm[0] = Wqi; a.Bm[1] = Wki; a.Bm[2] = Wvi;
            a.Cm[0] = q;   a.Cm[1] = k;   a.Cm[2] = v;
            a.nMulti = 3;
            gemm4<128,64><<<dim3(D / 64, S / 128, 3), 128, SMAB>>>(a);
        }

        if (i == 0) copyu2_k<<<EW4, 256>>>((const uint2*)v, (uint2*)v1);

        rmsrope2_k<<<dim3((S * H) / 8, 2), 256>>>(q, k);

        // vt = transpose((1-la)*v + la*v1)
        transmix_k<<<dim3(32, 32), dim3(32, 8)>>>(v, v1, lamb, i, vt);

        // fused attention: y = softmax'(mask, q k^T / 8) @ V   (p never materialized)
        flash_k<<<dim3(S / 64, H), 128, SMFL>>>(q, k, vt, mask, y, scale);

        // x = xl + y @ Wo^T  (fp32 out; 256 CTAs full wave)
        if (i == 0) cudaStreamWaitEvent(0, evWo, 0);
        {
            GArgs a = mkargs(y, D, 0, Woi, D, 0, x, D, 0, xl, 0, D, 1);
            gemm4<64,64><<<dim3(D / 64, S / 64, 1), 128, SMBB>>>(a);
        }

        // h = fp16(relu(rms(x) @ Wfc^T)^2)
        rms_rows_h_k<<<S, 256>>>(x, xn);
        if (i == 0) cudaStreamWaitEvent(0, evWfc, 0);
        {
            GArgs a = mkargs(xn, D, 0, Wfi, D, 0, h, DFF, 0, nullptr, 0, D, 2);
            gemm4<128,128><<<dim3(DFF / 128, S / 128, 1), 128, SMAA>>>(a);
        }

        // FC2 split-K x4 partials (reduced by next layer's xlrms_red / final rms)
        if (i == 0) cudaStreamWaitEvent(0, evWp, 0);
        {
            GArgs a = mkargs(h, DFF, 0, Wpi, DFF, 0, fc2, D, (long long)S * D,
                             nullptr, 0, DFF / 4, 0);
            a.flags = 4;
            gemm4<128,128><<<dim3(D / 128, S / 128, 4), 128, SMAA>>>(a);
        }
    }

    final_red_rms_k<<<S, 256>>>((const float4*)x, (const float4*)fc2, (float4*)d_out);
}